// round 7
// baseline (speedup 1.0000x reference)
#include <cuda_runtime.h>
#include <cstdint>

typedef unsigned int uint32;

#define NBT   3200          // B*T
#define NND   22
#define NCH   64
#define SLICE (NND*NCH)     // 1408
#define TOT   (NBT*SLICE)
#define MAXNZ 484
#define SPB   4             // slices per block
#define GRID1 (NBT/SPB)     // 800
#define OFFCAP0 32
#define OFFCAP1 96
#define XP    72            // pitch of permuted tf32 buffers in k_main (72 mod 32 = 8)
#define CP    200           // pitch of permuted scat in k_cat (200 mod 32 = 8)
// permuted column position within an 8-col group: order [0,4,1,5,2,6,3,7]
#define POSC(c) (((c) & ~7) + 2*((c) & 3) + (((c) >> 2) & 1))

// ---------------- device scratch ----------------
__device__ float g_hbuf0[TOT];
__device__ float g_hbuf1[TOT];
__device__ float g_hbuf2[TOT];
__device__ float g_pre2[TOT];
__device__ float g_part1[6*64*NBT];
__device__ float g_part2[2*64*NBT];
__device__ float g_scale1[192], g_shift1[192];
__device__ float g_scale2[64],  g_shift2[64];
__device__ float g_Wt[5*4096];          // [g][o][c]
__device__ float g_diag[2][NND*NCH];
__device__ float g_offv[2][MAXNZ*NCH];
__device__ int   g_offcol[2][MAXNZ];
__device__ int   g_rowptr[2][NND+1];

// ---------------- helpers ----------------
__device__ __forceinline__ uint32 tf32(float f){
    uint32 r; asm("cvt.rna.tf32.f32 %0, %1;" : "=r"(r) : "f"(f)); return r;
}
__device__ __forceinline__ void mma_tf32(float c[4], const uint32 a[4], const uint32 b[2]){
    asm volatile("mma.sync.aligned.m16n8k8.row.col.f32.tf32.tf32.f32 "
                 "{%0,%1,%2,%3}, {%4,%5,%6,%7}, {%8,%9}, {%0,%1,%2,%3};"
                 : "+f"(c[0]), "+f"(c[1]), "+f"(c[2]), "+f"(c[3])
                 : "r"(a[0]), "r"(a[1]), "r"(a[2]), "r"(a[3]),
                   "r"(b[0]), "r"(b[1]));
}
__device__ __forceinline__ float redg(float v){
    v += __shfl_down_sync(0xffffffffu, v, 16);
    v += __shfl_down_sync(0xffffffffu, v, 8);
    v += __shfl_down_sync(0xffffffffu, v, 4);
    return v;
}

// ---------------- prep (unchanged, proven) ----------------
__global__ void k_prep(const float* __restrict__ e_sym, const int* __restrict__ rows_sym,
                       const int* __restrict__ cols_sym, int nnz_sym,
                       const float* __restrict__ e_con, const int* __restrict__ rows_con,
                       const int* __restrict__ cols_con, int nnz_con,
                       const float* __restrict__ W_sym, const float* __restrict__ W_con,
                       const float* __restrict__ W_dis)
{
    int blk = blockIdx.x, tid = threadIdx.x;
    if (blk == 2){
        for (int p = tid; p < 5*4096; p += 256){
            int g = p >> 12, rem = p & 4095, c = rem >> 6, o = rem & 63;
            float v;
            if (g < 2)      v = W_sym[g*4096 + c*64 + o];
            else if (g < 4) v = W_con[(g-2)*4096 + c*64 + o];
            else            v = W_dis[c*64 + o];
            g_Wt[g*4096 + o*64 + c] = v;
        }
        return;
    }
    int br = blk;
    const float* e  = br ? e_con   : e_sym;
    const int* rows = br ? rows_con : rows_sym;
    const int* cols = br ? cols_con : cols_sym;
    int nnz         = br ? nnz_con : nnz_sym;

    __shared__ float sden[NND*NCH];
    __shared__ int   smap[512];

    for (int p = tid; p < NND*NCH; p += 256) g_diag[br][p] = 0.f;
    __syncthreads();

    if (tid == 0){
        int m = 0;
        for (int k = 0; k < nnz; k++){
            int r = rows[k], c = cols[k];
            if (c != r){ smap[k] = m; g_offcol[br][m] = c; m++; }
            else smap[k] = -1;
        }
        for (int i = 0; i <= NND; i++){
            int cnt = 0;
            for (int k = 0; k < nnz; k++)
                if (cols[k] != rows[k] && rows[k] < i) cnt++;
            g_rowptr[br][i] = cnt;
        }
    }
    __syncthreads();

    for (int p = tid; p < NND*NCH; p += 256){
        int i = p >> 6, o = p & 63;
        float s = 0.f;
        for (int k = 0; k < nnz; k++)
            if (rows[k] == i) s += expf(e[o*nnz + k]);
        sden[p] = s;
    }
    __syncthreads();

    for (int p = tid; p < 64*nnz; p += 256){
        int k = p >> 6, o = p & 63;
        int r = rows[k];
        float v = expf(e[o*nnz + k]) / sden[r*64 + o];
        int m = smap[k];
        if (m < 0) g_diag[br][r*64 + o] = v;
        else       g_offv[br][m*64 + o] = v;
    }
}

// gemm K=64, permuted tf32 smem (pitch XP), LDS.64 A loads, B frags in regs
__device__ __forceinline__ void mma8t64(const uint32* __restrict__ sbuf,
                                        const uint32 (&bwk)[8][2],
                                        int g, int tig, int r2ok,
                                        float acc0[4], float acc1[4]){
#pragma unroll
    for (int k8 = 0; k8 < 8; k8++){
        const uint32* p0 = sbuf + g*XP + k8*8 + 2*tig;
        uint2 va = *(const uint2*)p0;
        uint2 vb = *(const uint2*)(p0 + 8*XP);
        uint2 vc = r2ok ? *(const uint2*)(p0 + 16*XP) : make_uint2(0u, 0u);
        uint32 a0[4] = { va.x, vb.x, va.y, vb.y };
        uint32 a1[4] = { vc.x, 0u,   vc.y, 0u   };
        mma_tf32(acc0, a0, bwk[k8]);
        mma_tf32(acc1, a1, bwk[k8]);
    }
}

// same but B streamed from global (used once per slice for Wdis)
__device__ __forceinline__ void mma8g64(const uint32* __restrict__ sbuf,
                                        const float* __restrict__ wg,
                                        int n0, int g, int tig, int r2ok,
                                        float acc0[4], float acc1[4]){
#pragma unroll
    for (int k8 = 0; k8 < 8; k8++){
        const float* wp = wg + (n0 + g)*64 + k8*8 + tig;
        uint32 b[2];
        b[0] = tf32(__ldg(wp));
        b[1] = tf32(__ldg(wp + 4));
        const uint32* p0 = sbuf + g*XP + k8*8 + 2*tig;
        uint2 va = *(const uint2*)p0;
        uint2 vb = *(const uint2*)(p0 + 8*XP);
        uint2 vc = r2ok ? *(const uint2*)(p0 + 16*XP) : make_uint2(0u, 0u);
        uint32 a0[4] = { va.x, vb.x, va.y, vb.y };
        uint32 a1[4] = { vc.x, 0u,   vc.y, 0u   };
        mma_tf32(acc0, a0, b);
        mma_tf32(acc1, a1, b);
    }
}

// ---------------- main fused kernel ----------------
__global__ __launch_bounds__(256, 2) void k_main(const float* __restrict__ x,
                                                 const float* __restrict__ att,
                                                 const float* __restrict__ b_dis)
{
    extern __shared__ __align__(16) float smem_[];
    float*  sx    = smem_;                         // 1496 (pitch 68, fp32)
    uint32* sxt   = (uint32*)(sx + 1496);          // 1584 (pitch 72, permuted tf32)
    uint32* sdist = sxt + 1584;                    // 1584
    float*  sh1   = (float*)(sdist + 1584);        // 1408
    uint32* sdwT  = (uint32*)(sh1 + 1408);         // 1792 (64*28)
    uint32* sattT = sdwT + 1792;                   // 528 (22*24)
    float*  sdiag = (float*)(sattT + 528);         // 2816
    float*  soffv = sdiag + 2816;                  // 8192
    int*    ssrp  = (int*)(soffv + 8192);          // 48
    int*    ssocol= ssrp + 48;                     // 128
    float*  sS1   = (float*)(ssocol + 128);        // 64
    float*  sS2   = sS1 + 64;                      // 64

    int tid = threadIdx.x;
    int lane = tid & 31, w = tid >> 5;
    int g = lane >> 2, tig = lane & 3;
    int n0 = w*8;
    int o0 = n0 + 2*tig;
    int r2ok = (g + 16) < NND;

    // persistent B fragments: W0s, W1s, W0c, W1c (Wdis streams from L2)
    uint32 bw0s[8][2], bw1s[8][2], bw0c[8][2], bw1c[8][2];
#pragma unroll
    for (int k8 = 0; k8 < 8; k8++){
        const float* w0 = g_Wt + 0*4096 + (n0 + g)*64 + k8*8 + tig;
        const float* w1 = g_Wt + 1*4096 + (n0 + g)*64 + k8*8 + tig;
        const float* w2 = g_Wt + 2*4096 + (n0 + g)*64 + k8*8 + tig;
        const float* w3 = g_Wt + 3*4096 + (n0 + g)*64 + k8*8 + tig;
        bw0s[k8][0] = tf32(__ldg(w0)); bw0s[k8][1] = tf32(__ldg(w0 + 4));
        bw1s[k8][0] = tf32(__ldg(w1)); bw1s[k8][1] = tf32(__ldg(w1 + 4));
        bw0c[k8][0] = tf32(__ldg(w2)); bw0c[k8][1] = tf32(__ldg(w2 + 4));
        bw1c[k8][0] = tf32(__ldg(w3)); bw1c[k8][1] = tf32(__ldg(w3 + 4));
    }

    // ---- block-constant staging ----
    for (int p = tid; p < NND*24; p += 256){
        int i = p / 24, c = p % 24;
        sattT[p] = (c < NND) ? tf32(__ldg(&att[i*NND + c])) : 0u;
    }
    for (int p = tid; p < 64*28; p += 256) sdwT[p] = 0u;
    for (int p = tid; p < 2*(NND+1); p += 256) ssrp[(p/(NND+1))*23 + (p%(NND+1))] = g_rowptr[p/(NND+1)][p%(NND+1)];
    for (int p = tid; p < 2*NND*64; p += 256) sdiag[p] = g_diag[p/(NND*64)][p%(NND*64)];
    {
        int cnt0 = g_rowptr[0][NND]; if (cnt0 > OFFCAP0) cnt0 = OFFCAP0;
        int cnt1 = g_rowptr[1][NND]; if (cnt1 > OFFCAP1) cnt1 = OFFCAP1;
        for (int p = tid; p < cnt0*64; p += 256) soffv[p] = g_offv[0][p];
        for (int p = tid; p < cnt1*64; p += 256) soffv[OFFCAP0*64 + p] = g_offv[1][p];
        for (int p = tid; p < cnt0; p += 256) ssocol[p] = g_offcol[0][p];
        for (int p = tid; p < cnt1; p += 256) ssocol[OFFCAP0 + p] = g_offcol[1][p];
    }

    float2 bd = *(const float2*)&b_dis[o0];

    // prefetch slice 0
    float4 xr0, xr1;
    {
        const float4* xg = (const float4*)(x + (size_t)(blockIdx.x*SPB)*SLICE);
        xr0 = __ldg(xg + tid);
        xr1 = (tid + 256 < SLICE/4) ? __ldg(xg + tid + 256) : make_float4(0,0,0,0);
    }

    for (int s = 0; s < SPB; s++){
        int bt = blockIdx.x*SPB + s;
        __syncthreads();

        // write prefetched x: fp32 (pitch 68) + permuted tf32 (pitch 72)
        {
            int i = tid >> 4, c = (tid & 15)*4;
            *(float4*)&sx[i*68 + c] = xr0;
            int base = i*XP + (c & ~7) + ((c >> 2) & 1);
            sxt[base    ] = tf32(xr0.x);
            sxt[base + 2] = tf32(xr0.y);
            sxt[base + 4] = tf32(xr0.z);
            sxt[base + 6] = tf32(xr0.w);
            if (tid + 256 < SLICE/4){
                int p = tid + 256; i = p >> 4; c = (p & 15)*4;
                *(float4*)&sx[i*68 + c] = xr1;
                base = i*XP + (c & ~7) + ((c >> 2) & 1);
                sxt[base    ] = tf32(xr1.x);
                sxt[base + 2] = tf32(xr1.y);
                sxt[base + 4] = tf32(xr1.z);
                sxt[base + 6] = tf32(xr1.w);
            }
        }
        if (s + 1 < SPB){
            const float4* xg = (const float4*)(x + (size_t)(bt + 1)*SLICE);
            xr0 = __ldg(xg + tid);
            if (tid + 256 < SLICE/4) xr1 = __ldg(xg + tid + 256);
        }
        __syncthreads();

        if (tid < 64){
            float s1 = 0.f, s2 = 0.f;
#pragma unroll
            for (int i = 0; i < NND; i++){
                float v = sx[i*68 + tid];
                s1 += v; s2 += v*v;
            }
            sS1[tid] = s1; sS2[tid] = s2;
        }
        __syncthreads();

        for (int p = tid; p < SLICE; p += 256){
            int i = p >> 6, c = p & 63;
            float v = sx[i*68 + c];
            float d = sS2[c] - 2.f*v*sS1[c] + (float)NND*v*v;
            sdist[i*XP + POSC(c)] = tf32(sqrtf(fmaxf(d, 0.f)) + 1e-8f);
        }
        __syncthreads();

        size_t obase = (size_t)bt*SLICE;

        // ===== branches s (br=0) and c (br=1) =====
#pragma unroll
        for (int br = 0; br < 2; br++){
            float acc0[4] = {0,0,0,0}, acc1[4] = {0,0,0,0};
            if (br == 0) mma8t64(sxt, bw1s, g, tig, r2ok, acc0, acc1);
            else         mma8t64(sxt, bw1c, g, tig, r2ok, acc0, acc1);
            __syncwarp();
            sh1[ g      *64 + o0    ] = acc0[0];
            sh1[ g      *64 + o0 + 1] = acc0[1];
            sh1[(g + 8) *64 + o0    ] = acc0[2];
            sh1[(g + 8) *64 + o0 + 1] = acc0[3];
            if (r2ok){
                sh1[(g + 16)*64 + o0    ] = acc1[0];
                sh1[(g + 16)*64 + o0 + 1] = acc1[1];
            }
            __syncwarp();

            float h0a[4] = {0,0,0,0}, h0b[4] = {0,0,0,0};
            if (br == 0) mma8t64(sxt, bw0s, g, tig, r2ok, h0a, h0b);
            else         mma8t64(sxt, bw0c, g, tig, r2ok, h0a, h0b);

            int ob = br ? OFFCAP0 : 0;
            float su0 = 0.f, su1 = 0.f, sq0 = 0.f, sq1 = 0.f;
            int rr[3] = { g, g + 8, g + 16 };
            float va[3] = { h0a[0], h0a[2], h0b[0] };
            float vb[3] = { h0a[1], h0a[3], h0b[1] };
#pragma unroll
            for (int q = 0; q < 3; q++){
                if (q == 2 && !r2ok) break;
                int r = rr[q];
                float2 dg = *(const float2*)&sdiag[br*(NND*64) + r*64 + o0];
                float v0 = va[q]*dg.x, v1 = vb[q]*dg.y;
                int mb = ssrp[br*23 + r], me = ssrp[br*23 + r + 1];
                for (int m = mb; m < me; m++){
                    int cm = ssocol[ob + m];
                    float2 ov = *(const float2*)&soffv[(ob + m)*64 + o0];
                    v0 += ov.x * sh1[cm*64 + o0];
                    v1 += ov.y * sh1[cm*64 + o0 + 1];
                }
                float2 st = make_float2(v0, v1);
                if (br == 0) *(float2*)&g_hbuf0[obase + r*64 + o0] = st;
                else         *(float2*)&g_hbuf1[obase + r*64 + o0] = st;
                su0 += v0; su1 += v1; sq0 += v0*v0; sq1 += v1*v1;
            }
            su0 = redg(su0); su1 = redg(su1); sq0 = redg(sq0); sq1 = redg(sq1);
            if (lane < 4){
                g_part1[(size_t)((2*br  )*64 + o0    )*NBT + bt] = su0;
                g_part1[(size_t)((2*br  )*64 + o0 + 1)*NBT + bt] = su1;
                g_part1[(size_t)((2*br+1)*64 + o0    )*NBT + bt] = sq0;
                g_part1[(size_t)((2*br+1)*64 + o0 + 1)*NBT + bt] = sq1;
            }
            __syncwarp();
        }

        // ===== z branch =====
        {
            float acc0[4] = {0,0,0,0}, acc1[4] = {0,0,0,0};
            mma8g64(sdist, g_Wt + 4*4096, n0, g, tig, r2ok, acc0, acc1);
            __syncwarp();
            sdwT[ o0     *28 + g     ] = tf32(acc0[0]);
            sdwT[(o0 + 1)*28 + g     ] = tf32(acc0[1]);
            sdwT[ o0     *28 + g + 8 ] = tf32(acc0[2]);
            sdwT[(o0 + 1)*28 + g + 8 ] = tf32(acc0[3]);
            if (r2ok){
                sdwT[ o0     *28 + g + 16] = tf32(acc1[0]);
                sdwT[(o0 + 1)*28 + g + 16] = tf32(acc1[1]);
            }
            __syncwarp();

            float az0[4] = {0,0,0,0}, az1[4] = {0,0,0,0};
#pragma unroll
            for (int k8 = 0; k8 < 3; k8++){
                int c0 = k8*8 + tig, c1 = c0 + 4;
                uint32 a0[4], a1[4], bz[2];
                a0[0] = sattT[ g      *24 + c0];
                a0[1] = sattT[(g + 8) *24 + c0];
                a0[2] = sattT[ g      *24 + c1];
                a0[3] = sattT[(g + 8) *24 + c1];
                a1[0] = r2ok ? sattT[(g + 16)*24 + c0] : 0u;
                a1[1] = 0u;
                a1[2] = r2ok ? sattT[(g + 16)*24 + c1] : 0u;
                a1[3] = 0u;
                bz[0] = sdwT[(n0 + g)*28 + c0];
                bz[1] = sdwT[(n0 + g)*28 + c1];
                mma_tf32(az0, a0, bz);
                mma_tf32(az1, a1, bz);
            }
            float su0 = 0.f, su1 = 0.f, sq0 = 0.f, sq1 = 0.f;
            int rr[3] = { g, g + 8, g + 16 };
            float va[3] = { az0[0], az0[2], az1[0] };
            float vb[3] = { az0[1], az0[3], az1[1] };
#pragma unroll
            for (int q = 0; q < 3; q++){
                if (q == 2 && !r2ok) break;
                int r = rr[q];
                float v0 = va[q] + bd.x, v1 = vb[q] + bd.y;
                *(float2*)&g_hbuf2[obase + r*64 + o0] = make_float2(v0, v1);
                su0 += v0; su1 += v1; sq0 += v0*v0; sq1 += v1*v1;
            }
            su0 = redg(su0); su1 = redg(su1); sq0 = redg(sq0); sq1 = redg(sq1);
            if (lane < 4){
                g_part1[(size_t)(4*64 + o0    )*NBT + bt] = su0;
                g_part1[(size_t)(4*64 + o0 + 1)*NBT + bt] = su1;
                g_part1[(size_t)(5*64 + o0    )*NBT + bt] = sq0;
                g_part1[(size_t)(5*64 + o0 + 1)*NBT + bt] = sq1;
            }
        }
    }
}

// ---------------- BN stats finalize (unchanged) ----------------
__global__ void k_finalize(int which, const float* __restrict__ gammas,
                           const float* __restrict__ betas)
{
    int ch = blockIdx.x, tid = threadIdx.x;
    int b = ch >> 6, o = ch & 63;
    const float* part = which ? g_part2 : g_part1;
    const float* psum = part + (size_t)((2*b  )*64 + o) * NBT;
    const float* psq  = part + (size_t)((2*b+1)*64 + o) * NBT;
    __shared__ float r1[256], r2[256];
    float s = 0.f, q = 0.f;
    for (int t = tid; t < NBT; t += 256){ s += psum[t]; q += psq[t]; }
    r1[tid] = s; r2[tid] = q;
    __syncthreads();
    for (int off = 128; off; off >>= 1){
        if (tid < off){ r1[tid] += r1[tid+off]; r2[tid] += r2[tid+off]; }
        __syncthreads();
    }
    if (tid == 0){
        const float invM = 1.f / 70400.f;
        float mu  = r1[0]*invM;
        float var = r2[0]*invM - mu*mu;
        int grow = which ? 3 : b;
        float g  = gammas[grow*64 + o], be = betas[grow*64 + o];
        float sc = g * rsqrtf(var + 1e-5f);
        if (which){ g_scale2[o]  = sc; g_shift2[o]  = be - mu*sc; }
        else      { g_scale1[ch] = sc; g_shift1[ch] = be - mu*sc; }
    }
}

// ---------------- BN+ReLU + cat matmul (192->64) + stats ----------------
__global__ __launch_bounds__(256) void k_cat(const float* __restrict__ cat_w)
{
    __shared__ __align__(16) uint32 scat[NND*CP];
    __shared__ float ssc[192], ssh[192];

    int tid = threadIdx.x;
    int lane = tid & 31, w = tid >> 5;
    int g = lane >> 2, tig = lane & 3;
    int n0 = w*8;
    int o0 = n0 + 2*tig;
    int r2ok = (g + 16) < NND;

    uint32 bc[24][2];
#pragma unroll
    for (int k8 = 0; k8 < 24; k8++){
        const float* wp = cat_w + (n0 + g)*192 + k8*8 + tig;
        bc[k8][0] = tf32(__ldg(wp));
        bc[k8][1] = tf32(__ldg(wp + 4));
    }
    for (int p = tid; p < 192; p += 256){ ssc[p] = g_scale1[p]; ssh[p] = g_shift1[p]; }

    for (int s = 0; s < SPB; s++){
        int bt = blockIdx.x*SPB + s;
        __syncthreads();

        const float* bufs[3] = { g_hbuf0, g_hbuf1, g_hbuf2 };
#pragma unroll
        for (int br = 0; br < 3; br++){
            const float4* hb = (const float4*)(bufs[br] + (size_t)bt*SLICE);
            for (int p = tid; p < SLICE/4; p += 256){
                float4 v = __ldg(hb + p);
                int i = p >> 4, c = (p & 15)*4;
                int f = br*64 + c;
                int base = i*CP + (f & ~7) + ((f >> 2) & 1);
                scat[base    ] = tf32(fmaxf(v.x*ssc[f  ] + ssh[f  ], 0.f));
                scat[base + 2] = tf32(fmaxf(v.y*ssc[f+1] + ssh[f+1], 0.f));
                scat[base + 4] = tf32(fmaxf(v.z*ssc[f+2] + ssh[f+2], 0.f));
                scat[base + 6] = tf32(fmaxf(v.w*ssc[f+3] + ssh[f+3], 0.f));
            }
        }
        __syncthreads();

        float acc0[4] = {0,0,0,0}, acc1[4] = {0,0,0,0};
#pragma unroll
        for (int k8 = 0; k8 < 24; k8++){
            const uint32* p0 = scat + g*CP + k8*8 + 2*tig;
            uint2 va = *(const uint2*)p0;
            uint2 vb = *(const uint2*)(p0 + 8*CP);
            uint2 vc = r2ok ? *(const uint2*)(p0 + 16*CP) : make_uint2(0u, 0u);
            uint32 a0[4] = { va.x, vb.x, va.y, vb.y };
            uint32 a1[4] = { vc.x, 0u,   vc.y, 0u   };
            mma_tf32(acc0, a0, bc[k8]);
            mma_tf32(acc1, a1, bc[k8]);
        }

        float su0 = 0.f, su1 = 0.f, sq0 = 0.f, sq1 = 0.f;
        int rr[3] = { g, g + 8, g + 16 };
        float va[3] = { acc0[0], acc0[2], acc1[0] };
        float vb[3] = { acc0[1], acc0[3], acc1[1] };
        size_t obase = (size_t)bt*SLICE;
#pragma unroll
        for (int q = 0; q < 3; q++){
            if (q == 2 && !r2ok) break;
            int r = rr[q];
            float v0 = va[q], v1 = vb[q];
            *(float2*)&g_pre2[obase + r*64 + o0] = make_float2(v0, v1);
            su0 += v0; su1 += v1; sq0 += v0*v0; sq1 += v1*v1;
        }
        su0 = redg(su0); su1 = redg(su1); sq0 = redg(sq0); sq1 = redg(sq1);
        if (lane < 4){
            g_part2[(size_t)(o0     )*NBT + bt] = su0;
            g_part2[(size_t)(o0 + 1 )*NBT + bt] = su1;
            g_part2[(size_t)(64 + o0    )*NBT + bt] = sq0;
            g_part2[(size_t)(64 + o0 + 1)*NBT + bt] = sq1;
        }
    }
}

// ---------------- final BN+ReLU elementwise ----------------
__global__ void k_out(float* __restrict__ out)
{
    size_t idx = (size_t)blockIdx.x*256 + threadIdx.x;
    if (idx < TOT/4){
        float4 v = reinterpret_cast<const float4*>(g_pre2)[idx];
        int ob = (int)((idx*4) & 63);
        v.x = fmaxf(v.x*g_scale2[ob  ] + g_shift2[ob  ], 0.f);
        v.y = fmaxf(v.y*g_scale2[ob+1] + g_shift2[ob+1], 0.f);
        v.z = fmaxf(v.z*g_scale2[ob+2] + g_shift2[ob+2], 0.f);
        v.w = fmaxf(v.w*g_scale2[ob+3] + g_shift2[ob+3], 0.f);
        reinterpret_cast<float4*>(out)[idx] = v;
    }
}

// ---------------- launch ----------------
#define KMAIN_SMEM_BYTES (19704*4)

extern "C" void kernel_launch(void* const* d_in, const int* in_sizes, int n_in,
                              void* d_out, int out_size)
{
    const float* x        = (const float*)d_in[0];
    const float* W_sym    = (const float*)d_in[1];
    const float* e_sym    = (const float*)d_in[2];
    const float* W_con    = (const float*)d_in[3];
    const float* e_con    = (const float*)d_in[4];
    const float* W_dis    = (const float*)d_in[5];
    const float* att      = (const float*)d_in[6];
    const float* b_dis    = (const float*)d_in[7];
    const float* cat_w    = (const float*)d_in[8];
    const float* gammas   = (const float*)d_in[9];
    const float* betas    = (const float*)d_in[10];
    const int*   rows_sym = (const int*)d_in[11];
    const int*   cols_sym = (const int*)d_in[12];
    const int*   rows_con = (const int*)d_in[13];
    const int*   cols_con = (const int*)d_in[14];
    int nnz_sym = in_sizes[11];
    int nnz_con = in_sizes[13];

    static int configured = 0;
    if (!configured){
        cudaFuncSetAttribute(k_main, cudaFuncAttributeMaxDynamicSharedMemorySize, KMAIN_SMEM_BYTES);
        configured = 1;
    }

    k_prep<<<3, 256>>>(e_sym, rows_sym, cols_sym, nnz_sym,
                       e_con, rows_con, cols_con, nnz_con,
                       W_sym, W_con, W_dis);
    k_main<<<GRID1, 256, KMAIN_SMEM_BYTES>>>(x, att, b_dis);
    k_finalize<<<192, 256>>>(0, gammas, betas);
    k_cat<<<GRID1, 256>>>(cat_w);
    k_finalize<<<64, 256>>>(1, gammas, betas);
    k_out<<<(TOT/4 + 255)/256, 256>>>((float*)d_out);
    (void)n_in; (void)out_size;
}

// round 8
// speedup vs baseline: 1.0660x; 1.0660x over previous
#include <cuda_runtime.h>
#include <cstdint>

typedef unsigned int uint32;

#define NBT   3200          // B*T
#define NND   22
#define NCH   64
#define SLICE (NND*NCH)     // 1408
#define TOT   (NBT*SLICE)
#define MAXNZ 484
#define SPB   4             // slices per block
#define GRID1 (NBT/SPB)     // 800
#define OFFCAP0 32
#define OFFCAP1 96
#define XP    72            // pitch of permuted tf32 buffers in k_main (72 mod 32 = 8)
// permuted column position within an 8-col group: order [0,4,1,5,2,6,3,7]
#define POSC(c) (((c) & ~7) + 2*((c) & 3) + (((c) >> 2) & 1))

// ---------------- device scratch ----------------
__device__ float g_hbuf0[TOT];
__device__ float g_hbuf1[TOT];
__device__ float g_hbuf2[TOT];
__device__ float g_pre2[TOT];
__device__ float g_part1[6*64*NBT];
__device__ float g_part2[2*64*NBT];
__device__ float g_scale1[192], g_shift1[192];
__device__ float g_scale2[64],  g_shift2[64];
__device__ float g_Wt[5*4096];          // [g][o][c]
__device__ float g_diag[2][NND*NCH];
__device__ float g_offv[2][MAXNZ*NCH];
__device__ int   g_offcol[2][MAXNZ];
__device__ int   g_rowptr[2][NND+1];

// ---------------- helpers ----------------
__device__ __forceinline__ uint32 tf32(float f){
    uint32 r; asm("cvt.rna.tf32.f32 %0, %1;" : "=r"(r) : "f"(f)); return r;
}
__device__ __forceinline__ void mma_tf32(float c[4], const uint32 a[4], const uint32 b[2]){
    asm volatile("mma.sync.aligned.m16n8k8.row.col.f32.tf32.tf32.f32 "
                 "{%0,%1,%2,%3}, {%4,%5,%6,%7}, {%8,%9}, {%0,%1,%2,%3};"
                 : "+f"(c[0]), "+f"(c[1]), "+f"(c[2]), "+f"(c[3])
                 : "r"(a[0]), "r"(a[1]), "r"(a[2]), "r"(a[3]),
                   "r"(b[0]), "r"(b[1]));
}
__device__ __forceinline__ float redg(float v){
    v += __shfl_down_sync(0xffffffffu, v, 16);
    v += __shfl_down_sync(0xffffffffu, v, 8);
    v += __shfl_down_sync(0xffffffffu, v, 4);
    return v;
}

// ---------------- prep (unchanged, proven) ----------------
__global__ void k_prep(const float* __restrict__ e_sym, const int* __restrict__ rows_sym,
                       const int* __restrict__ cols_sym, int nnz_sym,
                       const float* __restrict__ e_con, const int* __restrict__ rows_con,
                       const int* __restrict__ cols_con, int nnz_con,
                       const float* __restrict__ W_sym, const float* __restrict__ W_con,
                       const float* __restrict__ W_dis)
{
    int blk = blockIdx.x, tid = threadIdx.x;
    if (blk == 2){
        for (int p = tid; p < 5*4096; p += 256){
            int g = p >> 12, rem = p & 4095, c = rem >> 6, o = rem & 63;
            float v;
            if (g < 2)      v = W_sym[g*4096 + c*64 + o];
            else if (g < 4) v = W_con[(g-2)*4096 + c*64 + o];
            else            v = W_dis[c*64 + o];
            g_Wt[g*4096 + o*64 + c] = v;
        }
        return;
    }
    int br = blk;
    const float* e  = br ? e_con   : e_sym;
    const int* rows = br ? rows_con : rows_sym;
    const int* cols = br ? cols_con : cols_sym;
    int nnz         = br ? nnz_con : nnz_sym;

    __shared__ float sden[NND*NCH];
    __shared__ int   smap[512];

    for (int p = tid; p < NND*NCH; p += 256) g_diag[br][p] = 0.f;
    __syncthreads();

    if (tid == 0){
        int m = 0;
        for (int k = 0; k < nnz; k++){
            int r = rows[k], c = cols[k];
            if (c != r){ smap[k] = m; g_offcol[br][m] = c; m++; }
            else smap[k] = -1;
        }
        for (int i = 0; i <= NND; i++){
            int cnt = 0;
            for (int k = 0; k < nnz; k++)
                if (cols[k] != rows[k] && rows[k] < i) cnt++;
            g_rowptr[br][i] = cnt;
        }
    }
    __syncthreads();

    for (int p = tid; p < NND*NCH; p += 256){
        int i = p >> 6, o = p & 63;
        float s = 0.f;
        for (int k = 0; k < nnz; k++)
            if (rows[k] == i) s += expf(e[o*nnz + k]);
        sden[p] = s;
    }
    __syncthreads();

    for (int p = tid; p < 64*nnz; p += 256){
        int k = p >> 6, o = p & 63;
        int r = rows[k];
        float v = expf(e[o*nnz + k]) / sden[r*64 + o];
        int m = smap[k];
        if (m < 0) g_diag[br][r*64 + o] = v;
        else       g_offv[br][m*64 + o] = v;
    }
}

// single gemm K=64, permuted tf32 smem (pitch XP), B streamed from global (Wdis)
__device__ __forceinline__ void mma8g64(const uint32* __restrict__ sbuf,
                                        const float* __restrict__ wg,
                                        int n0, int g, int tig, int r2ok,
                                        float acc0[4], float acc1[4]){
#pragma unroll
    for (int k8 = 0; k8 < 8; k8++){
        const float* wp = wg + (n0 + g)*64 + k8*8 + tig;
        uint32 b[2];
        b[0] = tf32(__ldg(wp));
        b[1] = tf32(__ldg(wp + 4));
        const uint32* p0 = sbuf + g*XP + k8*8 + 2*tig;
        uint2 va = *(const uint2*)p0;
        uint2 vb = *(const uint2*)(p0 + 8*XP);
        uint2 vc = r2ok ? *(const uint2*)(p0 + 16*XP) : make_uint2(0u, 0u);
        uint32 a0[4] = { va.x, vb.x, va.y, vb.y };
        uint32 a1[4] = { vc.x, 0u,   vc.y, 0u   };
        mma_tf32(acc0, a0, b);
        mma_tf32(acc1, a1, b);
    }
}

// ---------------- main fused kernel ----------------
__global__ __launch_bounds__(256, 2) void k_main(const float* __restrict__ x,
                                                 const float* __restrict__ att,
                                                 const float* __restrict__ b_dis)
{
    extern __shared__ __align__(16) float smem_[];
    float*  sx    = smem_;                         // 1496 (pitch 68, fp32)
    uint32* sxt   = (uint32*)(sx + 1496);          // 1584 (pitch 72, permuted tf32)
    uint32* sdist = sxt + 1584;                    // 1584
    float*  sh1s  = (float*)(sdist + 1584);        // 1408
    float*  sh1c  = sh1s + 1408;                   // 1408
    uint32* sdwT  = (uint32*)(sh1c + 1408);        // 1792 (64*28)
    uint32* sattT = sdwT + 1792;                   // 528 (22*24)
    float*  sdiag = (float*)(sattT + 528);         // 2816
    float*  soffv = sdiag + 2816;                  // 8192
    int*    ssrp  = (int*)(soffv + 8192);          // 48
    int*    ssocol= ssrp + 48;                     // 128
    float*  sS1   = (float*)(ssocol + 128);        // 64
    float*  sS2   = sS1 + 64;                      // 64

    int tid = threadIdx.x;
    int lane = tid & 31, w = tid >> 5;
    int g = lane >> 2, tig = lane & 3;
    int n0 = w*8;
    int o0 = n0 + 2*tig;
    int r2ok = (g + 16) < NND;

    // persistent B fragments: W0s, W1s, W0c, W1c (Wdis streams from L2)
    uint32 bw0s[8][2], bw1s[8][2], bw0c[8][2], bw1c[8][2];
#pragma unroll
    for (int k8 = 0; k8 < 8; k8++){
        const float* w0 = g_Wt + 0*4096 + (n0 + g)*64 + k8*8 + tig;
        const float* w1 = g_Wt + 1*4096 + (n0 + g)*64 + k8*8 + tig;
        const float* w2 = g_Wt + 2*4096 + (n0 + g)*64 + k8*8 + tig;
        const float* w3 = g_Wt + 3*4096 + (n0 + g)*64 + k8*8 + tig;
        bw0s[k8][0] = tf32(__ldg(w0)); bw0s[k8][1] = tf32(__ldg(w0 + 4));
        bw1s[k8][0] = tf32(__ldg(w1)); bw1s[k8][1] = tf32(__ldg(w1 + 4));
        bw0c[k8][0] = tf32(__ldg(w2)); bw0c[k8][1] = tf32(__ldg(w2 + 4));
        bw1c[k8][0] = tf32(__ldg(w3)); bw1c[k8][1] = tf32(__ldg(w3 + 4));
    }

    // ---- block-constant staging ----
    for (int p = tid; p < NND*24; p += 256){
        int i = p / 24, c = p % 24;
        sattT[p] = (c < NND) ? tf32(__ldg(&att[i*NND + c])) : 0u;
    }
    for (int p = tid; p < 64*28; p += 256) sdwT[p] = 0u;
    for (int p = tid; p < 2*(NND+1); p += 256) ssrp[(p/(NND+1))*23 + (p%(NND+1))] = g_rowptr[p/(NND+1)][p%(NND+1)];
    for (int p = tid; p < 2*NND*64; p += 256) sdiag[p] = g_diag[p/(NND*64)][p%(NND*64)];
    {
        int cnt0 = g_rowptr[0][NND]; if (cnt0 > OFFCAP0) cnt0 = OFFCAP0;
        int cnt1 = g_rowptr[1][NND]; if (cnt1 > OFFCAP1) cnt1 = OFFCAP1;
        for (int p = tid; p < cnt0*64; p += 256) soffv[p] = g_offv[0][p];
        for (int p = tid; p < cnt1*64; p += 256) soffv[OFFCAP0*64 + p] = g_offv[1][p];
        for (int p = tid; p < cnt0; p += 256) ssocol[p] = g_offcol[0][p];
        for (int p = tid; p < cnt1; p += 256) ssocol[OFFCAP0 + p] = g_offcol[1][p];
    }

    float2 bd = *(const float2*)&b_dis[o0];

    // prefetch slice 0
    float4 xr0, xr1;
    {
        const float4* xg = (const float4*)(x + (size_t)(blockIdx.x*SPB)*SLICE);
        xr0 = __ldg(xg + tid);
        xr1 = (tid + 256 < SLICE/4) ? __ldg(xg + tid + 256) : make_float4(0,0,0,0);
    }

    for (int s = 0; s < SPB; s++){
        int bt = blockIdx.x*SPB + s;
        __syncthreads();

        // write prefetched x: fp32 (pitch 68) + permuted tf32 (pitch 72)
        {
            int i = tid >> 4, c = (tid & 15)*4;
            *(float4*)&sx[i*68 + c] = xr0;
            int base = i*XP + (c & ~7) + ((c >> 2) & 1);
            sxt[base    ] = tf32(xr0.x);
            sxt[base + 2] = tf32(xr0.y);
            sxt[base + 4] = tf32(xr0.z);
            sxt[base + 6] = tf32(xr0.w);
            if (tid + 256 < SLICE/4){
                int p = tid + 256; i = p >> 4; c = (p & 15)*4;
                *(float4*)&sx[i*68 + c] = xr1;
                base = i*XP + (c & ~7) + ((c >> 2) & 1);
                sxt[base    ] = tf32(xr1.x);
                sxt[base + 2] = tf32(xr1.y);
                sxt[base + 4] = tf32(xr1.z);
                sxt[base + 6] = tf32(xr1.w);
            }
        }
        if (s + 1 < SPB){
            const float4* xg = (const float4*)(x + (size_t)(bt + 1)*SLICE);
            xr0 = __ldg(xg + tid);
            if (tid + 256 < SLICE/4) xr1 = __ldg(xg + tid + 256);
        }
        __syncthreads();

        if (tid < 64){
            float s1 = 0.f, s2 = 0.f;
#pragma unroll
            for (int i = 0; i < NND; i++){
                float v = sx[i*68 + tid];
                s1 += v; s2 += v*v;
            }
            sS1[tid] = s1; sS2[tid] = s2;
        }
        __syncthreads();

        for (int p = tid; p < SLICE; p += 256){
            int i = p >> 6, c = p & 63;
            float v = sx[i*68 + c];
            float d = sS2[c] - 2.f*v*sS1[c] + (float)NND*v*v;
            sdist[i*XP + POSC(c)] = tf32(sqrtf(fmaxf(d, 0.f)) + 1e-8f);
        }
        __syncthreads();

        size_t obase = (size_t)bt*SLICE;

        // ===== fused 4-weight x-gemm: ONE pass over A, 8 mma per kstep =====
        float hs0[4] = {0,0,0,0}, hs1[4] = {0,0,0,0};   // h0s
        float es0[4] = {0,0,0,0}, es1[4] = {0,0,0,0};   // h1s
        float hc0[4] = {0,0,0,0}, hc1[4] = {0,0,0,0};   // h0c
        float ec0[4] = {0,0,0,0}, ec1[4] = {0,0,0,0};   // h1c
#pragma unroll
        for (int k8 = 0; k8 < 8; k8++){
            const uint32* p0 = sxt + g*XP + k8*8 + 2*tig;
            uint2 va = *(const uint2*)p0;
            uint2 vb = *(const uint2*)(p0 + 8*XP);
            uint2 vc = r2ok ? *(const uint2*)(p0 + 16*XP) : make_uint2(0u, 0u);
            uint32 A0[4] = { va.x, vb.x, va.y, vb.y };
            uint32 A1[4] = { vc.x, 0u,   vc.y, 0u   };
            mma_tf32(hs0, A0, bw0s[k8]);  mma_tf32(hs1, A1, bw0s[k8]);
            mma_tf32(es0, A0, bw1s[k8]);  mma_tf32(es1, A1, bw1s[k8]);
            mma_tf32(hc0, A0, bw0c[k8]);  mma_tf32(hc1, A1, bw0c[k8]);
            mma_tf32(ec0, A0, bw1c[k8]);  mma_tf32(ec1, A1, bw1c[k8]);
        }
        __syncwarp();
        // store both h1 results to their smem buffers (own column stripe)
        sh1s[ g      *64 + o0    ] = es0[0];
        sh1s[ g      *64 + o0 + 1] = es0[1];
        sh1s[(g + 8) *64 + o0    ] = es0[2];
        sh1s[(g + 8) *64 + o0 + 1] = es0[3];
        sh1c[ g      *64 + o0    ] = ec0[0];
        sh1c[ g      *64 + o0 + 1] = ec0[1];
        sh1c[(g + 8) *64 + o0    ] = ec0[2];
        sh1c[(g + 8) *64 + o0 + 1] = ec0[3];
        if (r2ok){
            sh1s[(g + 16)*64 + o0    ] = es1[0];
            sh1s[(g + 16)*64 + o0 + 1] = es1[1];
            sh1c[(g + 16)*64 + o0    ] = ec1[0];
            sh1c[(g + 16)*64 + o0 + 1] = ec1[1];
        }
        __syncwarp();

        // ===== mix epilogues for branches s and c =====
#pragma unroll
        for (int br = 0; br < 2; br++){
            const float* sh1 = br ? sh1c : sh1s;
            int ob = br ? OFFCAP0 : 0;
            float su0 = 0.f, su1 = 0.f, sq0 = 0.f, sq1 = 0.f;
            int rr[3] = { g, g + 8, g + 16 };
            float va[3], vb[3];
            if (br == 0){ va[0]=hs0[0]; va[1]=hs0[2]; va[2]=hs1[0]; vb[0]=hs0[1]; vb[1]=hs0[3]; vb[2]=hs1[1]; }
            else        { va[0]=hc0[0]; va[1]=hc0[2]; va[2]=hc1[0]; vb[0]=hc0[1]; vb[1]=hc0[3]; vb[2]=hc1[1]; }
#pragma unroll
            for (int q = 0; q < 3; q++){
                if (q == 2 && !r2ok) break;
                int r = rr[q];
                float2 dg = *(const float2*)&sdiag[br*(NND*64) + r*64 + o0];
                float v0 = va[q]*dg.x, v1 = vb[q]*dg.y;
                int mb = ssrp[br*23 + r], me = ssrp[br*23 + r + 1];
                for (int m = mb; m < me; m++){
                    int cm = ssocol[ob + m];
                    float2 ov = *(const float2*)&soffv[(ob + m)*64 + o0];
                    v0 += ov.x * sh1[cm*64 + o0];
                    v1 += ov.y * sh1[cm*64 + o0 + 1];
                }
                float2 st = make_float2(v0, v1);
                if (br == 0) *(float2*)&g_hbuf0[obase + r*64 + o0] = st;
                else         *(float2*)&g_hbuf1[obase + r*64 + o0] = st;
                su0 += v0; su1 += v1; sq0 += v0*v0; sq1 += v1*v1;
            }
            su0 = redg(su0); su1 = redg(su1); sq0 = redg(sq0); sq1 = redg(sq1);
            if (lane < 4){
                g_part1[(size_t)((2*br  )*64 + o0    )*NBT + bt] = su0;
                g_part1[(size_t)((2*br  )*64 + o0 + 1)*NBT + bt] = su1;
                g_part1[(size_t)((2*br+1)*64 + o0    )*NBT + bt] = sq0;
                g_part1[(size_t)((2*br+1)*64 + o0 + 1)*NBT + bt] = sq1;
            }
        }

        // ===== z branch =====
        {
            float acc0[4] = {0,0,0,0}, acc1[4] = {0,0,0,0};
            mma8g64(sdist, g_Wt + 4*4096, n0, g, tig, r2ok, acc0, acc1);
            __syncwarp();
            sdwT[ o0     *28 + g     ] = tf32(acc0[0]);
            sdwT[(o0 + 1)*28 + g     ] = tf32(acc0[1]);
            sdwT[ o0     *28 + g + 8 ] = tf32(acc0[2]);
            sdwT[(o0 + 1)*28 + g + 8 ] = tf32(acc0[3]);
            if (r2ok){
                sdwT[ o0     *28 + g + 16] = tf32(acc1[0]);
                sdwT[(o0 + 1)*28 + g + 16] = tf32(acc1[1]);
            }
            __syncwarp();

            float az0[4] = {0,0,0,0}, az1[4] = {0,0,0,0};
#pragma unroll
            for (int k8 = 0; k8 < 3; k8++){
                int c0 = k8*8 + tig, c1 = c0 + 4;
                uint32 a0[4], a1[4], bz[2];
                a0[0] = sattT[ g      *24 + c0];
                a0[1] = sattT[(g + 8) *24 + c0];
                a0[2] = sattT[ g      *24 + c1];
                a0[3] = sattT[(g + 8) *24 + c1];
                a1[0] = r2ok ? sattT[(g + 16)*24 + c0] : 0u;
                a1[1] = 0u;
                a1[2] = r2ok ? sattT[(g + 16)*24 + c1] : 0u;
                a1[3] = 0u;
                bz[0] = sdwT[(n0 + g)*28 + c0];
                bz[1] = sdwT[(n0 + g)*28 + c1];
                mma_tf32(az0, a0, bz);
                mma_tf32(az1, a1, bz);
            }
            float su0 = 0.f, su1 = 0.f, sq0 = 0.f, sq1 = 0.f;
            int rr[3] = { g, g + 8, g + 16 };
            float va[3] = { az0[0], az0[2], az1[0] };
            float vb[3] = { az0[1], az0[3], az1[1] };
#pragma unroll
            for (int q = 0; q < 3; q++){
                if (q == 2 && !r2ok) break;
                int r = rr[q];
                float v0 = va[q] + bd.x, v1 = vb[q] + bd.y;
                *(float2*)&g_hbuf2[obase + r*64 + o0] = make_float2(v0, v1);
                su0 += v0; su1 += v1; sq0 += v0*v0; sq1 += v1*v1;
            }
            su0 = redg(su0); su1 = redg(su1); sq0 = redg(sq0); sq1 = redg(sq1);
            if (lane < 4){
                g_part1[(size_t)(4*64 + o0    )*NBT + bt] = su0;
                g_part1[(size_t)(4*64 + o0 + 1)*NBT + bt] = su1;
                g_part1[(size_t)(5*64 + o0    )*NBT + bt] = sq0;
                g_part1[(size_t)(5*64 + o0 + 1)*NBT + bt] = sq1;
            }
        }
    }
}

// ---------------- BN stats finalize (unchanged) ----------------
__global__ void k_finalize(int which, const float* __restrict__ gammas,
                           const float* __restrict__ betas)
{
    int ch = blockIdx.x, tid = threadIdx.x;
    int b = ch >> 6, o = ch & 63;
    const float* part = which ? g_part2 : g_part1;
    const float* psum = part + (size_t)((2*b  )*64 + o) * NBT;
    const float* psq  = part + (size_t)((2*b+1)*64 + o) * NBT;
    __shared__ float r1[256], r2[256];
    float s = 0.f, q = 0.f;
    for (int t = tid; t < NBT; t += 256){ s += psum[t]; q += psq[t]; }
    r1[tid] = s; r2[tid] = q;
    __syncthreads();
    for (int off = 128; off; off >>= 1){
        if (tid < off){ r1[tid] += r1[tid+off]; r2[tid] += r2[tid+off]; }
        __syncthreads();
    }
    if (tid == 0){
        const float invM = 1.f / 70400.f;
        float mu  = r1[0]*invM;
        float var = r2[0]*invM - mu*mu;
        int grow = which ? 3 : b;
        float g  = gammas[grow*64 + o], be = betas[grow*64 + o];
        float sc = g * rsqrtf(var + 1e-5f);
        if (which){ g_scale2[o]  = sc; g_shift2[o]  = be - mu*sc; }
        else      { g_scale1[ch] = sc; g_shift1[ch] = be - mu*sc; }
    }
}

// ---------------- BN+ReLU + cat matmul (192->64) + stats — R6 version (proven 53us) ----------------
__global__ __launch_bounds__(256) void k_cat(const float* __restrict__ cat_w)
{
    __shared__ __align__(16) uint32 scat[NND*196];
    __shared__ float ssc[192], ssh[192];

    int tid = threadIdx.x;
    int lane = tid & 31, w = tid >> 5;
    int g = lane >> 2, tig = lane & 3;
    int n0 = w*8;
    int o0 = n0 + 2*tig;
    int r2ok = (g + 16) < NND;

    uint32 bc[24][2];
#pragma unroll
    for (int k8 = 0; k8 < 24; k8++){
        const float* wp = cat_w + (n0 + g)*192 + k8*8 + tig;
        bc[k8][0] = tf32(__ldg(wp));
        bc[k8][1] = tf32(__ldg(wp + 4));
    }
    for (int p = tid; p < 192; p += 256){ ssc[p] = g_scale1[p]; ssh[p] = g_shift1[p]; }

    for (int s = 0; s < SPB; s++){
        int bt = blockIdx.x*SPB + s;
        __syncthreads();

        const float* bufs[3] = { g_hbuf0, g_hbuf1, g_hbuf2 };
#pragma unroll
        for (int br = 0; br < 3; br++){
            const float4* hb = (const float4*)(bufs[br] + (size_t)bt*SLICE);
            for (int p = tid; p < SLICE/4; p += 256){
                float4 v = __ldg(hb + p);
                int i = p >> 4, c = (p & 15)*4;
                int f = br*64 + c;
                uint32* dst = &scat[i*196 + f];
                dst[0] = tf32(fmaxf(v.x*ssc[f  ] + ssh[f  ], 0.f));
                dst[1] = tf32(fmaxf(v.y*ssc[f+1] + ssh[f+1], 0.f));
                dst[2] = tf32(fmaxf(v.z*ssc[f+2] + ssh[f+2], 0.f));
                dst[3] = tf32(fmaxf(v.w*ssc[f+3] + ssh[f+3], 0.f));
            }
        }
        __syncthreads();

        float acc0[4] = {0,0,0,0}, acc1[4] = {0,0,0,0};
#pragma unroll
        for (int k8 = 0; k8 < 24; k8++){
            int c0 = k8*8 + tig, c1 = c0 + 4;
            uint32 a0[4], a1[4];
            a0[0] = scat[ g      *196 + c0];
            a0[1] = scat[(g + 8) *196 + c0];
            a0[2] = scat[ g      *196 + c1];
            a0[3] = scat[(g + 8) *196 + c1];
            a1[0] = r2ok ? scat[(g + 16)*196 + c0] : 0u;
            a1[1] = 0u;
            a1[2] = r2ok ? scat[(g + 16)*196 + c1] : 0u;
            a1[3] = 0u;
            mma_tf32(acc0, a0, bc[k8]);
            mma_tf32(acc1, a1, bc[k8]);
        }

        float su0 = 0.f, su1 = 0.f, sq0 = 0.f, sq1 = 0.f;
        int rr[3] = { g, g + 8, g + 16 };
        float va[3] = { acc0[0], acc0[2], acc1[0] };
        float vb[3] = { acc0[1], acc0[3], acc1[1] };
        size_t obase = (size_t)bt*SLICE;
#pragma unroll
        for (int q = 0; q < 3; q++){
            if (q == 2 && !r2ok) break;
            int r = rr[q];
            float v0 = va[q], v1 = vb[q];
            *(float2*)&g_pre2[obase + r*64 + o0] = make_float2(v0, v1);
            su0 += v0; su1 += v1; sq0 += v0*v0; sq1 += v1*v1;
        }
        su0 = redg(su0); su1 = redg(su1); sq0 = redg(sq0); sq1 = redg(sq1);
        if (lane < 4){
            g_part2[(size_t)(o0     )*NBT + bt] = su0;
            g_part2[(size_t)(o0 + 1 )*NBT + bt] = su1;
            g_part2[(size_t)(64 + o0    )*NBT + bt] = sq0;
            g_part2[(size_t)(64 + o0 + 1)*NBT + bt] = sq1;
        }
    }
}

// ---------------- final BN+ReLU elementwise ----------------
__global__ void k_out(float* __restrict__ out)
{
    size_t idx = (size_t)blockIdx.x*256 + threadIdx.x;
    if (idx < TOT/4){
        float4 v = reinterpret_cast<const float4*>(g_pre2)[idx];
        int ob = (int)((idx*4) & 63);
        v.x = fmaxf(v.x*g_scale2[ob  ] + g_shift2[ob  ], 0.f);
        v.y = fmaxf(v.y*g_scale2[ob+1] + g_shift2[ob+1], 0.f);
        v.z = fmaxf(v.z*g_scale2[ob+2] + g_shift2[ob+2], 0.f);
        v.w = fmaxf(v.w*g_scale2[ob+3] + g_shift2[ob+3], 0.f);
        reinterpret_cast<float4*>(out)[idx] = v;
    }
}

// ---------------- launch ----------------
#define KMAIN_SMEM_BYTES (21112*4)

extern "C" void kernel_launch(void* const* d_in, const int* in_sizes, int n_in,
                              void* d_out, int out_size)
{
    const float* x        = (const float*)d_in[0];
    const float* W_sym    = (const float*)d_in[1];
    const float* e_sym    = (const float*)d_in[2];
    const float* W_con    = (const float*)d_in[3];
    const float* e_con    = (const float*)d_in[4];
    const float* W_dis    = (const float*)d_in[5];
    const float* att      = (const float*)d_in[6];
    const float* b_dis    = (const float*)d_in[7];
    const float* cat_w    = (const float*)d_in[8];
    const float* gammas   = (const float*)d_in[9];
    const float* betas    = (const float*)d_in[10];
    const int*   rows_sym = (const int*)d_in[11];
    const int*   cols_sym = (const int*)d_in[12];
    const int*   rows_con = (const int*)d_in[13];
    const int*   cols_con = (const int*)d_in[14];
    int nnz_sym = in_sizes[11];
    int nnz_con = in_sizes[13];

    static int configured = 0;
    if (!configured){
        cudaFuncSetAttribute(k_main, cudaFuncAttributeMaxDynamicSharedMemorySize, KMAIN_SMEM_BYTES);
        configured = 1;
    }

    k_prep<<<3, 256>>>(e_sym, rows_sym, cols_sym, nnz_sym,
                       e_con, rows_con, cols_con, nnz_con,
                       W_sym, W_con, W_dis);
    k_main<<<GRID1, 256, KMAIN_SMEM_BYTES>>>(x, att, b_dis);
    k_finalize<<<192, 256>>>(0, gammas, betas);
    k_cat<<<GRID1, 256>>>(cat_w);
    k_finalize<<<64, 256>>>(1, gammas, betas);
    k_out<<<(TOT/4 + 255)/256, 256>>>((float*)d_out);
    (void)n_in; (void)out_size;
}

// round 10
// speedup vs baseline: 1.1029x; 1.0347x over previous
#include <cuda_runtime.h>
#include <cstdint>

typedef unsigned int uint32;

#define NBT   3200          // B*T
#define NND   22
#define NCH   64
#define SLICE (NND*NCH)     // 1408
#define TOT   (NBT*SLICE)
#define MAXNZ 484
#define SPB   4             // slices per block
#define GRID1 (NBT/SPB)     // 800
#define OFFCAP0 32
#define OFFCAP1 96
#define ROWCAP0 3           // max off-diag per row, branch sym
#define ROWCAP1 6           // max off-diag per row, branch con
#define XP    72            // pitch of permuted tf32 buffers in k_main (72 mod 32 = 8)
// permuted column position within an 8-col group: order [0,4,1,5,2,6,3,7]
#define POSC(c) (((c) & ~7) + 2*((c) & 3) + (((c) >> 2) & 1))

// ---------------- device scratch ----------------
__device__ float g_hbuf0[TOT];
__device__ float g_hbuf1[TOT];
__device__ float g_hbuf2[TOT];
__device__ float g_pre2[TOT];
__device__ float g_part1[6*64*NBT];
__device__ float g_part2[2*64*NBT];
__device__ float g_scale1[192], g_shift1[192];
__device__ float g_scale2[64],  g_shift2[64];
__device__ float g_Wt[5*4096];          // [g][o][c]
__device__ float g_diag[2][NND*NCH];
__device__ float g_offv[2][MAXNZ*NCH];
__device__ int   g_offcol[2][MAXNZ];
__device__ int   g_rowptr[2][NND+1];

// ---------------- helpers ----------------
__device__ __forceinline__ uint32 tf32(float f){
    uint32 r; asm("cvt.rna.tf32.f32 %0, %1;" : "=r"(r) : "f"(f)); return r;
}
__device__ __forceinline__ void mma_tf32(float c[4], const uint32 a[4], const uint32 b[2]){
    asm volatile("mma.sync.aligned.m16n8k8.row.col.f32.tf32.tf32.f32 "
                 "{%0,%1,%2,%3}, {%4,%5,%6,%7}, {%8,%9}, {%0,%1,%2,%3};"
                 : "+f"(c[0]), "+f"(c[1]), "+f"(c[2]), "+f"(c[3])
                 : "r"(a[0]), "r"(a[1]), "r"(a[2]), "r"(a[3]),
                   "r"(b[0]), "r"(b[1]));
}
__device__ __forceinline__ float redg(float v){
    v += __shfl_down_sync(0xffffffffu, v, 16);
    v += __shfl_down_sync(0xffffffffu, v, 8);
    v += __shfl_down_sync(0xffffffffu, v, 4);
    return v;
}

// ---------------- prep (unchanged, proven) ----------------
__global__ void k_prep(const float* __restrict__ e_sym, const int* __restrict__ rows_sym,
                       const int* __restrict__ cols_sym, int nnz_sym,
                       const float* __restrict__ e_con, const int* __restrict__ rows_con,
                       const int* __restrict__ cols_con, int nnz_con,
                       const float* __restrict__ W_sym, const float* __restrict__ W_con,
                       const float* __restrict__ W_dis)
{
    int blk = blockIdx.x, tid = threadIdx.x;
    if (blk == 2){
        for (int p = tid; p < 5*4096; p += 256){
            int g = p >> 12, rem = p & 4095, c = rem >> 6, o = rem & 63;
            float v;
            if (g < 2)      v = W_sym[g*4096 + c*64 + o];
            else if (g < 4) v = W_con[(g-2)*4096 + c*64 + o];
            else            v = W_dis[c*64 + o];
            g_Wt[g*4096 + o*64 + c] = v;
        }
        return;
    }
    int br = blk;
    const float* e  = br ? e_con   : e_sym;
    const int* rows = br ? rows_con : rows_sym;
    const int* cols = br ? cols_con : cols_sym;
    int nnz         = br ? nnz_con : nnz_sym;

    __shared__ float sden[NND*NCH];
    __shared__ int   smap[512];

    for (int p = tid; p < NND*NCH; p += 256) g_diag[br][p] = 0.f;
    __syncthreads();

    if (tid == 0){
        int m = 0;
        for (int k = 0; k < nnz; k++){
            int r = rows[k], c = cols[k];
            if (c != r){ smap[k] = m; g_offcol[br][m] = c; m++; }
            else smap[k] = -1;
        }
        for (int i = 0; i <= NND; i++){
            int cnt = 0;
            for (int k = 0; k < nnz; k++)
                if (cols[k] != rows[k] && rows[k] < i) cnt++;
            g_rowptr[br][i] = cnt;
        }
    }
    __syncthreads();

    for (int p = tid; p < NND*NCH; p += 256){
        int i = p >> 6, o = p & 63;
        float s = 0.f;
        for (int k = 0; k < nnz; k++)
            if (rows[k] == i) s += expf(e[o*nnz + k]);
        sden[p] = s;
    }
    __syncthreads();

    for (int p = tid; p < 64*nnz; p += 256){
        int k = p >> 6, o = p & 63;
        int r = rows[k];
        float v = expf(e[o*nnz + k]) / sden[r*64 + o];
        int m = smap[k];
        if (m < 0) g_diag[br][r*64 + o] = v;
        else       g_offv[br][m*64 + o] = v;
    }
}

// single gemm K=64, permuted tf32 smem (pitch XP), B streamed from global (Wdis)
__device__ __forceinline__ void mma8g64(const uint32* __restrict__ sbuf,
                                        const float* __restrict__ wg,
                                        int n0, int g, int tig, int r2ok,
                                        float acc0[4], float acc1[4]){
#pragma unroll
    for (int k8 = 0; k8 < 8; k8++){
        const float* wp = wg + (n0 + g)*64 + k8*8 + tig;
        uint32 b[2];
        b[0] = tf32(__ldg(wp));
        b[1] = tf32(__ldg(wp + 4));
        const uint32* p0 = sbuf + g*XP + k8*8 + 2*tig;
        uint2 va = *(const uint2*)p0;
        uint2 vb = *(const uint2*)(p0 + 8*XP);
        uint2 vc = r2ok ? *(const uint2*)(p0 + 16*XP) : make_uint2(0u, 0u);
        uint32 a0[4] = { va.x, vb.x, va.y, vb.y };
        uint32 a1[4] = { vc.x, 0u,   vc.y, 0u   };
        mma_tf32(acc0, a0, b);
        mma_tf32(acc1, a1, b);
    }
}

// ---------------- main fused kernel ----------------
__global__ __launch_bounds__(256, 2) void k_main(const float* __restrict__ x,
                                                 const float* __restrict__ att,
                                                 const float* __restrict__ b_dis)
{
    extern __shared__ __align__(16) float smem_[];
    float*  sx    = smem_;                         // 1496 (pitch 68, fp32)
    uint32* sxt   = (uint32*)(sx + 1496);          // 1584 (pitch 72, permuted tf32)
    uint32* sdist = sxt + 1584;                    // 1584
    float*  sh1s  = (float*)(sdist + 1584);        // 1408
    float*  sh1c  = sh1s + 1408;                   // 1408
    uint32* sdwT  = (uint32*)(sh1c + 1408);        // 1792 (64*28)
    uint32* sattT = sdwT + 1792;                   // 528 (22*24)
    float*  sdiag = (float*)(sattT + 528);         // 2816
    float*  soffv = sdiag + 2816;                  // 8192
    int*    ssrp  = (int*)(soffv + 8192);          // 48
    int*    ssocol= ssrp + 48;                     // 128
    float*  sS1   = (float*)(ssocol + 128);        // 64
    float*  sS2   = sS1 + 64;                      // 64

    int tid = threadIdx.x;
    int lane = tid & 31, w = tid >> 5;
    int g = lane >> 2, tig = lane & 3;
    int n0 = w*8;
    int o0 = n0 + 2*tig;
    int r2ok = (g + 16) < NND;

    // persistent B fragments: W0s, W1s, W0c, W1c (Wdis streams from L2)
    uint32 bw0s[8][2], bw1s[8][2], bw0c[8][2], bw1c[8][2];
#pragma unroll
    for (int k8 = 0; k8 < 8; k8++){
        const float* w0 = g_Wt + 0*4096 + (n0 + g)*64 + k8*8 + tig;
        const float* w1 = g_Wt + 1*4096 + (n0 + g)*64 + k8*8 + tig;
        const float* w2 = g_Wt + 2*4096 + (n0 + g)*64 + k8*8 + tig;
        const float* w3 = g_Wt + 3*4096 + (n0 + g)*64 + k8*8 + tig;
        bw0s[k8][0] = tf32(__ldg(w0)); bw0s[k8][1] = tf32(__ldg(w0 + 4));
        bw1s[k8][0] = tf32(__ldg(w1)); bw1s[k8][1] = tf32(__ldg(w1 + 4));
        bw0c[k8][0] = tf32(__ldg(w2)); bw0c[k8][1] = tf32(__ldg(w2 + 4));
        bw1c[k8][0] = tf32(__ldg(w3)); bw1c[k8][1] = tf32(__ldg(w3 + 4));
    }

    // ---- block-constant staging ----
    for (int p = tid; p < NND*24; p += 256){
        int i = p / 24, c = p % 24;
        sattT[p] = (c < NND) ? tf32(__ldg(&att[i*NND + c])) : 0u;
    }
    for (int p = tid; p < 64*28; p += 256) sdwT[p] = 0u;
    for (int p = tid; p < 2*(NND+1); p += 256) ssrp[(p/(NND+1))*23 + (p%(NND+1))] = g_rowptr[p/(NND+1)][p%(NND+1)];
    for (int p = tid; p < 2*NND*64; p += 256) sdiag[p] = g_diag[p/(NND*64)][p%(NND*64)];
    {
        int cnt0 = g_rowptr[0][NND]; if (cnt0 > OFFCAP0) cnt0 = OFFCAP0;
        int cnt1 = g_rowptr[1][NND]; if (cnt1 > OFFCAP1) cnt1 = OFFCAP1;
        for (int p = tid; p < cnt0*64; p += 256) soffv[p] = g_offv[0][p];
        for (int p = tid; p < cnt1*64; p += 256) soffv[OFFCAP0*64 + p] = g_offv[1][p];
        for (int p = tid; p < cnt0; p += 256) ssocol[p] = g_offcol[0][p];
        for (int p = tid; p < cnt1; p += 256) ssocol[OFFCAP0 + p] = g_offcol[1][p];
    }

    float2 bd = *(const float2*)&b_dis[o0];

    // prefetch slice 0
    float4 xr0, xr1;
    {
        const float4* xg = (const float4*)(x + (size_t)(blockIdx.x*SPB)*SLICE);
        xr0 = __ldg(xg + tid);
        xr1 = (tid + 256 < SLICE/4) ? __ldg(xg + tid + 256) : make_float4(0,0,0,0);
    }

    for (int s = 0; s < SPB; s++){
        int bt = blockIdx.x*SPB + s;
        __syncthreads();

        // write prefetched x: fp32 (pitch 68) + permuted tf32 (pitch 72)
        {
            int i = tid >> 4, c = (tid & 15)*4;
            *(float4*)&sx[i*68 + c] = xr0;
            int base = i*XP + (c & ~7) + ((c >> 2) & 1);
            sxt[base    ] = tf32(xr0.x);
            sxt[base + 2] = tf32(xr0.y);
            sxt[base + 4] = tf32(xr0.z);
            sxt[base + 6] = tf32(xr0.w);
            if (tid + 256 < SLICE/4){
                int p = tid + 256; i = p >> 4; c = (p & 15)*4;
                *(float4*)&sx[i*68 + c] = xr1;
                base = i*XP + (c & ~7) + ((c >> 2) & 1);
                sxt[base    ] = tf32(xr1.x);
                sxt[base + 2] = tf32(xr1.y);
                sxt[base + 4] = tf32(xr1.z);
                sxt[base + 6] = tf32(xr1.w);
            }
        }
        if (s + 1 < SPB){
            const float4* xg = (const float4*)(x + (size_t)(bt + 1)*SLICE);
            xr0 = __ldg(xg + tid);
            if (tid + 256 < SLICE/4) xr1 = __ldg(xg + tid + 256);
        }
        __syncthreads();

        if (tid < 64){
            float s1 = 0.f, s2 = 0.f;
#pragma unroll
            for (int i = 0; i < NND; i++){
                float v = sx[i*68 + tid];
                s1 += v; s2 += v*v;
            }
            sS1[tid] = s1; sS2[tid] = s2;
        }
        __syncthreads();

        for (int p = tid; p < SLICE; p += 256){
            int i = p >> 6, c = p & 63;
            float v = sx[i*68 + c];
            float d = sS2[c] - 2.f*v*sS1[c] + (float)NND*v*v;
            sdist[i*XP + POSC(c)] = tf32(sqrtf(fmaxf(d, 0.f)) + 1e-8f);
        }
        __syncthreads();

        size_t obase = (size_t)bt*SLICE;

        // ===== fused 4-weight x-gemm: ONE pass over A, 8 mma per kstep =====
        float hs0[4] = {0,0,0,0}, hs1[4] = {0,0,0,0};   // h0s
        float es0[4] = {0,0,0,0}, es1[4] = {0,0,0,0};   // h1s
        float hc0[4] = {0,0,0,0}, hc1[4] = {0,0,0,0};   // h0c
        float ec0[4] = {0,0,0,0}, ec1[4] = {0,0,0,0};   // h1c
#pragma unroll
        for (int k8 = 0; k8 < 8; k8++){
            const uint32* p0 = sxt + g*XP + k8*8 + 2*tig;
            uint2 va = *(const uint2*)p0;
            uint2 vb = *(const uint2*)(p0 + 8*XP);
            uint2 vc = r2ok ? *(const uint2*)(p0 + 16*XP) : make_uint2(0u, 0u);
            uint32 A0[4] = { va.x, vb.x, va.y, vb.y };
            uint32 A1[4] = { vc.x, 0u,   vc.y, 0u   };
            mma_tf32(hs0, A0, bw0s[k8]);  mma_tf32(hs1, A1, bw0s[k8]);
            mma_tf32(es0, A0, bw1s[k8]);  mma_tf32(es1, A1, bw1s[k8]);
            mma_tf32(hc0, A0, bw0c[k8]);  mma_tf32(hc1, A1, bw0c[k8]);
            mma_tf32(ec0, A0, bw1c[k8]);  mma_tf32(ec1, A1, bw1c[k8]);
        }
        __syncwarp();
        // store both h1 results to their smem buffers (own column stripe)
        sh1s[ g      *64 + o0    ] = es0[0];
        sh1s[ g      *64 + o0 + 1] = es0[1];
        sh1s[(g + 8) *64 + o0    ] = es0[2];
        sh1s[(g + 8) *64 + o0 + 1] = es0[3];
        sh1c[ g      *64 + o0    ] = ec0[0];
        sh1c[ g      *64 + o0 + 1] = ec0[1];
        sh1c[(g + 8) *64 + o0    ] = ec0[2];
        sh1c[(g + 8) *64 + o0 + 1] = ec0[3];
        if (r2ok){
            sh1s[(g + 16)*64 + o0    ] = es1[0];
            sh1s[(g + 16)*64 + o0 + 1] = es1[1];
            sh1c[(g + 16)*64 + o0    ] = ec1[0];
            sh1c[(g + 16)*64 + o0 + 1] = ec1[1];
        }
        __syncwarp();

        // ===== mix epilogues for branches s and c (fixed-trip unrolled sparse loops) =====
#pragma unroll
        for (int br = 0; br < 2; br++){
            const float* sh1 = br ? sh1c : sh1s;
            const int ob = br ? OFFCAP0 : 0;
            const int CAP = br ? ROWCAP1 : ROWCAP0;
            float su0 = 0.f, su1 = 0.f, sq0 = 0.f, sq1 = 0.f;
            int rr[3] = { g, g + 8, g + 16 };
            float va[3], vb[3];
            if (br == 0){ va[0]=hs0[0]; va[1]=hs0[2]; va[2]=hs1[0]; vb[0]=hs0[1]; vb[1]=hs0[3]; vb[2]=hs1[1]; }
            else        { va[0]=hc0[0]; va[1]=hc0[2]; va[2]=hc1[0]; vb[0]=hc0[1]; vb[1]=hc0[3]; vb[2]=hc1[1]; }
#pragma unroll
            for (int q = 0; q < 3; q++){
                if (q == 2 && !r2ok) break;
                int r = rr[q];
                float2 dg = *(const float2*)&sdiag[br*(NND*64) + r*64 + o0];
                float v0 = va[q]*dg.x, v1 = vb[q]*dg.y;
                int mb = ssrp[br*23 + r], me = ssrp[br*23 + r + 1];
#pragma unroll
                for (int m = 0; m < CAP; m++){
                    int idx = mb + m;
                    if (idx < me){
                        int cm = ssocol[ob + idx];
                        float2 ov = *(const float2*)&soffv[(ob + idx)*64 + o0];
                        v0 += ov.x * sh1[cm*64 + o0];
                        v1 += ov.y * sh1[cm*64 + o0 + 1];
                    }
                }
                float2 st = make_float2(v0, v1);
                if (br == 0) *(float2*)&g_hbuf0[obase + r*64 + o0] = st;
                else         *(float2*)&g_hbuf1[obase + r*64 + o0] = st;
                su0 += v0; su1 += v1; sq0 += v0*v0; sq1 += v1*v1;
            }
            su0 = redg(su0); su1 = redg(su1); sq0 = redg(sq0); sq1 = redg(sq1);
            if (lane < 4){
                g_part1[(size_t)((2*br  )*64 + o0    )*NBT + bt] = su0;
                g_part1[(size_t)((2*br  )*64 + o0 + 1)*NBT + bt] = su1;
                g_part1[(size_t)((2*br+1)*64 + o0    )*NBT + bt] = sq0;
                g_part1[(size_t)((2*br+1)*64 + o0 + 1)*NBT + bt] = sq1;
            }
        }

        // ===== z branch =====
        {
            float acc0[4] = {0,0,0,0}, acc1[4] = {0,0,0,0};
            mma8g64(sdist, g_Wt + 4*4096, n0, g, tig, r2ok, acc0, acc1);
            __syncwarp();
            sdwT[ o0     *28 + g     ] = tf32(acc0[0]);
            sdwT[(o0 + 1)*28 + g     ] = tf32(acc0[1]);
            sdwT[ o0     *28 + g + 8 ] = tf32(acc0[2]);
            sdwT[(o0 + 1)*28 + g + 8 ] = tf32(acc0[3]);
            if (r2ok){
                sdwT[ o0     *28 + g + 16] = tf32(acc1[0]);
                sdwT[(o0 + 1)*28 + g + 16] = tf32(acc1[1]);
            }
            __syncwarp();

            float az0[4] = {0,0,0,0}, az1[4] = {0,0,0,0};
#pragma unroll
            for (int k8 = 0; k8 < 3; k8++){
                int c0 = k8*8 + tig, c1 = c0 + 4;
                uint32 a0[4], a1[4], bz[2];
                a0[0] = sattT[ g      *24 + c0];
                a0[1] = sattT[(g + 8) *24 + c0];
                a0[2] = sattT[ g      *24 + c1];
                a0[3] = sattT[(g + 8) *24 + c1];
                a1[0] = r2ok ? sattT[(g + 16)*24 + c0] : 0u;
                a1[1] = 0u;
                a1[2] = r2ok ? sattT[(g + 16)*24 + c1] : 0u;
                a1[3] = 0u;
                bz[0] = sdwT[(n0 + g)*28 + c0];
                bz[1] = sdwT[(n0 + g)*28 + c1];
                mma_tf32(az0, a0, bz);
                mma_tf32(az1, a1, bz);
            }
            float su0 = 0.f, su1 = 0.f, sq0 = 0.f, sq1 = 0.f;
            int rr[3] = { g, g + 8, g + 16 };
            float va[3] = { az0[0], az0[2], az1[0] };
            float vb[3] = { az0[1], az0[3], az1[1] };
#pragma unroll
            for (int q = 0; q < 3; q++){
                if (q == 2 && !r2ok) break;
                int r = rr[q];
                float v0 = va[q] + bd.x, v1 = vb[q] + bd.y;
                *(float2*)&g_hbuf2[obase + r*64 + o0] = make_float2(v0, v1);
                su0 += v0; su1 += v1; sq0 += v0*v0; sq1 += v1*v1;
            }
            su0 = redg(su0); su1 = redg(su1); sq0 = redg(sq0); sq1 = redg(sq1);
            if (lane < 4){
                g_part1[(size_t)(4*64 + o0    )*NBT + bt] = su0;
                g_part1[(size_t)(4*64 + o0 + 1)*NBT + bt] = su1;
                g_part1[(size_t)(5*64 + o0    )*NBT + bt] = sq0;
                g_part1[(size_t)(5*64 + o0 + 1)*NBT + bt] = sq1;
            }
        }
    }
}

// ---------------- BN stats finalize (unchanged) ----------------
__global__ void k_finalize(int which, const float* __restrict__ gammas,
                           const float* __restrict__ betas)
{
    int ch = blockIdx.x, tid = threadIdx.x;
    int b = ch >> 6, o = ch & 63;
    const float* part = which ? g_part2 : g_part1;
    const float* psum = part + (size_t)((2*b  )*64 + o) * NBT;
    const float* psq  = part + (size_t)((2*b+1)*64 + o) * NBT;
    __shared__ float r1[256], r2[256];
    float s = 0.f, q = 0.f;
    for (int t = tid; t < NBT; t += 256){ s += psum[t]; q += psq[t]; }
    r1[tid] = s; r2[tid] = q;
    __syncthreads();
    for (int off = 128; off; off >>= 1){
        if (tid < off){ r1[tid] += r1[tid+off]; r2[tid] += r2[tid+off]; }
        __syncthreads();
    }
    if (tid == 0){
        const float invM = 1.f / 70400.f;
        float mu  = r1[0]*invM;
        float var = r2[0]*invM - mu*mu;
        int grow = which ? 3 : b;
        float g  = gammas[grow*64 + o], be = betas[grow*64 + o];
        float sc = g * rsqrtf(var + 1e-5f);
        if (which){ g_scale2[o]  = sc; g_shift2[o]  = be - mu*sc; }
        else      { g_scale1[ch] = sc; g_shift1[ch] = be - mu*sc; }
    }
}

// ---------------- BN+ReLU + cat matmul (192->64): double-buffered prefetch ----------------
__global__ __launch_bounds__(256) void k_cat(const float* __restrict__ cat_w)
{
    __shared__ __align__(16) uint32 scat[2][NND*196];
    __shared__ float ssc[192], ssh[192];

    int tid = threadIdx.x;
    int lane = tid & 31, w = tid >> 5;
    int g = lane >> 2, tig = lane & 3;
    int n0 = w*8;
    int o0 = n0 + 2*tig;
    int r2ok = (g + 16) < NND;

    uint32 bc[24][2];
#pragma unroll
    for (int k8 = 0; k8 < 24; k8++){
        const float* wp = cat_w + (n0 + g)*192 + k8*8 + tig;
        bc[k8][0] = tf32(__ldg(wp));
        bc[k8][1] = tf32(__ldg(wp + 4));
    }
    for (int p = tid; p < 192; p += 256){ ssc[p] = g_scale1[p]; ssh[p] = g_shift1[p]; }

    // prefetch slice 0: flat f over 3 bufs x 352 float4 = 1056
    float4 pf[5];
#pragma unroll
    for (int k = 0; k < 5; k++){
        int f = tid + k*256;
        if (f < 1056){
            int buf = f / 352, p = f % 352;
            const float* hb = (buf == 0) ? g_hbuf0 : ((buf == 1) ? g_hbuf1 : g_hbuf2);
            pf[k] = __ldg((const float4*)(hb + (size_t)(blockIdx.x*SPB)*SLICE) + p);
        }
    }

    // FIX (R9 bug): order ssc/ssh writes before their first cross-thread read
    // in the staging phase below. The loop-top sync that used to provide this
    // was removed with double-buffering.
    __syncthreads();

    for (int s = 0; s < SPB; s++){
        int bt = blockIdx.x*SPB + s;
        int cur = s & 1;

        // stage BN(ReLU(prefetched)) into scat[cur]
#pragma unroll
        for (int k = 0; k < 5; k++){
            int f = tid + k*256;
            if (f < 1056){
                int buf = f / 352, p = f % 352;
                int i = p >> 4, c = (p & 15)*4;
                int fc = buf*64 + c;
                uint32* dst = &scat[cur][i*196 + fc];
                dst[0] = tf32(fmaxf(pf[k].x*ssc[fc  ] + ssh[fc  ], 0.f));
                dst[1] = tf32(fmaxf(pf[k].y*ssc[fc+1] + ssh[fc+1], 0.f));
                dst[2] = tf32(fmaxf(pf[k].z*ssc[fc+2] + ssh[fc+2], 0.f));
                dst[3] = tf32(fmaxf(pf[k].w*ssc[fc+3] + ssh[fc+3], 0.f));
            }
        }
        // issue prefetch for next slice (flies under the mma phase)
        if (s + 1 < SPB){
#pragma unroll
            for (int k = 0; k < 5; k++){
                int f = tid + k*256;
                if (f < 1056){
                    int buf = f / 352, p = f % 352;
                    const float* hb = (buf == 0) ? g_hbuf0 : ((buf == 1) ? g_hbuf1 : g_hbuf2);
                    pf[k] = __ldg((const float4*)(hb + (size_t)(bt + 1)*SLICE) + p);
                }
            }
        }
        __syncthreads();

        const uint32* sc = scat[cur];
        float acc0[4] = {0,0,0,0}, acc1[4] = {0,0,0,0};
#pragma unroll
        for (int k8 = 0; k8 < 24; k8++){
            int c0 = k8*8 + tig, c1 = c0 + 4;
            uint32 a0[4], a1[4];
            a0[0] = sc[ g      *196 + c0];
            a0[1] = sc[(g + 8) *196 + c0];
            a0[2] = sc[ g      *196 + c1];
            a0[3] = sc[(g + 8) *196 + c1];
            a1[0] = r2ok ? sc[(g + 16)*196 + c0] : 0u;
            a1[1] = 0u;
            a1[2] = r2ok ? sc[(g + 16)*196 + c1] : 0u;
            a1[3] = 0u;
            mma_tf32(acc0, a0, bc[k8]);
            mma_tf32(acc1, a1, bc[k8]);
        }

        float su0 = 0.f, su1 = 0.f, sq0 = 0.f, sq1 = 0.f;
        int rr[3] = { g, g + 8, g + 16 };
        float va[3] = { acc0[0], acc0[2], acc1[0] };
        float vb[3] = { acc0[1], acc0[3], acc1[1] };
        size_t obase = (size_t)bt*SLICE;
#pragma unroll
        for (int q = 0; q < 3; q++){
            if (q == 2 && !r2ok) break;
            int r = rr[q];
            float v0 = va[q], v1 = vb[q];
            *(float2*)&g_pre2[obase + r*64 + o0] = make_float2(v0, v1);
            su0 += v0; su1 += v1; sq0 += v0*v0; sq1 += v1*v1;
        }
        su0 = redg(su0); su1 = redg(su1); sq0 = redg(sq0); sq1 = redg(sq1);
        if (lane < 4){
            g_part2[(size_t)(o0     )*NBT + bt] = su0;
            g_part2[(size_t)(o0 + 1 )*NBT + bt] = su1;
            g_part2[(size_t)(64 + o0    )*NBT + bt] = sq0;
            g_part2[(size_t)(64 + o0 + 1)*NBT + bt] = sq1;
        }
        // no trailing sync needed: next iteration writes the OTHER buffer,
        // and its __syncthreads orders those writes vs this iteration's reads.
    }
}

// ---------------- final BN+ReLU elementwise ----------------
__global__ void k_out(float* __restrict__ out)
{
    size_t idx = (size_t)blockIdx.x*256 + threadIdx.x;
    if (idx < TOT/4){
        float4 v = reinterpret_cast<const float4*>(g_pre2)[idx];
        int ob = (int)((idx*4) & 63);
        v.x = fmaxf(v.x*g_scale2[ob  ] + g_shift2[ob  ], 0.f);
        v.y = fmaxf(v.y*g_scale2[ob+1] + g_shift2[ob+1], 0.f);
        v.z = fmaxf(v.z*g_scale2[ob+2] + g_shift2[ob+2], 0.f);
        v.w = fmaxf(v.w*g_scale2[ob+3] + g_shift2[ob+3], 0.f);
        reinterpret_cast<float4*>(out)[idx] = v;
    }
}

// ---------------- launch ----------------
#define KMAIN_SMEM_BYTES (21112*4)

extern "C" void kernel_launch(void* const* d_in, const int* in_sizes, int n_in,
                              void* d_out, int out_size)
{
    const float* x        = (const float*)d_in[0];
    const float* W_sym    = (const float*)d_in[1];
    const float* e_sym    = (const float*)d_in[2];
    const float* W_con    = (const float*)d_in[3];
    const float* e_con    = (const float*)d_in[4];
    const float* W_dis    = (const float*)d_in[5];
    const float* att      = (const float*)d_in[6];
    const float* b_dis    = (const float*)d_in[7];
    const float* cat_w    = (const float*)d_in[8];
    const float* gammas   = (const float*)d_in[9];
    const float* betas    = (const float*)d_in[10];
    const int*   rows_sym = (const int*)d_in[11];
    const int*   cols_sym = (const int*)d_in[12];
    const int*   rows_con = (const int*)d_in[13];
    const int*   cols_con = (const int*)d_in[14];
    int nnz_sym = in_sizes[11];
    int nnz_con = in_sizes[13];

    static int configured = 0;
    if (!configured){
        cudaFuncSetAttribute(k_main, cudaFuncAttributeMaxDynamicSharedMemorySize, KMAIN_SMEM_BYTES);
        configured = 1;
    }

    k_prep<<<3, 256>>>(e_sym, rows_sym, cols_sym, nnz_sym,
                       e_con, rows_con, cols_con, nnz_con,
                       W_sym, W_con, W_dis);
    k_main<<<GRID1, 256, KMAIN_SMEM_BYTES>>>(x, att, b_dis);
    k_finalize<<<192, 256>>>(0, gammas, betas);
    k_cat<<<GRID1, 256>>>(cat_w);
    k_finalize<<<64, 256>>>(1, gammas, betas);
    k_out<<<(TOT/4 + 255)/256, 256>>>((float*)d_out);
    (void)n_in; (void)out_size;
}

// round 11
// speedup vs baseline: 1.1757x; 1.0660x over previous
#include <cuda_runtime.h>
#include <cstdint>

typedef unsigned int uint32;

#define NBT   3200          // B*T
#define NND   22
#define NCH   64
#define SLICE (NND*NCH)     // 1408
#define TOT   (NBT*SLICE)
#define MAXNZ 484
#define SPB   4             // slices per block
#define GRID1 (NBT/SPB)     // 800
#define OFFCAP0 32
#define OFFCAP1 96
#define ROWCAP0 3           // max off-diag per row, branch sym
#define ROWCAP1 6           // max off-diag per row, branch con
#define XP    72            // pitch of permuted tf32 buffers in k_main (72 mod 32 = 8)
// permuted column position within an 8-col group: order [0,4,1,5,2,6,3,7]
#define POSC(c) (((c) & ~7) + 2*((c) & 3) + (((c) >> 2) & 1))

// ---------------- device scratch ----------------
__device__ float g_hbuf0[TOT];
__device__ float g_hbuf1[TOT];
__device__ float g_hbuf2[TOT];
__device__ float g_pre2[TOT];
__device__ float g_part1[6*64*NBT];
__device__ float g_part2[2*64*NBT];
__device__ float g_scale1[192], g_shift1[192];
__device__ float g_scale2[64],  g_shift2[64];
__device__ float g_Wt[5*4096];          // [g][o][c]
__device__ float g_diag[2][NND*NCH];
__device__ float g_offv[2][MAXNZ*NCH];
__device__ int   g_offcol[2][MAXNZ];
__device__ int   g_rowptr[2][NND+1];

// ---------------- helpers ----------------
__device__ __forceinline__ uint32 tf32(float f){
    uint32 r; asm("cvt.rna.tf32.f32 %0, %1;" : "=r"(r) : "f"(f)); return r;
}
__device__ __forceinline__ void mma_tf32(float c[4], const uint32 a[4], const uint32 b[2]){
    asm volatile("mma.sync.aligned.m16n8k8.row.col.f32.tf32.tf32.f32 "
                 "{%0,%1,%2,%3}, {%4,%5,%6,%7}, {%8,%9}, {%0,%1,%2,%3};"
                 : "+f"(c[0]), "+f"(c[1]), "+f"(c[2]), "+f"(c[3])
                 : "r"(a[0]), "r"(a[1]), "r"(a[2]), "r"(a[3]),
                   "r"(b[0]), "r"(b[1]));
}
__device__ __forceinline__ float redg(float v){
    v += __shfl_down_sync(0xffffffffu, v, 16);
    v += __shfl_down_sync(0xffffffffu, v, 8);
    v += __shfl_down_sync(0xffffffffu, v, 4);
    return v;
}

// ---------------- prep: PARALLEL softmax adjacency construction ----------------
// rows come from np.nonzero (C-order) -> non-decreasing. Summation order per
// (row, channel) is ascending k, identical to the proven serial version.
__global__ void k_prep(const float* __restrict__ e_sym, const int* __restrict__ rows_sym,
                       const int* __restrict__ cols_sym, int nnz_sym,
                       const float* __restrict__ e_con, const int* __restrict__ rows_con,
                       const int* __restrict__ cols_con, int nnz_con,
                       const float* __restrict__ W_sym, const float* __restrict__ W_con,
                       const float* __restrict__ W_dis)
{
    int blk = blockIdx.x, tid = threadIdx.x;
    if (blk == 2){
        for (int p = tid; p < 5*4096; p += 256){
            int g = p >> 12, rem = p & 4095, c = rem >> 6, o = rem & 63;
            float v;
            if (g < 2)      v = W_sym[g*4096 + c*64 + o];
            else if (g < 4) v = W_con[(g-2)*4096 + c*64 + o];
            else            v = W_dis[c*64 + o];
            g_Wt[g*4096 + o*64 + c] = v;
        }
        return;
    }
    int br = blk;
    const float* e  = br ? e_con   : e_sym;
    const int* rows = br ? rows_con : rows_sym;
    const int* cols = br ? cols_con : cols_sym;
    int nnz         = br ? nnz_con : nnz_sym;

    __shared__ int   srows[512], scols[512], sscan[512];
    __shared__ int   srs[NND+1];
    __shared__ float sden[NND*NCH];

    for (int p = tid; p < 512; p += 256){
        int r = (p < nnz) ? rows[p] : 0x7fffffff;
        int c = (p < nnz) ? cols[p] : 0x7fffffff;
        srows[p] = r; scols[p] = c;
        sscan[p] = (p < nnz && r != c) ? 1 : 0;
    }
    for (int p = tid; p < NND*NCH; p += 256) g_diag[br][p] = 0.f;
    __syncthreads();

    // inclusive prefix of off-diag flags: single warp, 16 chunks of 32
    if (tid < 32){
        int carry = 0;
        for (int base = 0; base < 512; base += 32){
            int v = sscan[base + tid];
#pragma unroll
            for (int d = 1; d < 32; d <<= 1){
                int t = __shfl_up_sync(0xffffffffu, v, d);
                if (tid >= d) v += t;
            }
            sscan[base + tid] = v + carry;
            carry += __shfl_sync(0xffffffffu, v, 31);
        }
    }
    __syncthreads();

    // scatter off-diag column indices (m = sscan[k]-1, identical to serial order)
    for (int p = tid; p < nnz; p += 256)
        if (srows[p] != scols[p]) g_offcol[br][sscan[p] - 1] = scols[p];

    // rowptr (off-diag counts) + full row starts (order-independent counting)
    for (int p = tid; p <= NND; p += 256){
        int cntoff = 0, cntall = 0;
        for (int k = 0; k < nnz; k++){
            int ro = srows[k];
            cntall += (ro < p);
            cntoff += (ro < p && ro != scols[k]);
        }
        g_rowptr[br][p] = cntoff;
        srs[p] = cntall;
    }
    __syncthreads();

    // softmax denominators: scan only this row's k-range (rows sorted)
    for (int p = tid; p < NND*NCH; p += 256){
        int i = p >> 6, o = p & 63;
        float s = 0.f;
        int kb = srs[i], ke = srs[i+1];
        for (int k = kb; k < ke; k++) s += expf(e[o*nnz + k]);
        sden[p] = s;
    }
    __syncthreads();

    for (int p = tid; p < 64*nnz; p += 256){
        int k = p >> 6, o = p & 63;
        int r = srows[k];
        float v = expf(e[o*nnz + k]) / sden[r*64 + o];
        if (r != scols[k]) g_offv[br][(sscan[k] - 1)*64 + o] = v;
        else               g_diag[br][r*64 + o] = v;
    }
}

// z gemm K=64: A from permuted tf32 smem, B (Wdis) from smem tf32 (pitch 68)
__device__ __forceinline__ void mma8s64(const uint32* __restrict__ sbuf,
                                        const uint32* __restrict__ swd,
                                        int n0, int g, int tig, int r2ok,
                                        float acc0[4], float acc1[4]){
#pragma unroll
    for (int k8 = 0; k8 < 8; k8++){
        uint32 b[2];
        b[0] = swd[(n0 + g)*68 + k8*8 + tig];
        b[1] = swd[(n0 + g)*68 + k8*8 + tig + 4];
        const uint32* p0 = sbuf + g*XP + k8*8 + 2*tig;
        uint2 va = *(const uint2*)p0;
        uint2 vb = *(const uint2*)(p0 + 8*XP);
        uint2 vc = r2ok ? *(const uint2*)(p0 + 16*XP) : make_uint2(0u, 0u);
        uint32 a0[4] = { va.x, vb.x, va.y, vb.y };
        uint32 a1[4] = { vc.x, 0u,   vc.y, 0u   };
        mma_tf32(acc0, a0, b);
        mma_tf32(acc1, a1, b);
    }
}

// ---------------- main fused kernel ----------------
__global__ __launch_bounds__(256, 2) void k_main(const float* __restrict__ x,
                                                 const float* __restrict__ att,
                                                 const float* __restrict__ b_dis)
{
    extern __shared__ __align__(16) float smem_[];
    float*  sx    = smem_;                         // 1496 (pitch 68, fp32)
    uint32* sxt   = (uint32*)(sx + 1496);          // 1584 (pitch 72, permuted tf32)
    uint32* sdist = sxt + 1584;                    // 1584
    float*  sh1s  = (float*)(sdist + 1584);        // 1408
    float*  sh1c  = sh1s + 1408;                   // 1408
    uint32* sdwT  = (uint32*)(sh1c + 1408);        // 1792 (64*28)
    uint32* sattT = sdwT + 1792;                   // 528 (22*24)
    float*  sdiag = (float*)(sattT + 528);         // 2816
    float*  soffv = sdiag + 2816;                  // 8192
    int*    ssrp  = (int*)(soffv + 8192);          // 48
    int*    ssocol= ssrp + 48;                     // 128
    float*  sS1   = (float*)(ssocol + 128);        // 64
    float*  sS2   = sS1 + 64;                      // 64
    uint32* swd   = (uint32*)(sS2 + 64);           // 4352 (Wdis tf32, pitch 68)

    int tid = threadIdx.x;
    int lane = tid & 31, w = tid >> 5;
    int g = lane >> 2, tig = lane & 3;
    int n0 = w*8;
    int o0 = n0 + 2*tig;
    int r2ok = (g + 16) < NND;

    // persistent B fragments: W0s, W1s, W0c, W1c
    uint32 bw0s[8][2], bw1s[8][2], bw0c[8][2], bw1c[8][2];
#pragma unroll
    for (int k8 = 0; k8 < 8; k8++){
        const float* w0 = g_Wt + 0*4096 + (n0 + g)*64 + k8*8 + tig;
        const float* w1 = g_Wt + 1*4096 + (n0 + g)*64 + k8*8 + tig;
        const float* w2 = g_Wt + 2*4096 + (n0 + g)*64 + k8*8 + tig;
        const float* w3 = g_Wt + 3*4096 + (n0 + g)*64 + k8*8 + tig;
        bw0s[k8][0] = tf32(__ldg(w0)); bw0s[k8][1] = tf32(__ldg(w0 + 4));
        bw1s[k8][0] = tf32(__ldg(w1)); bw1s[k8][1] = tf32(__ldg(w1 + 4));
        bw0c[k8][0] = tf32(__ldg(w2)); bw0c[k8][1] = tf32(__ldg(w2 + 4));
        bw1c[k8][0] = tf32(__ldg(w3)); bw1c[k8][1] = tf32(__ldg(w3 + 4));
    }

    // ---- block-constant staging ----
    for (int p = tid; p < NND*24; p += 256){
        int i = p / 24, c = p % 24;
        sattT[p] = (c < NND) ? tf32(__ldg(&att[i*NND + c])) : 0u;
    }
    for (int p = tid; p < 64*28; p += 256) sdwT[p] = 0u;
    for (int p = tid; p < 4096; p += 256) swd[(p >> 6)*68 + (p & 63)] = tf32(g_Wt[4*4096 + p]);
    for (int p = tid; p < 2*(NND+1); p += 256) ssrp[(p/(NND+1))*23 + (p%(NND+1))] = g_rowptr[p/(NND+1)][p%(NND+1)];
    for (int p = tid; p < 2*NND*64; p += 256) sdiag[p] = g_diag[p/(NND*64)][p%(NND*64)];
    {
        int cnt0 = g_rowptr[0][NND]; if (cnt0 > OFFCAP0) cnt0 = OFFCAP0;
        int cnt1 = g_rowptr[1][NND]; if (cnt1 > OFFCAP1) cnt1 = OFFCAP1;
        for (int p = tid; p < cnt0*64; p += 256) soffv[p] = g_offv[0][p];
        for (int p = tid; p < cnt1*64; p += 256) soffv[OFFCAP0*64 + p] = g_offv[1][p];
        for (int p = tid; p < cnt0; p += 256) ssocol[p] = g_offcol[0][p];
        for (int p = tid; p < cnt1; p += 256) ssocol[OFFCAP0 + p] = g_offcol[1][p];
    }

    float2 bd = *(const float2*)&b_dis[o0];

    // prefetch slice 0
    float4 xr0, xr1;
    {
        const float4* xg = (const float4*)(x + (size_t)(blockIdx.x*SPB)*SLICE);
        xr0 = __ldg(xg + tid);
        xr1 = (tid + 256 < SLICE/4) ? __ldg(xg + tid + 256) : make_float4(0,0,0,0);
    }

    for (int s = 0; s < SPB; s++){
        int bt = blockIdx.x*SPB + s;
        __syncthreads();

        // write prefetched x: fp32 (pitch 68) + permuted tf32 (pitch 72)
        {
            int i = tid >> 4, c = (tid & 15)*4;
            *(float4*)&sx[i*68 + c] = xr0;
            int base = i*XP + (c & ~7) + ((c >> 2) & 1);
            sxt[base    ] = tf32(xr0.x);
            sxt[base + 2] = tf32(xr0.y);
            sxt[base + 4] = tf32(xr0.z);
            sxt[base + 6] = tf32(xr0.w);
            if (tid + 256 < SLICE/4){
                int p = tid + 256; i = p >> 4; c = (p & 15)*4;
                *(float4*)&sx[i*68 + c] = xr1;
                base = i*XP + (c & ~7) + ((c >> 2) & 1);
                sxt[base    ] = tf32(xr1.x);
                sxt[base + 2] = tf32(xr1.y);
                sxt[base + 4] = tf32(xr1.z);
                sxt[base + 6] = tf32(xr1.w);
            }
        }
        if (s + 1 < SPB){
            const float4* xg = (const float4*)(x + (size_t)(bt + 1)*SLICE);
            xr0 = __ldg(xg + tid);
            if (tid + 256 < SLICE/4) xr1 = __ldg(xg + tid + 256);
        }
        __syncthreads();

        if (tid < 64){
            float s1 = 0.f, s2 = 0.f;
#pragma unroll
            for (int i = 0; i < NND; i++){
                float v = sx[i*68 + tid];
                s1 += v; s2 += v*v;
            }
            sS1[tid] = s1; sS2[tid] = s2;
        }
        __syncthreads();

        for (int p = tid; p < SLICE; p += 256){
            int i = p >> 6, c = p & 63;
            float v = sx[i*68 + c];
            float d = sS2[c] - 2.f*v*sS1[c] + (float)NND*v*v;
            sdist[i*XP + POSC(c)] = tf32(sqrtf(fmaxf(d, 0.f)) + 1e-8f);
        }
        __syncthreads();

        size_t obase = (size_t)bt*SLICE;

        // ===== fused 4-weight x-gemm: ONE pass over A, 8 mma per kstep =====
        float hs0[4] = {0,0,0,0}, hs1[4] = {0,0,0,0};   // h0s
        float es0[4] = {0,0,0,0}, es1[4] = {0,0,0,0};   // h1s
        float hc0[4] = {0,0,0,0}, hc1[4] = {0,0,0,0};   // h0c
        float ec0[4] = {0,0,0,0}, ec1[4] = {0,0,0,0};   // h1c
#pragma unroll
        for (int k8 = 0; k8 < 8; k8++){
            const uint32* p0 = sxt + g*XP + k8*8 + 2*tig;
            uint2 va = *(const uint2*)p0;
            uint2 vb = *(const uint2*)(p0 + 8*XP);
            uint2 vc = r2ok ? *(const uint2*)(p0 + 16*XP) : make_uint2(0u, 0u);
            uint32 A0[4] = { va.x, vb.x, va.y, vb.y };
            uint32 A1[4] = { vc.x, 0u,   vc.y, 0u   };
            mma_tf32(hs0, A0, bw0s[k8]);  mma_tf32(hs1, A1, bw0s[k8]);
            mma_tf32(es0, A0, bw1s[k8]);  mma_tf32(es1, A1, bw1s[k8]);
            mma_tf32(hc0, A0, bw0c[k8]);  mma_tf32(hc1, A1, bw0c[k8]);
            mma_tf32(ec0, A0, bw1c[k8]);  mma_tf32(ec1, A1, bw1c[k8]);
        }
        __syncwarp();
        // store both h1 results to their smem buffers (own column stripe)
        sh1s[ g      *64 + o0    ] = es0[0];
        sh1s[ g      *64 + o0 + 1] = es0[1];
        sh1s[(g + 8) *64 + o0    ] = es0[2];
        sh1s[(g + 8) *64 + o0 + 1] = es0[3];
        sh1c[ g      *64 + o0    ] = ec0[0];
        sh1c[ g      *64 + o0 + 1] = ec0[1];
        sh1c[(g + 8) *64 + o0    ] = ec0[2];
        sh1c[(g + 8) *64 + o0 + 1] = ec0[3];
        if (r2ok){
            sh1s[(g + 16)*64 + o0    ] = es1[0];
            sh1s[(g + 16)*64 + o0 + 1] = es1[1];
            sh1c[(g + 16)*64 + o0    ] = ec1[0];
            sh1c[(g + 16)*64 + o0 + 1] = ec1[1];
        }
        __syncwarp();

        // ===== mix epilogues for branches s and c (fixed-trip unrolled sparse loops) =====
#pragma unroll
        for (int br = 0; br < 2; br++){
            const float* sh1 = br ? sh1c : sh1s;
            const int ob = br ? OFFCAP0 : 0;
            const int CAP = br ? ROWCAP1 : ROWCAP0;
            float su0 = 0.f, su1 = 0.f, sq0 = 0.f, sq1 = 0.f;
            int rr[3] = { g, g + 8, g + 16 };
            float va[3], vb[3];
            if (br == 0){ va[0]=hs0[0]; va[1]=hs0[2]; va[2]=hs1[0]; vb[0]=hs0[1]; vb[1]=hs0[3]; vb[2]=hs1[1]; }
            else        { va[0]=hc0[0]; va[1]=hc0[2]; va[2]=hc1[0]; vb[0]=hc0[1]; vb[1]=hc0[3]; vb[2]=hc1[1]; }
#pragma unroll
            for (int q = 0; q < 3; q++){
                if (q == 2 && !r2ok) break;
                int r = rr[q];
                float2 dg = *(const float2*)&sdiag[br*(NND*64) + r*64 + o0];
                float v0 = va[q]*dg.x, v1 = vb[q]*dg.y;
                int mb = ssrp[br*23 + r], me = ssrp[br*23 + r + 1];
#pragma unroll
                for (int m = 0; m < CAP; m++){
                    int idx = mb + m;
                    if (idx < me){
                        int cm = ssocol[ob + idx];
                        float2 ov = *(const float2*)&soffv[(ob + idx)*64 + o0];
                        v0 += ov.x * sh1[cm*64 + o0];
                        v1 += ov.y * sh1[cm*64 + o0 + 1];
                    }
                }
                float2 st = make_float2(v0, v1);
                if (br == 0) *(float2*)&g_hbuf0[obase + r*64 + o0] = st;
                else         *(float2*)&g_hbuf1[obase + r*64 + o0] = st;
                su0 += v0; su1 += v1; sq0 += v0*v0; sq1 += v1*v1;
            }
            su0 = redg(su0); su1 = redg(su1); sq0 = redg(sq0); sq1 = redg(sq1);
            if (lane < 4){
                g_part1[(size_t)((2*br  )*64 + o0    )*NBT + bt] = su0;
                g_part1[(size_t)((2*br  )*64 + o0 + 1)*NBT + bt] = su1;
                g_part1[(size_t)((2*br+1)*64 + o0    )*NBT + bt] = sq0;
                g_part1[(size_t)((2*br+1)*64 + o0 + 1)*NBT + bt] = sq1;
            }
        }

        // ===== z branch =====
        {
            float acc0[4] = {0,0,0,0}, acc1[4] = {0,0,0,0};
            mma8s64(sdist, swd, n0, g, tig, r2ok, acc0, acc1);
            __syncwarp();
            sdwT[ o0     *28 + g     ] = tf32(acc0[0]);
            sdwT[(o0 + 1)*28 + g     ] = tf32(acc0[1]);
            sdwT[ o0     *28 + g + 8 ] = tf32(acc0[2]);
            sdwT[(o0 + 1)*28 + g + 8 ] = tf32(acc0[3]);
            if (r2ok){
                sdwT[ o0     *28 + g + 16] = tf32(acc1[0]);
                sdwT[(o0 + 1)*28 + g + 16] = tf32(acc1[1]);
            }
            __syncwarp();

            float az0[4] = {0,0,0,0}, az1[4] = {0,0,0,0};
#pragma unroll
            for (int k8 = 0; k8 < 3; k8++){
                int c0 = k8*8 + tig, c1 = c0 + 4;
                uint32 a0[4], a1[4], bz[2];
                a0[0] = sattT[ g      *24 + c0];
                a0[1] = sattT[(g + 8) *24 + c0];
                a0[2] = sattT[ g      *24 + c1];
                a0[3] = sattT[(g + 8) *24 + c1];
                a1[0] = r2ok ? sattT[(g + 16)*24 + c0] : 0u;
                a1[1] = 0u;
                a1[2] = r2ok ? sattT[(g + 16)*24 + c1] : 0u;
                a1[3] = 0u;
                bz[0] = sdwT[(n0 + g)*28 + c0];
                bz[1] = sdwT[(n0 + g)*28 + c1];
                mma_tf32(az0, a0, bz);
                mma_tf32(az1, a1, bz);
            }
            float su0 = 0.f, su1 = 0.f, sq0 = 0.f, sq1 = 0.f;
            int rr[3] = { g, g + 8, g + 16 };
            float va[3] = { az0[0], az0[2], az1[0] };
            float vb[3] = { az0[1], az0[3], az1[1] };
#pragma unroll
            for (int q = 0; q < 3; q++){
                if (q == 2 && !r2ok) break;
                int r = rr[q];
                float v0 = va[q] + bd.x, v1 = vb[q] + bd.y;
                *(float2*)&g_hbuf2[obase + r*64 + o0] = make_float2(v0, v1);
                su0 += v0; su1 += v1; sq0 += v0*v0; sq1 += v1*v1;
            }
            su0 = redg(su0); su1 = redg(su1); sq0 = redg(sq0); sq1 = redg(sq1);
            if (lane < 4){
                g_part1[(size_t)(4*64 + o0    )*NBT + bt] = su0;
                g_part1[(size_t)(4*64 + o0 + 1)*NBT + bt] = su1;
                g_part1[(size_t)(5*64 + o0    )*NBT + bt] = sq0;
                g_part1[(size_t)(5*64 + o0 + 1)*NBT + bt] = sq1;
            }
        }
    }
}

// ---------------- BN stats finalize (unchanged) ----------------
__global__ void k_finalize(int which, const float* __restrict__ gammas,
                           const float* __restrict__ betas)
{
    int ch = blockIdx.x, tid = threadIdx.x;
    int b = ch >> 6, o = ch & 63;
    const float* part = which ? g_part2 : g_part1;
    const float* psum = part + (size_t)((2*b  )*64 + o) * NBT;
    const float* psq  = part + (size_t)((2*b+1)*64 + o) * NBT;
    __shared__ float r1[256], r2[256];
    float s = 0.f, q = 0.f;
    for (int t = tid; t < NBT; t += 256){ s += psum[t]; q += psq[t]; }
    r1[tid] = s; r2[tid] = q;
    __syncthreads();
    for (int off = 128; off; off >>= 1){
        if (tid < off){ r1[tid] += r1[tid+off]; r2[tid] += r2[tid+off]; }
        __syncthreads();
    }
    if (tid == 0){
        const float invM = 1.f / 70400.f;
        float mu  = r1[0]*invM;
        float var = r2[0]*invM - mu*mu;
        int grow = which ? 3 : b;
        float g  = gammas[grow*64 + o], be = betas[grow*64 + o];
        float sc = g * rsqrtf(var + 1e-5f);
        if (which){ g_scale2[o]  = sc; g_shift2[o]  = be - mu*sc; }
        else      { g_scale1[ch] = sc; g_shift1[ch] = be - mu*sc; }
    }
}

// ---------------- BN+ReLU + cat matmul (192->64): double-buffered prefetch ----------------
__global__ __launch_bounds__(256) void k_cat(const float* __restrict__ cat_w)
{
    __shared__ __align__(16) uint32 scat[2][NND*196];
    __shared__ float ssc[192], ssh[192];

    int tid = threadIdx.x;
    int lane = tid & 31, w = tid >> 5;
    int g = lane >> 2, tig = lane & 3;
    int n0 = w*8;
    int o0 = n0 + 2*tig;
    int r2ok = (g + 16) < NND;

    uint32 bc[24][2];
#pragma unroll
    for (int k8 = 0; k8 < 24; k8++){
        const float* wp = cat_w + (n0 + g)*192 + k8*8 + tig;
        bc[k8][0] = tf32(__ldg(wp));
        bc[k8][1] = tf32(__ldg(wp + 4));
    }
    for (int p = tid; p < 192; p += 256){ ssc[p] = g_scale1[p]; ssh[p] = g_shift1[p]; }

    // prefetch slice 0: flat f over 3 bufs x 352 float4 = 1056
    float4 pf[5];
#pragma unroll
    for (int k = 0; k < 5; k++){
        int f = tid + k*256;
        if (f < 1056){
            int buf = f / 352, p = f % 352;
            const float* hb = (buf == 0) ? g_hbuf0 : ((buf == 1) ? g_hbuf1 : g_hbuf2);
            pf[k] = __ldg((const float4*)(hb + (size_t)(blockIdx.x*SPB)*SLICE) + p);
        }
    }

    // order ssc/ssh writes before their first cross-thread read below
    __syncthreads();

    for (int s = 0; s < SPB; s++){
        int bt = blockIdx.x*SPB + s;
        int cur = s & 1;

        // stage BN(ReLU(prefetched)) into scat[cur]
#pragma unroll
        for (int k = 0; k < 5; k++){
            int f = tid + k*256;
            if (f < 1056){
                int buf = f / 352, p = f % 352;
                int i = p >> 4, c = (p & 15)*4;
                int fc = buf*64 + c;
                uint32* dst = &scat[cur][i*196 + fc];
                dst[0] = tf32(fmaxf(pf[k].x*ssc[fc  ] + ssh[fc  ], 0.f));
                dst[1] = tf32(fmaxf(pf[k].y*ssc[fc+1] + ssh[fc+1], 0.f));
                dst[2] = tf32(fmaxf(pf[k].z*ssc[fc+2] + ssh[fc+2], 0.f));
                dst[3] = tf32(fmaxf(pf[k].w*ssc[fc+3] + ssh[fc+3], 0.f));
            }
        }
        // issue prefetch for next slice (flies under the mma phase)
        if (s + 1 < SPB){
#pragma unroll
            for (int k = 0; k < 5; k++){
                int f = tid + k*256;
                if (f < 1056){
                    int buf = f / 352, p = f % 352;
                    const float* hb = (buf == 0) ? g_hbuf0 : ((buf == 1) ? g_hbuf1 : g_hbuf2);
                    pf[k] = __ldg((const float4*)(hb + (size_t)(bt + 1)*SLICE) + p);
                }
            }
        }
        __syncthreads();

        const uint32* sc = scat[cur];
        float acc0[4] = {0,0,0,0}, acc1[4] = {0,0,0,0};
#pragma unroll
        for (int k8 = 0; k8 < 24; k8++){
            int c0 = k8*8 + tig, c1 = c0 + 4;
            uint32 a0[4], a1[4];
            a0[0] = sc[ g      *196 + c0];
            a0[1] = sc[(g + 8) *196 + c0];
            a0[2] = sc[ g      *196 + c1];
            a0[3] = sc[(g + 8) *196 + c1];
            a1[0] = r2ok ? sc[(g + 16)*196 + c0] : 0u;
            a1[1] = 0u;
            a1[2] = r2ok ? sc[(g + 16)*196 + c1] : 0u;
            a1[3] = 0u;
            mma_tf32(acc0, a0, bc[k8]);
            mma_tf32(acc1, a1, bc[k8]);
        }

        float su0 = 0.f, su1 = 0.f, sq0 = 0.f, sq1 = 0.f;
        int rr[3] = { g, g + 8, g + 16 };
        float va[3] = { acc0[0], acc0[2], acc1[0] };
        float vb[3] = { acc0[1], acc0[3], acc1[1] };
        size_t obase = (size_t)bt*SLICE;
#pragma unroll
        for (int q = 0; q < 3; q++){
            if (q == 2 && !r2ok) break;
            int r = rr[q];
            float v0 = va[q], v1 = vb[q];
            *(float2*)&g_pre2[obase + r*64 + o0] = make_float2(v0, v1);
            su0 += v0; su1 += v1; sq0 += v0*v0; sq1 += v1*v1;
        }
        su0 = redg(su0); su1 = redg(su1); sq0 = redg(sq0); sq1 = redg(sq1);
        if (lane < 4){
            g_part2[(size_t)(o0     )*NBT + bt] = su0;
            g_part2[(size_t)(o0 + 1 )*NBT + bt] = su1;
            g_part2[(size_t)(64 + o0    )*NBT + bt] = sq0;
            g_part2[(size_t)(64 + o0 + 1)*NBT + bt] = sq1;
        }
    }
}

// ---------------- final BN+ReLU elementwise ----------------
__global__ void k_out(float* __restrict__ out)
{
    size_t idx = (size_t)blockIdx.x*256 + threadIdx.x;
    if (idx < TOT/4){
        float4 v = reinterpret_cast<const float4*>(g_pre2)[idx];
        int ob = (int)((idx*4) & 63);
        v.x = fmaxf(v.x*g_scale2[ob  ] + g_shift2[ob  ], 0.f);
        v.y = fmaxf(v.y*g_scale2[ob+1] + g_shift2[ob+1], 0.f);
        v.z = fmaxf(v.z*g_scale2[ob+2] + g_shift2[ob+2], 0.f);
        v.w = fmaxf(v.w*g_scale2[ob+3] + g_shift2[ob+3], 0.f);
        reinterpret_cast<float4*>(out)[idx] = v;
    }
}

// ---------------- launch ----------------
#define KMAIN_SMEM_BYTES (25464*4)

extern "C" void kernel_launch(void* const* d_in, const int* in_sizes, int n_in,
                              void* d_out, int out_size)
{
    const float* x        = (const float*)d_in[0];
    const float* W_sym    = (const float*)d_in[1];
    const float* e_sym    = (const float*)d_in[2];
    const float* W_con    = (const float*)d_in[3];
    const float* e_con    = (const float*)d_in[4];
    const float* W_dis    = (const float*)d_in[5];
    const float* att      = (const float*)d_in[6];
    const float* b_dis    = (const float*)d_in[7];
    const float* cat_w    = (const float*)d_in[8];
    const float* gammas   = (const float*)d_in[9];
    const float* betas    = (const float*)d_in[10];
    const int*   rows_sym = (const int*)d_in[11];
    const int*   cols_sym = (const int*)d_in[12];
    const int*   rows_con = (const int*)d_in[13];
    const int*   cols_con = (const int*)d_in[14];
    int nnz_sym = in_sizes[11];
    int nnz_con = in_sizes[13];

    static int configured = 0;
    if (!configured){
        cudaFuncSetAttribute(k_main, cudaFuncAttributeMaxDynamicSharedMemorySize, KMAIN_SMEM_BYTES);
        configured = 1;
    }

    k_prep<<<3, 256>>>(e_sym, rows_sym, cols_sym, nnz_sym,
                       e_con, rows_con, cols_con, nnz_con,
                       W_sym, W_con, W_dis);
    k_main<<<GRID1, 256, KMAIN_SMEM_BYTES>>>(x, att, b_dis);
    k_finalize<<<192, 256>>>(0, gammas, betas);
    k_cat<<<GRID1, 256>>>(cat_w);
    k_finalize<<<64, 256>>>(1, gammas, betas);
    k_out<<<(TOT/4 + 255)/256, 256>>>((float*)d_out);
    (void)n_in; (void)out_size;
}

// round 12
// speedup vs baseline: 1.2950x; 1.1015x over previous
#include <cuda_runtime.h>
#include <cuda_fp16.h>
#include <cstdint>

typedef unsigned int uint32;

#define NBT   3200          // B*T
#define NND   22
#define NCH   64
#define SLICE (NND*NCH)     // 1408
#define TOT   (NBT*SLICE)
#define MAXNZ 484
#define SPB   4             // slices per block
#define GRID1 (NBT/SPB)     // 800
#define OFFCAP0 32
#define OFFCAP1 96
#define ROWCAP0 3
#define ROWCAP1 6
#define XP    72
#define POSC(c) (((c) & ~7) + 2*((c) & 3) + (((c) >> 2) & 1))

// ---------------- device scratch ----------------
__device__ __half g_hbuf0h[TOT];
__device__ __half g_hbuf1h[TOT];
__device__ __half g_hbuf2h[TOT];
__device__ __half g_pre2h[TOT];
__device__ float g_part1[6*64*NBT];
__device__ float g_part2[2*64*NBT];
__device__ float g_scale1[192], g_shift1[192];
__device__ float g_scale2[64],  g_shift2[64];
__device__ float g_Wt[5*4096];          // [g][o][c]
__device__ float g_diag[2][NND*NCH];
__device__ float g_offv[2][MAXNZ*NCH];
__device__ int   g_offcol[2][MAXNZ];
__device__ int   g_rowptr[2][NND+1];

// ---------------- helpers ----------------
__device__ __forceinline__ uint32 tf32(float f){
    uint32 r; asm("cvt.rna.tf32.f32 %0, %1;" : "=r"(r) : "f"(f)); return r;
}
__device__ __forceinline__ void mma_tf32(float c[4], const uint32 a[4], const uint32 b[2]){
    asm volatile("mma.sync.aligned.m16n8k8.row.col.f32.tf32.tf32.f32 "
                 "{%0,%1,%2,%3}, {%4,%5,%6,%7}, {%8,%9}, {%0,%1,%2,%3};"
                 : "+f"(c[0]), "+f"(c[1]), "+f"(c[2]), "+f"(c[3])
                 : "r"(a[0]), "r"(a[1]), "r"(a[2]), "r"(a[3]),
                   "r"(b[0]), "r"(b[1]));
}
__device__ __forceinline__ float redg(float v){
    v += __shfl_down_sync(0xffffffffu, v, 16);
    v += __shfl_down_sync(0xffffffffu, v, 8);
    v += __shfl_down_sync(0xffffffffu, v, 4);
    return v;
}

// ---------------- prep: parallel softmax adjacency construction (proven) ----------------
__global__ void k_prep(const float* __restrict__ e_sym, const int* __restrict__ rows_sym,
                       const int* __restrict__ cols_sym, int nnz_sym,
                       const float* __restrict__ e_con, const int* __restrict__ rows_con,
                       const int* __restrict__ cols_con, int nnz_con,
                       const float* __restrict__ W_sym, const float* __restrict__ W_con,
                       const float* __restrict__ W_dis)
{
    int blk = blockIdx.x, tid = threadIdx.x;
    if (blk == 2){
        for (int p = tid; p < 5*4096; p += 256){
            int g = p >> 12, rem = p & 4095, c = rem >> 6, o = rem & 63;
            float v;
            if (g < 2)      v = W_sym[g*4096 + c*64 + o];
            else if (g < 4) v = W_con[(g-2)*4096 + c*64 + o];
            else            v = W_dis[c*64 + o];
            g_Wt[g*4096 + o*64 + c] = v;
        }
        return;
    }
    int br = blk;
    const float* e  = br ? e_con   : e_sym;
    const int* rows = br ? rows_con : rows_sym;
    const int* cols = br ? cols_con : cols_sym;
    int nnz         = br ? nnz_con : nnz_sym;

    __shared__ int   srows[512], scols[512], sscan[512];
    __shared__ int   srs[NND+1];
    __shared__ float sden[NND*NCH];

    for (int p = tid; p < 512; p += 256){
        int r = (p < nnz) ? rows[p] : 0x7fffffff;
        int c = (p < nnz) ? cols[p] : 0x7fffffff;
        srows[p] = r; scols[p] = c;
        sscan[p] = (p < nnz && r != c) ? 1 : 0;
    }
    for (int p = tid; p < NND*NCH; p += 256) g_diag[br][p] = 0.f;
    __syncthreads();

    if (tid < 32){
        int carry = 0;
        for (int base = 0; base < 512; base += 32){
            int v = sscan[base + tid];
#pragma unroll
            for (int d = 1; d < 32; d <<= 1){
                int t = __shfl_up_sync(0xffffffffu, v, d);
                if (tid >= d) v += t;
            }
            sscan[base + tid] = v + carry;
            carry += __shfl_sync(0xffffffffu, v, 31);
        }
    }
    __syncthreads();

    for (int p = tid; p < nnz; p += 256)
        if (srows[p] != scols[p]) g_offcol[br][sscan[p] - 1] = scols[p];

    for (int p = tid; p <= NND; p += 256){
        int cntoff = 0, cntall = 0;
        for (int k = 0; k < nnz; k++){
            int ro = srows[k];
            cntall += (ro < p);
            cntoff += (ro < p && ro != scols[k]);
        }
        g_rowptr[br][p] = cntoff;
        srs[p] = cntall;
    }
    __syncthreads();

    for (int p = tid; p < NND*NCH; p += 256){
        int i = p >> 6, o = p & 63;
        float s = 0.f;
        int kb = srs[i], ke = srs[i+1];
        for (int k = kb; k < ke; k++) s += expf(e[o*nnz + k]);
        sden[p] = s;
    }
    __syncthreads();

    for (int p = tid; p < 64*nnz; p += 256){
        int k = p >> 6, o = p & 63;
        int r = srows[k];
        float v = expf(e[o*nnz + k]) / sden[r*64 + o];
        if (r != scols[k]) g_offv[br][(sscan[k] - 1)*64 + o] = v;
        else               g_diag[br][r*64 + o] = v;
    }
}

// z gemm K=64: A from permuted tf32 smem, B (Wdis) from smem tf32 (pitch 68)
__device__ __forceinline__ void mma8s64(const uint32* __restrict__ sbuf,
                                        const uint32* __restrict__ swd,
                                        int n0, int g, int tig, int r2ok,
                                        float acc0[4], float acc1[4]){
#pragma unroll
    for (int k8 = 0; k8 < 8; k8++){
        uint32 b[2];
        b[0] = swd[(n0 + g)*68 + k8*8 + tig];
        b[1] = swd[(n0 + g)*68 + k8*8 + tig + 4];
        const uint32* p0 = sbuf + g*XP + k8*8 + 2*tig;
        uint2 va = *(const uint2*)p0;
        uint2 vb = *(const uint2*)(p0 + 8*XP);
        uint2 vc = r2ok ? *(const uint2*)(p0 + 16*XP) : make_uint2(0u, 0u);
        uint32 a0[4] = { va.x, vb.x, va.y, vb.y };
        uint32 a1[4] = { vc.x, 0u,   vc.y, 0u   };
        mma_tf32(acc0, a0, b);
        mma_tf32(acc1, a1, b);
    }
}

// ---------------- main fused kernel (R11 structure, half2 epilogue stores) ----------------
__global__ __launch_bounds__(256, 2) void k_main(const float* __restrict__ x,
                                                 const float* __restrict__ att,
                                                 const float* __restrict__ b_dis)
{
    extern __shared__ __align__(16) float smem_[];
    float*  sx    = smem_;                         // 1496
    uint32* sxt   = (uint32*)(sx + 1496);          // 1584
    uint32* sdist = sxt + 1584;                    // 1584
    float*  sh1s  = (float*)(sdist + 1584);        // 1408
    float*  sh1c  = sh1s + 1408;                   // 1408
    uint32* sdwT  = (uint32*)(sh1c + 1408);        // 1792
    uint32* sattT = sdwT + 1792;                   // 528
    float*  sdiag = (float*)(sattT + 528);         // 2816
    float*  soffv = sdiag + 2816;                  // 8192
    int*    ssrp  = (int*)(soffv + 8192);          // 48
    int*    ssocol= ssrp + 48;                     // 128
    float*  sS1   = (float*)(ssocol + 128);        // 64
    float*  sS2   = sS1 + 64;                      // 64
    uint32* swd   = (uint32*)(sS2 + 64);           // 4352

    int tid = threadIdx.x;
    int lane = tid & 31, w = tid >> 5;
    int g = lane >> 2, tig = lane & 3;
    int n0 = w*8;
    int o0 = n0 + 2*tig;
    int r2ok = (g + 16) < NND;

    uint32 bw0s[8][2], bw1s[8][2], bw0c[8][2], bw1c[8][2];
#pragma unroll
    for (int k8 = 0; k8 < 8; k8++){
        const float* w0 = g_Wt + 0*4096 + (n0 + g)*64 + k8*8 + tig;
        const float* w1 = g_Wt + 1*4096 + (n0 + g)*64 + k8*8 + tig;
        const float* w2 = g_Wt + 2*4096 + (n0 + g)*64 + k8*8 + tig;
        const float* w3 = g_Wt + 3*4096 + (n0 + g)*64 + k8*8 + tig;
        bw0s[k8][0] = tf32(__ldg(w0)); bw0s[k8][1] = tf32(__ldg(w0 + 4));
        bw1s[k8][0] = tf32(__ldg(w1)); bw1s[k8][1] = tf32(__ldg(w1 + 4));
        bw0c[k8][0] = tf32(__ldg(w2)); bw0c[k8][1] = tf32(__ldg(w2 + 4));
        bw1c[k8][0] = tf32(__ldg(w3)); bw1c[k8][1] = tf32(__ldg(w3 + 4));
    }

    for (int p = tid; p < NND*24; p += 256){
        int i = p / 24, c = p % 24;
        sattT[p] = (c < NND) ? tf32(__ldg(&att[i*NND + c])) : 0u;
    }
    for (int p = tid; p < 64*28; p += 256) sdwT[p] = 0u;
    for (int p = tid; p < 4096; p += 256) swd[(p >> 6)*68 + (p & 63)] = tf32(g_Wt[4*4096 + p]);
    for (int p = tid; p < 2*(NND+1); p += 256) ssrp[(p/(NND+1))*23 + (p%(NND+1))] = g_rowptr[p/(NND+1)][p%(NND+1)];
    for (int p = tid; p < 2*NND*64; p += 256) sdiag[p] = g_diag[p/(NND*64)][p%(NND*64)];
    {
        int cnt0 = g_rowptr[0][NND]; if (cnt0 > OFFCAP0) cnt0 = OFFCAP0;
        int cnt1 = g_rowptr[1][NND]; if (cnt1 > OFFCAP1) cnt1 = OFFCAP1;
        for (int p = tid; p < cnt0*64; p += 256) soffv[p] = g_offv[0][p];
        for (int p = tid; p < cnt1*64; p += 256) soffv[OFFCAP0*64 + p] = g_offv[1][p];
        for (int p = tid; p < cnt0; p += 256) ssocol[p] = g_offcol[0][p];
        for (int p = tid; p < cnt1; p += 256) ssocol[OFFCAP0 + p] = g_offcol[1][p];
    }

    float2 bd = *(const float2*)&b_dis[o0];

    float4 xr0, xr1;
    {
        const float4* xg = (const float4*)(x + (size_t)(blockIdx.x*SPB)*SLICE);
        xr0 = __ldg(xg + tid);
        xr1 = (tid + 256 < SLICE/4) ? __ldg(xg + tid + 256) : make_float4(0,0,0,0);
    }

    for (int s = 0; s < SPB; s++){
        int bt = blockIdx.x*SPB + s;
        __syncthreads();

        {
            int i = tid >> 4, c = (tid & 15)*4;
            *(float4*)&sx[i*68 + c] = xr0;
            int base = i*XP + (c & ~7) + ((c >> 2) & 1);
            sxt[base    ] = tf32(xr0.x);
            sxt[base + 2] = tf32(xr0.y);
            sxt[base + 4] = tf32(xr0.z);
            sxt[base + 6] = tf32(xr0.w);
            if (tid + 256 < SLICE/4){
                int p = tid + 256; i = p >> 4; c = (p & 15)*4;
                *(float4*)&sx[i*68 + c] = xr1;
                base = i*XP + (c & ~7) + ((c >> 2) & 1);
                sxt[base    ] = tf32(xr1.x);
                sxt[base + 2] = tf32(xr1.y);
                sxt[base + 4] = tf32(xr1.z);
                sxt[base + 6] = tf32(xr1.w);
            }
        }
        if (s + 1 < SPB){
            const float4* xg = (const float4*)(x + (size_t)(bt + 1)*SLICE);
            xr0 = __ldg(xg + tid);
            if (tid + 256 < SLICE/4) xr1 = __ldg(xg + tid + 256);
        }
        __syncthreads();

        if (tid < 64){
            float s1 = 0.f, s2 = 0.f;
#pragma unroll
            for (int i = 0; i < NND; i++){
                float v = sx[i*68 + tid];
                s1 += v; s2 += v*v;
            }
            sS1[tid] = s1; sS2[tid] = s2;
        }
        __syncthreads();

        for (int p = tid; p < SLICE; p += 256){
            int i = p >> 6, c = p & 63;
            float v = sx[i*68 + c];
            float d = sS2[c] - 2.f*v*sS1[c] + (float)NND*v*v;
            sdist[i*XP + POSC(c)] = tf32(sqrtf(fmaxf(d, 0.f)) + 1e-8f);
        }
        __syncthreads();

        size_t obase = (size_t)bt*SLICE;

        float hs0[4] = {0,0,0,0}, hs1[4] = {0,0,0,0};
        float es0[4] = {0,0,0,0}, es1[4] = {0,0,0,0};
        float hc0[4] = {0,0,0,0}, hc1[4] = {0,0,0,0};
        float ec0[4] = {0,0,0,0}, ec1[4] = {0,0,0,0};
#pragma unroll
        for (int k8 = 0; k8 < 8; k8++){
            const uint32* p0 = sxt + g*XP + k8*8 + 2*tig;
            uint2 va = *(const uint2*)p0;
            uint2 vb = *(const uint2*)(p0 + 8*XP);
            uint2 vc = r2ok ? *(const uint2*)(p0 + 16*XP) : make_uint2(0u, 0u);
            uint32 A0[4] = { va.x, vb.x, va.y, vb.y };
            uint32 A1[4] = { vc.x, 0u,   vc.y, 0u   };
            mma_tf32(hs0, A0, bw0s[k8]);  mma_tf32(hs1, A1, bw0s[k8]);
            mma_tf32(es0, A0, bw1s[k8]);  mma_tf32(es1, A1, bw1s[k8]);
            mma_tf32(hc0, A0, bw0c[k8]);  mma_tf32(hc1, A1, bw0c[k8]);
            mma_tf32(ec0, A0, bw1c[k8]);  mma_tf32(ec1, A1, bw1c[k8]);
        }
        __syncwarp();
        sh1s[ g      *64 + o0    ] = es0[0];
        sh1s[ g      *64 + o0 + 1] = es0[1];
        sh1s[(g + 8) *64 + o0    ] = es0[2];
        sh1s[(g + 8) *64 + o0 + 1] = es0[3];
        sh1c[ g      *64 + o0    ] = ec0[0];
        sh1c[ g      *64 + o0 + 1] = ec0[1];
        sh1c[(g + 8) *64 + o0    ] = ec0[2];
        sh1c[(g + 8) *64 + o0 + 1] = ec0[3];
        if (r2ok){
            sh1s[(g + 16)*64 + o0    ] = es1[0];
            sh1s[(g + 16)*64 + o0 + 1] = es1[1];
            sh1c[(g + 16)*64 + o0    ] = ec1[0];
            sh1c[(g + 16)*64 + o0 + 1] = ec1[1];
        }
        __syncwarp();

#pragma unroll
        for (int br = 0; br < 2; br++){
            const float* sh1 = br ? sh1c : sh1s;
            const int ob = br ? OFFCAP0 : 0;
            const int CAP = br ? ROWCAP1 : ROWCAP0;
            float su0 = 0.f, su1 = 0.f, sq0 = 0.f, sq1 = 0.f;
            int rr[3] = { g, g + 8, g + 16 };
            float va[3], vb[3];
            if (br == 0){ va[0]=hs0[0]; va[1]=hs0[2]; va[2]=hs1[0]; vb[0]=hs0[1]; vb[1]=hs0[3]; vb[2]=hs1[1]; }
            else        { va[0]=hc0[0]; va[1]=hc0[2]; va[2]=hc1[0]; vb[0]=hc0[1]; vb[1]=hc0[3]; vb[2]=hc1[1]; }
#pragma unroll
            for (int q = 0; q < 3; q++){
                if (q == 2 && !r2ok) break;
                int r = rr[q];
                float2 dg = *(const float2*)&sdiag[br*(NND*64) + r*64 + o0];
                float v0 = va[q]*dg.x, v1 = vb[q]*dg.y;
                int mb = ssrp[br*23 + r], me = ssrp[br*23 + r + 1];
#pragma unroll
                for (int m = 0; m < CAP; m++){
                    int idx = mb + m;
                    if (idx < me){
                        int cm = ssocol[ob + idx];
                        float2 ov = *(const float2*)&soffv[(ob + idx)*64 + o0];
                        v0 += ov.x * sh1[cm*64 + o0];
                        v1 += ov.y * sh1[cm*64 + o0 + 1];
                    }
                }
                __half2 sth = __floats2half2_rn(v0, v1);
                if (br == 0) *(__half2*)&g_hbuf0h[obase + r*64 + o0] = sth;
                else         *(__half2*)&g_hbuf1h[obase + r*64 + o0] = sth;
                su0 += v0; su1 += v1; sq0 += v0*v0; sq1 += v1*v1;
            }
            su0 = redg(su0); su1 = redg(su1); sq0 = redg(sq0); sq1 = redg(sq1);
            if (lane < 4){
                g_part1[(size_t)((2*br  )*64 + o0    )*NBT + bt] = su0;
                g_part1[(size_t)((2*br  )*64 + o0 + 1)*NBT + bt] = su1;
                g_part1[(size_t)((2*br+1)*64 + o0    )*NBT + bt] = sq0;
                g_part1[(size_t)((2*br+1)*64 + o0 + 1)*NBT + bt] = sq1;
            }
        }

        {
            float acc0[4] = {0,0,0,0}, acc1[4] = {0,0,0,0};
            mma8s64(sdist, swd, n0, g, tig, r2ok, acc0, acc1);
            __syncwarp();
            sdwT[ o0     *28 + g     ] = tf32(acc0[0]);
            sdwT[(o0 + 1)*28 + g     ] = tf32(acc0[1]);
            sdwT[ o0     *28 + g + 8 ] = tf32(acc0[2]);
            sdwT[(o0 + 1)*28 + g + 8 ] = tf32(acc0[3]);
            if (r2ok){
                sdwT[ o0     *28 + g + 16] = tf32(acc1[0]);
                sdwT[(o0 + 1)*28 + g + 16] = tf32(acc1[1]);
            }
            __syncwarp();

            float az0[4] = {0,0,0,0}, az1[4] = {0,0,0,0};
#pragma unroll
            for (int k8 = 0; k8 < 3; k8++){
                int c0 = k8*8 + tig, c1 = c0 + 4;
                uint32 a0[4], a1[4], bz[2];
                a0[0] = sattT[ g      *24 + c0];
                a0[1] = sattT[(g + 8) *24 + c0];
                a0[2] = sattT[ g      *24 + c1];
                a0[3] = sattT[(g + 8) *24 + c1];
                a1[0] = r2ok ? sattT[(g + 16)*24 + c0] : 0u;
                a1[1] = 0u;
                a1[2] = r2ok ? sattT[(g + 16)*24 + c1] : 0u;
                a1[3] = 0u;
                bz[0] = sdwT[(n0 + g)*28 + c0];
                bz[1] = sdwT[(n0 + g)*28 + c1];
                mma_tf32(az0, a0, bz);
                mma_tf32(az1, a1, bz);
            }
            float su0 = 0.f, su1 = 0.f, sq0 = 0.f, sq1 = 0.f;
            int rr[3] = { g, g + 8, g + 16 };
            float va[3] = { az0[0], az0[2], az1[0] };
            float vb[3] = { az0[1], az0[3], az1[1] };
#pragma unroll
            for (int q = 0; q < 3; q++){
                if (q == 2 && !r2ok) break;
                int r = rr[q];
                float v0 = va[q] + bd.x, v1 = vb[q] + bd.y;
                *(__half2*)&g_hbuf2h[obase + r*64 + o0] = __floats2half2_rn(v0, v1);
                su0 += v0; su1 += v1; sq0 += v0*v0; sq1 += v1*v1;
            }
            su0 = redg(su0); su1 = redg(su1); sq0 = redg(sq0); sq1 = redg(sq1);
            if (lane < 4){
                g_part1[(size_t)(4*64 + o0    )*NBT + bt] = su0;
                g_part1[(size_t)(4*64 + o0 + 1)*NBT + bt] = su1;
                g_part1[(size_t)(5*64 + o0    )*NBT + bt] = sq0;
                g_part1[(size_t)(5*64 + o0 + 1)*NBT + bt] = sq1;
            }
        }
    }
}

// ---------------- BN stats finalize (unchanged) ----------------
__global__ void k_finalize(int which, const float* __restrict__ gammas,
                           const float* __restrict__ betas)
{
    int ch = blockIdx.x, tid = threadIdx.x;
    int b = ch >> 6, o = ch & 63;
    const float* part = which ? g_part2 : g_part1;
    const float* psum = part + (size_t)((2*b  )*64 + o) * NBT;
    const float* psq  = part + (size_t)((2*b+1)*64 + o) * NBT;
    __shared__ float r1[256], r2[256];
    float s = 0.f, q = 0.f;
    for (int t = tid; t < NBT; t += 256){ s += psum[t]; q += psq[t]; }
    r1[tid] = s; r2[tid] = q;
    __syncthreads();
    for (int off = 128; off; off >>= 1){
        if (tid < off){ r1[tid] += r1[tid+off]; r2[tid] += r2[tid+off]; }
        __syncthreads();
    }
    if (tid == 0){
        const float invM = 1.f / 70400.f;
        float mu  = r1[0]*invM;
        float var = r2[0]*invM - mu*mu;
        int grow = which ? 3 : b;
        float g  = gammas[grow*64 + o], be = betas[grow*64 + o];
        float sc = g * rsqrtf(var + 1e-5f);
        if (which){ g_scale2[o]  = sc; g_shift2[o]  = be - mu*sc; }
        else      { g_scale1[ch] = sc; g_shift1[ch] = be - mu*sc; }
    }
}

// ---------------- k_cat: 128 threads / 4 warps, 2 n-tiles per warp, fp16 I/O ----------------
__global__ __launch_bounds__(128) void k_cat(const float* __restrict__ cat_w)
{
    __shared__ __align__(16) uint32 scat[2][NND*196];
    __shared__ float ssc[192], ssh[192];

    int tid = threadIdx.x;
    int lane = tid & 31, w = tid >> 5;        // 4 warps
    int g = lane >> 2, tig = lane & 3;
    int n0 = w*16;                            // 16 output columns per warp
    int oA = n0 + 2*tig;                      // ntile0 column pair
    int oB = oA + 8;                          // ntile1 column pair
    int r2ok = (g + 16) < NND;

    // B fragments: 24 ksteps x (ntile0: 2, ntile1: 2)
    uint32 bc[24][4];
#pragma unroll
    for (int k8 = 0; k8 < 24; k8++){
        const float* wp0 = cat_w + (n0 + g)*192 + k8*8 + tig;
        const float* wp1 = cat_w + (n0 + 8 + g)*192 + k8*8 + tig;
        bc[k8][0] = tf32(__ldg(wp0)); bc[k8][1] = tf32(__ldg(wp0 + 4));
        bc[k8][2] = tf32(__ldg(wp1)); bc[k8][3] = tf32(__ldg(wp1 + 4));
    }
    for (int p = tid; p < 192; p += 128){ ssc[p] = g_scale1[p]; ssh[p] = g_shift1[p]; }

    // prefetch slice 0 from fp16 hbufs: 3 x 176 uint4 (8 halves each) = 528
    uint4 pf[5];
#pragma unroll
    for (int k = 0; k < 5; k++){
        int f = tid + k*128;
        if (f < 528){
            int buf = f / 176, p = f % 176;
            const __half* hb = (buf == 0) ? g_hbuf0h : ((buf == 1) ? g_hbuf1h : g_hbuf2h);
            pf[k] = __ldg((const uint4*)(hb + (size_t)(blockIdx.x*SPB)*SLICE) + p);
        }
    }
    __syncthreads();   // ssc/ssh visible before staging reads

    for (int s = 0; s < SPB; s++){
        int bt = blockIdx.x*SPB + s;
        int cur = s & 1;

        // stage BN(ReLU(fp16 prefetched)) as tf32 into scat[cur]
#pragma unroll
        for (int k = 0; k < 5; k++){
            int f = tid + k*128;
            if (f < 528){
                int buf = f / 176, p = f % 176;
                int i = p >> 3, c = (p & 7)*8;
                int fc = buf*64 + c;
                uint32* dst = &scat[cur][i*196 + fc];
                uint32 hw[4] = { pf[k].x, pf[k].y, pf[k].z, pf[k].w };
#pragma unroll
                for (int hh = 0; hh < 4; hh++){
                    float2 fv = __half22float2(*reinterpret_cast<__half2*>(&hw[hh]));
                    dst[2*hh    ] = tf32(fmaxf(fv.x*ssc[fc + 2*hh    ] + ssh[fc + 2*hh    ], 0.f));
                    dst[2*hh + 1] = tf32(fmaxf(fv.y*ssc[fc + 2*hh + 1] + ssh[fc + 2*hh + 1], 0.f));
                }
            }
        }
        if (s + 1 < SPB){
#pragma unroll
            for (int k = 0; k < 5; k++){
                int f = tid + k*128;
                if (f < 528){
                    int buf = f / 176, p = f % 176;
                    const __half* hb = (buf == 0) ? g_hbuf0h : ((buf == 1) ? g_hbuf1h : g_hbuf2h);
                    pf[k] = __ldg((const uint4*)(hb + (size_t)(bt + 1)*SLICE) + p);
                }
            }
        }
        __syncthreads();

        const uint32* sc = scat[cur];
        float a0A[4] = {0,0,0,0}, a1A[4] = {0,0,0,0};   // ntile0
        float a0B[4] = {0,0,0,0}, a1B[4] = {0,0,0,0};   // ntile1
#pragma unroll
        for (int k8 = 0; k8 < 24; k8++){
            int c0 = k8*8 + tig, c1 = c0 + 4;
            uint32 A0[4], A1[4];
            A0[0] = sc[ g      *196 + c0];
            A0[1] = sc[(g + 8) *196 + c0];
            A0[2] = sc[ g      *196 + c1];
            A0[3] = sc[(g + 8) *196 + c1];
            A1[0] = r2ok ? sc[(g + 16)*196 + c0] : 0u;
            A1[1] = 0u;
            A1[2] = r2ok ? sc[(g + 16)*196 + c1] : 0u;
            A1[3] = 0u;
            uint32 b0[2] = { bc[k8][0], bc[k8][1] };
            uint32 b1[2] = { bc[k8][2], bc[k8][3] };
            mma_tf32(a0A, A0, b0);  mma_tf32(a1A, A1, b0);
            mma_tf32(a0B, A0, b1);  mma_tf32(a1B, A1, b1);
        }

        float suA0=0.f, suA1=0.f, sqA0=0.f, sqA1=0.f;
        float suB0=0.f, suB1=0.f, sqB0=0.f, sqB1=0.f;
        int rr[3] = { g, g + 8, g + 16 };
        float vaA[3] = { a0A[0], a0A[2], a1A[0] };
        float vbA[3] = { a0A[1], a0A[3], a1A[1] };
        float vaB[3] = { a0B[0], a0B[2], a1B[0] };
        float vbB[3] = { a0B[1], a0B[3], a1B[1] };
        size_t obase = (size_t)bt*SLICE;
#pragma unroll
        for (int q = 0; q < 3; q++){
            if (q == 2 && !r2ok) break;
            int r = rr[q];
            float v0 = vaA[q], v1 = vbA[q], v2 = vaB[q], v3 = vbB[q];
            *(__half2*)&g_pre2h[obase + r*64 + oA] = __floats2half2_rn(v0, v1);
            *(__half2*)&g_pre2h[obase + r*64 + oB] = __floats2half2_rn(v2, v3);
            suA0 += v0; suA1 += v1; sqA0 += v0*v0; sqA1 += v1*v1;
            suB0 += v2; suB1 += v3; sqB0 += v2*v2; sqB1 += v3*v3;
        }
        suA0 = redg(suA0); suA1 = redg(suA1); sqA0 = redg(sqA0); sqA1 = redg(sqA1);
        suB0 = redg(suB0); suB1 = redg(suB1); sqB0 = redg(sqB0); sqB1 = redg(sqB1);
        if (lane < 4){
            g_part2[(size_t)(oA    )*NBT + bt] = suA0;
            g_part2[(size_t)(oA + 1)*NBT + bt] = suA1;
            g_part2[(size_t)(oB    )*NBT + bt] = suB0;
            g_part2[(size_t)(oB + 1)*NBT + bt] = suB1;
            g_part2[(size_t)(64 + oA    )*NBT + bt] = sqA0;
            g_part2[(size_t)(64 + oA + 1)*NBT + bt] = sqA1;
            g_part2[(size_t)(64 + oB    )*NBT + bt] = sqB0;
            g_part2[(size_t)(64 + oB + 1)*NBT + bt] = sqB1;
        }
    }
}

// ---------------- final BN+ReLU elementwise (fp16 in, fp32 out) ----------------
__global__ void k_out(float* __restrict__ out)
{
    size_t idx8 = (size_t)blockIdx.x*256 + threadIdx.x;   // 8 elements per thread
    if (idx8 < TOT/8){
        uint4 v = reinterpret_cast<const uint4*>(g_pre2h)[idx8];
        int ob = (int)((idx8*8) & 63);
        uint32 hw[4] = { v.x, v.y, v.z, v.w };
        float4 o0, o1;
        float2 f0 = __half22float2(*reinterpret_cast<__half2*>(&hw[0]));
        float2 f1 = __half22float2(*reinterpret_cast<__half2*>(&hw[1]));
        float2 f2 = __half22float2(*reinterpret_cast<__half2*>(&hw[2]));
        float2 f3 = __half22float2(*reinterpret_cast<__half2*>(&hw[3]));
        o0.x = fmaxf(f0.x*g_scale2[ob  ] + g_shift2[ob  ], 0.f);
        o0.y = fmaxf(f0.y*g_scale2[ob+1] + g_shift2[ob+1], 0.f);
        o0.z = fmaxf(f1.x*g_scale2[ob+2] + g_shift2[ob+2], 0.f);
        o0.w = fmaxf(f1.y*g_scale2[ob+3] + g_shift2[ob+3], 0.f);
        o1.x = fmaxf(f2.x*g_scale2[ob+4] + g_shift2[ob+4], 0.f);
        o1.y = fmaxf(f2.y*g_scale2[ob+5] + g_shift2[ob+5], 0.f);
        o1.z = fmaxf(f3.x*g_scale2[ob+6] + g_shift2[ob+6], 0.f);
        o1.w = fmaxf(f3.y*g_scale2[ob+7] + g_shift2[ob+7], 0.f);
        reinterpret_cast<float4*>(out)[idx8*2    ] = o0;
        reinterpret_cast<float4*>(out)[idx8*2 + 1] = o1;
    }
}

// ---------------- launch ----------------
#define KMAIN_SMEM_BYTES (25464*4)

extern "C" void kernel_launch(void* const* d_in, const int* in_sizes, int n_in,
                              void* d_out, int out_size)
{
    const float* x        = (const float*)d_in[0];
    const float* W_sym    = (const float*)d_in[1];
    const float* e_sym    = (const float*)d_in[2];
    const float* W_con    = (const float*)d_in[3];
    const float* e_con    = (const float*)d_in[4];
    const float* W_dis    = (const float*)d_in[5];
    const float* att      = (const float*)d_in[6];
    const float* b_dis    = (const float*)d_in[7];
    const float* cat_w    = (const float*)d_in[8];
    const float* gammas   = (const float*)d_in[9];
    const float* betas    = (const float*)d_in[10];
    const int*   rows_sym = (const int*)d_in[11];
    const int*   cols_sym = (const int*)d_in[12];
    const int*   rows_con = (const int*)d_in[13];
    const int*   cols_con = (const int*)d_in[14];
    int nnz_sym = in_sizes[11];
    int nnz_con = in_sizes[13];

    static int configured = 0;
    if (!configured){
        cudaFuncSetAttribute(k_main, cudaFuncAttributeMaxDynamicSharedMemorySize, KMAIN_SMEM_BYTES);
        configured = 1;
    }

    k_prep<<<3, 256>>>(e_sym, rows_sym, cols_sym, nnz_sym,
                       e_con, rows_con, cols_con, nnz_con,
                       W_sym, W_con, W_dis);
    k_main<<<GRID1, 256, KMAIN_SMEM_BYTES>>>(x, att, b_dis);
    k_finalize<<<192, 256>>>(0, gammas, betas);
    k_cat<<<GRID1, 128>>>(cat_w);
    k_finalize<<<64, 256>>>(1, gammas, betas);
    k_out<<<(TOT/8 + 255)/256, 256>>>((float*)d_out);
    (void)n_in; (void)out_size;
}

// round 13
// speedup vs baseline: 1.3343x; 1.0303x over previous
#include <cuda_runtime.h>
#include <cuda_fp16.h>
#include <cstdint>

typedef unsigned int uint32;

#define NBT   3200          // B*T
#define NND   22
#define NCH   64
#define SLICE (NND*NCH)     // 1408
#define TOT   (NBT*SLICE)
#define MAXNZ 484
#define SPB   4             // slices per block (k_main)
#define GRID1 (NBT/SPB)     // 800
#define SPB_CAT 8           // slices per block (k_cat) -> single wave
#define GRID_CAT (NBT/SPB_CAT) // 400
#define OFFCAP0 32
#define OFFCAP1 96
#define ROWCAP0 3
#define ROWCAP1 6
#define XP    72
#define POSC(c) (((c) & ~7) + 2*((c) & 3) + (((c) >> 2) & 1))

// ---------------- device scratch ----------------
__device__ __half g_hbuf0h[TOT];
__device__ __half g_hbuf1h[TOT];
__device__ __half g_hbuf2h[TOT];
__device__ __half g_pre2h[TOT];
__device__ float g_part1[6*64*NBT];
__device__ float g_part2[2*64*NBT];
__device__ float g_scale1[192], g_shift1[192];
__device__ float g_scale2[64],  g_shift2[64];
__device__ float g_Wt[5*4096];          // [g][o][c]
__device__ float g_diag[2][NND*NCH];
__device__ float g_offv[2][MAXNZ*NCH];
__device__ int   g_offcol[2][MAXNZ];
__device__ int   g_rowptr[2][NND+1];

// ---------------- helpers ----------------
__device__ __forceinline__ uint32 tf32(float f){
    uint32 r; asm("cvt.rna.tf32.f32 %0, %1;" : "=r"(r) : "f"(f)); return r;
}
__device__ __forceinline__ void mma_tf32(float c[4], const uint32 a[4], const uint32 b[2]){
    asm volatile("mma.sync.aligned.m16n8k8.row.col.f32.tf32.tf32.f32 "
                 "{%0,%1,%2,%3}, {%4,%5,%6,%7}, {%8,%9}, {%0,%1,%2,%3};"
                 : "+f"(c[0]), "+f"(c[1]), "+f"(c[2]), "+f"(c[3])
                 : "r"(a[0]), "r"(a[1]), "r"(a[2]), "r"(a[3]),
                   "r"(b[0]), "r"(b[1]));
}
__device__ __forceinline__ float redg(float v){
    v += __shfl_down_sync(0xffffffffu, v, 16);
    v += __shfl_down_sync(0xffffffffu, v, 8);
    v += __shfl_down_sync(0xffffffffu, v, 4);
    return v;
}

// no-op spacer: shifts ncu's fixed capture slot onto k_main
__global__ void k_nop(){ }

// ---------------- prep: parallel softmax adjacency construction (proven) ----------------
__global__ void k_prep(const float* __restrict__ e_sym, const int* __restrict__ rows_sym,
                       const int* __restrict__ cols_sym, int nnz_sym,
                       const float* __restrict__ e_con, const int* __restrict__ rows_con,
                       const int* __restrict__ cols_con, int nnz_con,
                       const float* __restrict__ W_sym, const float* __restrict__ W_con,
                       const float* __restrict__ W_dis)
{
    int blk = blockIdx.x, tid = threadIdx.x;
    if (blk == 2){
        for (int p = tid; p < 5*4096; p += 256){
            int g = p >> 12, rem = p & 4095, c = rem >> 6, o = rem & 63;
            float v;
            if (g < 2)      v = W_sym[g*4096 + c*64 + o];
            else if (g < 4) v = W_con[(g-2)*4096 + c*64 + o];
            else            v = W_dis[c*64 + o];
            g_Wt[g*4096 + o*64 + c] = v;
        }
        return;
    }
    int br = blk;
    const float* e  = br ? e_con   : e_sym;
    const int* rows = br ? rows_con : rows_sym;
    const int* cols = br ? cols_con : cols_sym;
    int nnz         = br ? nnz_con : nnz_sym;

    __shared__ int   srows[512], scols[512], sscan[512];
    __shared__ int   srs[NND+1];
    __shared__ float sden[NND*NCH];

    for (int p = tid; p < 512; p += 256){
        int r = (p < nnz) ? rows[p] : 0x7fffffff;
        int c = (p < nnz) ? cols[p] : 0x7fffffff;
        srows[p] = r; scols[p] = c;
        sscan[p] = (p < nnz && r != c) ? 1 : 0;
    }
    for (int p = tid; p < NND*NCH; p += 256) g_diag[br][p] = 0.f;
    __syncthreads();

    if (tid < 32){
        int carry = 0;
        for (int base = 0; base < 512; base += 32){
            int v = sscan[base + tid];
#pragma unroll
            for (int d = 1; d < 32; d <<= 1){
                int t = __shfl_up_sync(0xffffffffu, v, d);
                if (tid >= d) v += t;
            }
            sscan[base + tid] = v + carry;
            carry += __shfl_sync(0xffffffffu, v, 31);
        }
    }
    __syncthreads();

    for (int p = tid; p < nnz; p += 256)
        if (srows[p] != scols[p]) g_offcol[br][sscan[p] - 1] = scols[p];

    for (int p = tid; p <= NND; p += 256){
        int cntoff = 0, cntall = 0;
        for (int k = 0; k < nnz; k++){
            int ro = srows[k];
            cntall += (ro < p);
            cntoff += (ro < p && ro != scols[k]);
        }
        g_rowptr[br][p] = cntoff;
        srs[p] = cntall;
    }
    __syncthreads();

    for (int p = tid; p < NND*NCH; p += 256){
        int i = p >> 6, o = p & 63;
        float s = 0.f;
        int kb = srs[i], ke = srs[i+1];
        for (int k = kb; k < ke; k++) s += expf(e[o*nnz + k]);
        sden[p] = s;
    }
    __syncthreads();

    for (int p = tid; p < 64*nnz; p += 256){
        int k = p >> 6, o = p & 63;
        int r = srows[k];
        float v = expf(e[o*nnz + k]) / sden[r*64 + o];
        if (r != scols[k]) g_offv[br][(sscan[k] - 1)*64 + o] = v;
        else               g_diag[br][r*64 + o] = v;
    }
}

// z gemm K=64: A from permuted tf32 smem, B (Wdis) from smem tf32 (pitch 68)
__device__ __forceinline__ void mma8s64(const uint32* __restrict__ sbuf,
                                        const uint32* __restrict__ swd,
                                        int n0, int g, int tig, int r2ok,
                                        float acc0[4], float acc1[4]){
#pragma unroll
    for (int k8 = 0; k8 < 8; k8++){
        uint32 b[2];
        b[0] = swd[(n0 + g)*68 + k8*8 + tig];
        b[1] = swd[(n0 + g)*68 + k8*8 + tig + 4];
        const uint32* p0 = sbuf + g*XP + k8*8 + 2*tig;
        uint2 va = *(const uint2*)p0;
        uint2 vb = *(const uint2*)(p0 + 8*XP);
        uint2 vc = r2ok ? *(const uint2*)(p0 + 16*XP) : make_uint2(0u, 0u);
        uint32 a0[4] = { va.x, vb.x, va.y, vb.y };
        uint32 a1[4] = { vc.x, 0u,   vc.y, 0u   };
        mma_tf32(acc0, a0, b);
        mma_tf32(acc1, a1, b);
    }
}

// ---------------- main fused kernel ----------------
__global__ __launch_bounds__(256, 2) void k_main(const float* __restrict__ x,
                                                 const float* __restrict__ att,
                                                 const float* __restrict__ b_dis)
{
    extern __shared__ __align__(16) float smem_[];
    float*  sx    = smem_;                         // 1496
    uint32* sxt   = (uint32*)(sx + 1496);          // 1584
    uint32* sdist = sxt + 1584;                    // 1584
    float*  sh1s  = (float*)(sdist + 1584);        // 1408 (also S1/S2 scratch)
    float*  sh1c  = sh1s + 1408;                   // 1408
    uint32* sdwT  = (uint32*)(sh1c + 1408);        // 1792
    uint32* sattT = sdwT + 1792;                   // 528
    float*  sdiag = (float*)(sattT + 528);         // 2816
    float*  soffv = sdiag + 2816;                  // 8192
    int*    ssrp  = (int*)(soffv + 8192);          // 48
    int*    ssocol= ssrp + 48;                     // 128
    float*  sS1   = (float*)(ssocol + 128);        // 64
    float*  sS2   = sS1 + 64;                      // 64
    uint32* swd   = (uint32*)(sS2 + 64);           // 4352

    int tid = threadIdx.x;
    int lane = tid & 31, w = tid >> 5;
    int g = lane >> 2, tig = lane & 3;
    int n0 = w*8;
    int o0 = n0 + 2*tig;
    int r2ok = (g + 16) < NND;

    uint32 bw0s[8][2], bw1s[8][2], bw0c[8][2], bw1c[8][2];
#pragma unroll
    for (int k8 = 0; k8 < 8; k8++){
        const float* w0 = g_Wt + 0*4096 + (n0 + g)*64 + k8*8 + tig;
        const float* w1 = g_Wt + 1*4096 + (n0 + g)*64 + k8*8 + tig;
        const float* w2 = g_Wt + 2*4096 + (n0 + g)*64 + k8*8 + tig;
        const float* w3 = g_Wt + 3*4096 + (n0 + g)*64 + k8*8 + tig;
        bw0s[k8][0] = tf32(__ldg(w0)); bw0s[k8][1] = tf32(__ldg(w0 + 4));
        bw1s[k8][0] = tf32(__ldg(w1)); bw1s[k8][1] = tf32(__ldg(w1 + 4));
        bw0c[k8][0] = tf32(__ldg(w2)); bw0c[k8][1] = tf32(__ldg(w2 + 4));
        bw1c[k8][0] = tf32(__ldg(w3)); bw1c[k8][1] = tf32(__ldg(w3 + 4));
    }

    for (int p = tid; p < NND*24; p += 256){
        int i = p / 24, c = p % 24;
        sattT[p] = (c < NND) ? tf32(__ldg(&att[i*NND + c])) : 0u;
    }
    for (int p = tid; p < 64*28; p += 256) sdwT[p] = 0u;
    for (int p = tid; p < 4096; p += 256) swd[(p >> 6)*68 + (p & 63)] = tf32(g_Wt[4*4096 + p]);
    for (int p = tid; p < 2*(NND+1); p += 256) ssrp[(p/(NND+1))*23 + (p%(NND+1))] = g_rowptr[p/(NND+1)][p%(NND+1)];
    for (int p = tid; p < 2*NND*64; p += 256) sdiag[p] = g_diag[p/(NND*64)][p%(NND*64)];
    {
        int cnt0 = g_rowptr[0][NND]; if (cnt0 > OFFCAP0) cnt0 = OFFCAP0;
        int cnt1 = g_rowptr[1][NND]; if (cnt1 > OFFCAP1) cnt1 = OFFCAP1;
        for (int p = tid; p < cnt0*64; p += 256) soffv[p] = g_offv[0][p];
        for (int p = tid; p < cnt1*64; p += 256) soffv[OFFCAP0*64 + p] = g_offv[1][p];
        for (int p = tid; p < cnt0; p += 256) ssocol[p] = g_offcol[0][p];
        for (int p = tid; p < cnt1; p += 256) ssocol[OFFCAP0 + p] = g_offcol[1][p];
    }

    float2 bd = *(const float2*)&b_dis[o0];

    float4 xr0, xr1;
    {
        const float4* xg = (const float4*)(x + (size_t)(blockIdx.x*SPB)*SLICE);
        xr0 = __ldg(xg + tid);
        xr1 = (tid + 256 < SLICE/4) ? __ldg(xg + tid + 256) : make_float4(0,0,0,0);
    }

    for (int s = 0; s < SPB; s++){
        int bt = blockIdx.x*SPB + s;
        __syncthreads();

        {
            int i = tid >> 4, c = (tid & 15)*4;
            *(float4*)&sx[i*68 + c] = xr0;
            int base = i*XP + (c & ~7) + ((c >> 2) & 1);
            sxt[base    ] = tf32(xr0.x);
            sxt[base + 2] = tf32(xr0.y);
            sxt[base + 4] = tf32(xr0.z);
            sxt[base + 6] = tf32(xr0.w);
            if (tid + 256 < SLICE/4){
                int p = tid + 256; i = p >> 4; c = (p & 15)*4;
                *(float4*)&sx[i*68 + c] = xr1;
                base = i*XP + (c & ~7) + ((c >> 2) & 1);
                sxt[base    ] = tf32(xr1.x);
                sxt[base + 2] = tf32(xr1.y);
                sxt[base + 4] = tf32(xr1.z);
                sxt[base + 6] = tf32(xr1.w);
            }
        }
        if (s + 1 < SPB){
            const float4* xg = (const float4*)(x + (size_t)(bt + 1)*SLICE);
            xr0 = __ldg(xg + tid);
            if (tid + 256 < SLICE/4) xr1 = __ldg(xg + tid + 256);
        }
        __syncthreads();

        // parallel S1/S2: 256 threads (4 row-groups x 64 channels), scratch = sh1s
        {
            int ch = tid & 63, grp = tid >> 6;
            int rb = grp*6, re = rb + 6; if (re > NND) re = NND;
            float s1 = 0.f, s2 = 0.f;
            for (int i = rb; i < re; i++){
                float v = sx[i*68 + ch];
                s1 += v; s2 += v*v;
            }
            sh1s[grp*64 + ch]       = s1;
            sh1s[256 + grp*64 + ch] = s2;
        }
        __syncthreads();
        if (tid < 64){
            sS1[tid] = sh1s[tid] + sh1s[64 + tid] + sh1s[128 + tid] + sh1s[192 + tid];
            sS2[tid] = sh1s[256 + tid] + sh1s[320 + tid] + sh1s[384 + tid] + sh1s[448 + tid];
        }
        __syncthreads();

        for (int p = tid; p < SLICE; p += 256){
            int i = p >> 6, c = p & 63;
            float v = sx[i*68 + c];
            float d = sS2[c] - 2.f*v*sS1[c] + (float)NND*v*v;
            sdist[i*XP + POSC(c)] = tf32(sqrtf(fmaxf(d, 0.f)) + 1e-8f);
        }
        __syncthreads();

        size_t obase = (size_t)bt*SLICE;

        float hs0[4] = {0,0,0,0}, hs1[4] = {0,0,0,0};
        float es0[4] = {0,0,0,0}, es1[4] = {0,0,0,0};
        float hc0[4] = {0,0,0,0}, hc1[4] = {0,0,0,0};
        float ec0[4] = {0,0,0,0}, ec1[4] = {0,0,0,0};
#pragma unroll
        for (int k8 = 0; k8 < 8; k8++){
            const uint32* p0 = sxt + g*XP + k8*8 + 2*tig;
            uint2 va = *(const uint2*)p0;
            uint2 vb = *(const uint2*)(p0 + 8*XP);
            uint2 vc = r2ok ? *(const uint2*)(p0 + 16*XP) : make_uint2(0u, 0u);
            uint32 A0[4] = { va.x, vb.x, va.y, vb.y };
            uint32 A1[4] = { vc.x, 0u,   vc.y, 0u   };
            mma_tf32(hs0, A0, bw0s[k8]);  mma_tf32(hs1, A1, bw0s[k8]);
            mma_tf32(es0, A0, bw1s[k8]);  mma_tf32(es1, A1, bw1s[k8]);
            mma_tf32(hc0, A0, bw0c[k8]);  mma_tf32(hc1, A1, bw0c[k8]);
            mma_tf32(ec0, A0, bw1c[k8]);  mma_tf32(ec1, A1, bw1c[k8]);
        }
        __syncthreads();   // sh1s scratch fully consumed before overwrite
        sh1s[ g      *64 + o0    ] = es0[0];
        sh1s[ g      *64 + o0 + 1] = es0[1];
        sh1s[(g + 8) *64 + o0    ] = es0[2];
        sh1s[(g + 8) *64 + o0 + 1] = es0[3];
        sh1c[ g      *64 + o0    ] = ec0[0];
        sh1c[ g      *64 + o0 + 1] = ec0[1];
        sh1c[(g + 8) *64 + o0    ] = ec0[2];
        sh1c[(g + 8) *64 + o0 + 1] = ec0[3];
        if (r2ok){
            sh1s[(g + 16)*64 + o0    ] = es1[0];
            sh1s[(g + 16)*64 + o0 + 1] = es1[1];
            sh1c[(g + 16)*64 + o0    ] = ec1[0];
            sh1c[(g + 16)*64 + o0 + 1] = ec1[1];
        }
        __syncwarp();

#pragma unroll
        for (int br = 0; br < 2; br++){
            const float* sh1 = br ? sh1c : sh1s;
            const int ob = br ? OFFCAP0 : 0;
            const int CAP = br ? ROWCAP1 : ROWCAP0;
            float su0 = 0.f, su1 = 0.f, sq0 = 0.f, sq1 = 0.f;
            int rr[3] = { g, g + 8, g + 16 };
            float va[3], vb[3];
            if (br == 0){ va[0]=hs0[0]; va[1]=hs0[2]; va[2]=hs1[0]; vb[0]=hs0[1]; vb[1]=hs0[3]; vb[2]=hs1[1]; }
            else        { va[0]=hc0[0]; va[1]=hc0[2]; va[2]=hc1[0]; vb[0]=hc0[1]; vb[1]=hc0[3]; vb[2]=hc1[1]; }
#pragma unroll
            for (int q = 0; q < 3; q++){
                if (q == 2 && !r2ok) break;
                int r = rr[q];
                float2 dg = *(const float2*)&sdiag[br*(NND*64) + r*64 + o0];
                float v0 = va[q]*dg.x, v1 = vb[q]*dg.y;
                int mb = ssrp[br*23 + r], me = ssrp[br*23 + r + 1];
#pragma unroll
                for (int m = 0; m < CAP; m++){
                    int idx = mb + m;
                    if (idx < me){
                        int cm = ssocol[ob + idx];
                        float2 ov = *(const float2*)&soffv[(ob + idx)*64 + o0];
                        v0 += ov.x * sh1[cm*64 + o0];
                        v1 += ov.y * sh1[cm*64 + o0 + 1];
                    }
                }
                __half2 sth = __floats2half2_rn(v0, v1);
                if (br == 0) *(__half2*)&g_hbuf0h[obase + r*64 + o0] = sth;
                else         *(__half2*)&g_hbuf1h[obase + r*64 + o0] = sth;
                su0 += v0; su1 += v1; sq0 += v0*v0; sq1 += v1*v1;
            }
            su0 = redg(su0); su1 = redg(su1); sq0 = redg(sq0); sq1 = redg(sq1);
            if (lane < 4){
                g_part1[(size_t)((2*br  )*64 + o0    )*NBT + bt] = su0;
                g_part1[(size_t)((2*br  )*64 + o0 + 1)*NBT + bt] = su1;
                g_part1[(size_t)((2*br+1)*64 + o0    )*NBT + bt] = sq0;
                g_part1[(size_t)((2*br+1)*64 + o0 + 1)*NBT + bt] = sq1;
            }
        }

        {
            float acc0[4] = {0,0,0,0}, acc1[4] = {0,0,0,0};
            mma8s64(sdist, swd, n0, g, tig, r2ok, acc0, acc1);
            __syncwarp();
            sdwT[ o0     *28 + g     ] = tf32(acc0[0]);
            sdwT[(o0 + 1)*28 + g     ] = tf32(acc0[1]);
            sdwT[ o0     *28 + g + 8 ] = tf32(acc0[2]);
            sdwT[(o0 + 1)*28 + g + 8 ] = tf32(acc0[3]);
            if (r2ok){
                sdwT[ o0     *28 + g + 16] = tf32(acc1[0]);
                sdwT[(o0 + 1)*28 + g + 16] = tf32(acc1[1]);
            }
            __syncwarp();

            float az0[4] = {0,0,0,0}, az1[4] = {0,0,0,0};
#pragma unroll
            for (int k8 = 0; k8 < 3; k8++){
                int c0 = k8*8 + tig, c1 = c0 + 4;
                uint32 a0[4], a1[4], bz[2];
                a0[0] = sattT[ g      *24 + c0];
                a0[1] = sattT[(g + 8) *24 + c0];
                a0[2] = sattT[ g      *24 + c1];
                a0[3] = sattT[(g + 8) *24 + c1];
                a1[0] = r2ok ? sattT[(g + 16)*24 + c0] : 0u;
                a1[1] = 0u;
                a1[2] = r2ok ? sattT[(g + 16)*24 + c1] : 0u;
                a1[3] = 0u;
                bz[0] = sdwT[(n0 + g)*28 + c0];
                bz[1] = sdwT[(n0 + g)*28 + c1];
                mma_tf32(az0, a0, bz);
                mma_tf32(az1, a1, bz);
            }
            float su0 = 0.f, su1 = 0.f, sq0 = 0.f, sq1 = 0.f;
            int rr[3] = { g, g + 8, g + 16 };
            float va[3] = { az0[0], az0[2], az1[0] };
            float vb[3] = { az0[1], az0[3], az1[1] };
#pragma unroll
            for (int q = 0; q < 3; q++){
                if (q == 2 && !r2ok) break;
                int r = rr[q];
                float v0 = va[q] + bd.x, v1 = vb[q] + bd.y;
                *(__half2*)&g_hbuf2h[obase + r*64 + o0] = __floats2half2_rn(v0, v1);
                su0 += v0; su1 += v1; sq0 += v0*v0; sq1 += v1*v1;
            }
            su0 = redg(su0); su1 = redg(su1); sq0 = redg(sq0); sq1 = redg(sq1);
            if (lane < 4){
                g_part1[(size_t)(4*64 + o0    )*NBT + bt] = su0;
                g_part1[(size_t)(4*64 + o0 + 1)*NBT + bt] = su1;
                g_part1[(size_t)(5*64 + o0    )*NBT + bt] = sq0;
                g_part1[(size_t)(5*64 + o0 + 1)*NBT + bt] = sq1;
            }
        }
    }
}

// ---------------- BN stats finalize (unchanged) ----------------
__global__ void k_finalize(int which, const float* __restrict__ gammas,
                           const float* __restrict__ betas)
{
    int ch = blockIdx.x, tid = threadIdx.x;
    int b = ch >> 6, o = ch & 63;
    const float* part = which ? g_part2 : g_part1;
    const float* psum = part + (size_t)((2*b  )*64 + o) * NBT;
    const float* psq  = part + (size_t)((2*b+1)*64 + o) * NBT;
    __shared__ float r1[256], r2[256];
    float s = 0.f, q = 0.f;
    for (int t = tid; t < NBT; t += 256){ s += psum[t]; q += psq[t]; }
    r1[tid] = s; r2[tid] = q;
    __syncthreads();
    for (int off = 128; off; off >>= 1){
        if (tid < off){ r1[tid] += r1[tid+off]; r2[tid] += r2[tid+off]; }
        __syncthreads();
    }
    if (tid == 0){
        const float invM = 1.f / 70400.f;
        float mu  = r1[0]*invM;
        float var = r2[0]*invM - mu*mu;
        int grow = which ? 3 : b;
        float g  = gammas[grow*64 + o], be = betas[grow*64 + o];
        float sc = g * rsqrtf(var + 1e-5f);
        if (which){ g_scale2[o]  = sc; g_shift2[o]  = be - mu*sc; }
        else      { g_scale1[ch] = sc; g_shift1[ch] = be - mu*sc; }
    }
}

// ---------------- k_cat: 128 threads / 4 warps, 2 n-tiles per warp, fp16 I/O, SPB_CAT slices ----------------
__global__ __launch_bounds__(128) void k_cat(const float* __restrict__ cat_w)
{
    __shared__ __align__(16) uint32 scat[2][NND*196];
    __shared__ float ssc[192], ssh[192];

    int tid = threadIdx.x;
    int lane = tid & 31, w = tid >> 5;
    int g = lane >> 2, tig = lane & 3;
    int n0 = w*16;
    int oA = n0 + 2*tig;
    int oB = oA + 8;
    int r2ok = (g + 16) < NND;

    uint32 bc[24][4];
#pragma unroll
    for (int k8 = 0; k8 < 24; k8++){
        const float* wp0 = cat_w + (n0 + g)*192 + k8*8 + tig;
        const float* wp1 = cat_w + (n0 + 8 + g)*192 + k8*8 + tig;
        bc[k8][0] = tf32(__ldg(wp0)); bc[k8][1] = tf32(__ldg(wp0 + 4));
        bc[k8][2] = tf32(__ldg(wp1)); bc[k8][3] = tf32(__ldg(wp1 + 4));
    }
    for (int p = tid; p < 192; p += 128){ ssc[p] = g_scale1[p]; ssh[p] = g_shift1[p]; }

    uint4 pf[5];
#pragma unroll
    for (int k = 0; k < 5; k++){
        int f = tid + k*128;
        if (f < 528){
            int buf = f / 176, p = f % 176;
            const __half* hb = (buf == 0) ? g_hbuf0h : ((buf == 1) ? g_hbuf1h : g_hbuf2h);
            pf[k] = __ldg((const uint4*)(hb + (size_t)(blockIdx.x*SPB_CAT)*SLICE) + p);
        }
    }
    __syncthreads();

    for (int s = 0; s < SPB_CAT; s++){
        int bt = blockIdx.x*SPB_CAT + s;
        int cur = s & 1;

#pragma unroll
        for (int k = 0; k < 5; k++){
            int f = tid + k*128;
            if (f < 528){
                int buf = f / 176, p = f % 176;
                int i = p >> 3, c = (p & 7)*8;
                int fc = buf*64 + c;
                uint32* dst = &scat[cur][i*196 + fc];
                uint32 hw[4] = { pf[k].x, pf[k].y, pf[k].z, pf[k].w };
#pragma unroll
                for (int hh = 0; hh < 4; hh++){
                    float2 fv = __half22float2(*reinterpret_cast<__half2*>(&hw[hh]));
                    dst[2*hh    ] = tf32(fmaxf(fv.x*ssc[fc + 2*hh    ] + ssh[fc + 2*hh    ], 0.f));
                    dst[2*hh + 1] = tf32(fmaxf(fv.y*ssc[fc + 2*hh + 1] + ssh[fc + 2*hh + 1], 0.f));
                }
            }
        }
        if (s + 1 < SPB_CAT){
#pragma unroll
            for (int k = 0; k < 5; k++){
                int f = tid + k*128;
                if (f < 528){
                    int buf = f / 176, p = f % 176;
                    const __half* hb = (buf == 0) ? g_hbuf0h : ((buf == 1) ? g_hbuf1h : g_hbuf2h);
                    pf[k] = __ldg((const uint4*)(hb + (size_t)(bt + 1)*SLICE) + p);
                }
            }
        }
        __syncthreads();

        const uint32* sc = scat[cur];
        float a0A[4] = {0,0,0,0}, a1A[4] = {0,0,0,0};
        float a0B[4] = {0,0,0,0}, a1B[4] = {0,0,0,0};
#pragma unroll
        for (int k8 = 0; k8 < 24; k8++){
            int c0 = k8*8 + tig, c1 = c0 + 4;
            uint32 A0[4], A1[4];
            A0[0] = sc[ g      *196 + c0];
            A0[1] = sc[(g + 8) *196 + c0];
            A0[2] = sc[ g      *196 + c1];
            A0[3] = sc[(g + 8) *196 + c1];
            A1[0] = r2ok ? sc[(g + 16)*196 + c0] : 0u;
            A1[1] = 0u;
            A1[2] = r2ok ? sc[(g + 16)*196 + c1] : 0u;
            A1[3] = 0u;
            uint32 b0[2] = { bc[k8][0], bc[k8][1] };
            uint32 b1[2] = { bc[k8][2], bc[k8][3] };
            mma_tf32(a0A, A0, b0);  mma_tf32(a1A, A1, b0);
            mma_tf32(a0B, A0, b1);  mma_tf32(a1B, A1, b1);
        }

        float suA0=0.f, suA1=0.f, sqA0=0.f, sqA1=0.f;
        float suB0=0.f, suB1=0.f, sqB0=0.f, sqB1=0.f;
        int rr[3] = { g, g + 8, g + 16 };
        float vaA[3] = { a0A[0], a0A[2], a1A[0] };
        float vbA[3] = { a0A[1], a0A[3], a1A[1] };
        float vaB[3] = { a0B[0], a0B[2], a1B[0] };
        float vbB[3] = { a0B[1], a0B[3], a1B[1] };
        size_t obase = (size_t)bt*SLICE;
#pragma unroll
        for (int q = 0; q < 3; q++){
            if (q == 2 && !r2ok) break;
            int r = rr[q];
            float v0 = vaA[q], v1 = vbA[q], v2 = vaB[q], v3 = vbB[q];
            *(__half2*)&g_pre2h[obase + r*64 + oA] = __floats2half2_rn(v0, v1);
            *(__half2*)&g_pre2h[obase + r*64 + oB] = __floats2half2_rn(v2, v3);
            suA0 += v0; suA1 += v1; sqA0 += v0*v0; sqA1 += v1*v1;
            suB0 += v2; suB1 += v3; sqB0 += v2*v2; sqB1 += v3*v3;
        }
        suA0 = redg(suA0); suA1 = redg(suA1); sqA0 = redg(sqA0); sqA1 = redg(sqA1);
        suB0 = redg(suB0); suB1 = redg(suB1); sqB0 = redg(sqB0); sqB1 = redg(sqB1);
        if (lane < 4){
            g_part2[(size_t)(oA    )*NBT + bt] = suA0;
            g_part2[(size_t)(oA + 1)*NBT + bt] = suA1;
            g_part2[(size_t)(oB    )*NBT + bt] = suB0;
            g_part2[(size_t)(oB + 1)*NBT + bt] = suB1;
            g_part2[(size_t)(64 + oA    )*NBT + bt] = sqA0;
            g_part2[(size_t)(64 + oA + 1)*NBT + bt] = sqA1;
            g_part2[(size_t)(64 + oB    )*NBT + bt] = sqB0;
            g_part2[(size_t)(64 + oB + 1)*NBT + bt] = sqB1;
        }
    }
}

// ---------------- final BN+ReLU elementwise (fp16 in, fp32 out) ----------------
__global__ void k_out(float* __restrict__ out)
{
    size_t idx8 = (size_t)blockIdx.x*256 + threadIdx.x;
    if (idx8 < TOT/8){
        uint4 v = reinterpret_cast<const uint4*>(g_pre2h)[idx8];
        int ob = (int)((idx8*8) & 63);
        uint32 hw[4] = { v.x, v.y, v.z, v.w };
        float4 o0, o1;
        float2 f0 = __half22float2(*reinterpret_cast<__half2*>(&hw[0]));
        float2 f1 = __half22float2(*reinterpret_cast<__half2*>(&hw[1]));
        float2 f2 = __half22float2(*reinterpret_cast<__half2*>(&hw[2]));
        float2 f3 = __half22float2(*reinterpret_cast<__half2*>(&hw[3]));
        o0.x = fmaxf(f0.x*g_scale2[ob  ] + g_shift2[ob  ], 0.f);
        o0.y = fmaxf(f0.y*g_scale2[ob+1] + g_shift2[ob+1], 0.f);
        o0.z = fmaxf(f1.x*g_scale2[ob+2] + g_shift2[ob+2], 0.f);
        o0.w = fmaxf(f1.y*g_scale2[ob+3] + g_shift2[ob+3], 0.f);
        o1.x = fmaxf(f2.x*g_scale2[ob+4] + g_shift2[ob+4], 0.f);
        o1.y = fmaxf(f2.y*g_scale2[ob+5] + g_shift2[ob+5], 0.f);
        o1.z = fmaxf(f3.x*g_scale2[ob+6] + g_shift2[ob+6], 0.f);
        o1.w = fmaxf(f3.y*g_scale2[ob+7] + g_shift2[ob+7], 0.f);
        reinterpret_cast<float4*>(out)[idx8*2    ] = o0;
        reinterpret_cast<float4*>(out)[idx8*2 + 1] = o1;
    }
}

// ---------------- launch ----------------
#define KMAIN_SMEM_BYTES (25464*4)

extern "C" void kernel_launch(void* const* d_in, const int* in_sizes, int n_in,
                              void* d_out, int out_size)
{
    const float* x        = (const float*)d_in[0];
    const float* W_sym    = (const float*)d_in[1];
    const float* e_sym    = (const float*)d_in[2];
    const float* W_con    = (const float*)d_in[3];
    const float* e_con    = (const float*)d_in[4];
    const float* W_dis    = (const float*)d_in[5];
    const float* att      = (const float*)d_in[6];
    const float* b_dis    = (const float*)d_in[7];
    const float* cat_w    = (const float*)d_in[8];
    const float* gammas   = (const float*)d_in[9];
    const float* betas    = (const float*)d_in[10];
    const int*   rows_sym = (const int*)d_in[11];
    const int*   cols_sym = (const int*)d_in[12];
    const int*   rows_con = (const int*)d_in[13];
    const int*   cols_con = (const int*)d_in[14];
    int nnz_sym = in_sizes[11];
    int nnz_con = in_sizes[13];

    static int configured = 0;
    if (!configured){
        cudaFuncSetAttribute(k_main, cudaFuncAttributeMaxDynamicSharedMemorySize, KMAIN_SMEM_BYTES);
        configured = 1;
    }

    k_prep<<<3, 256>>>(e_sym, rows_sym, cols_sym, nnz_sym,
                       e_con, rows_con, cols_con, nnz_con,
                       W_sym, W_con, W_dis);
    // spacers: shift ncu's fixed capture slot (historically k_cat, 4th launch)
    // onto k_main for this instrumentation round
    k_nop<<<1, 32>>>();
    k_nop<<<1, 32>>>();
    k_main<<<GRID1, 256, KMAIN_SMEM_BYTES>>>(x, att, b_dis);
    k_finalize<<<192, 256>>>(0, gammas, betas);
    k_cat<<<GRID_CAT, 128>>>(cat_w);
    k_finalize<<<64, 256>>>(1, gammas, betas);
    k_out<<<(TOT/8 + 255)/256, 256>>>((float*)d_out);
    (void)n_in; (void)out_size;
}

// round 14
// speedup vs baseline: 1.5105x; 1.1321x over previous
#include <cuda_runtime.h>
#include <cuda_fp16.h>
#include <cstdint>

typedef unsigned int uint32;

#define NBT   3200
#define NND   22
#define NCH   64
#define SLICE (NND*NCH)
#define TOT   (NBT*SLICE)
#define MAXNZ 484
#define SPB   4
#define GRID1 (NBT/SPB)
#define SPB_CAT 8
#define GRID_CAT (NBT/SPB_CAT)
#define OFFCAP0 32
#define OFFCAP1 96
#define ROWCAP0 3
#define ROWCAP1 6
#define XPH   40            // b32-word pitch of half2 x/dist buffers (40 mod 32 = 8)
#define CPH   104           // b32-word pitch of half2 scat buffer (104 mod 32 = 8)
// permuted position of logical word w within its 8-word group: order [0,4,1,5,2,6,3,7]
#define POSW(w) (((w) & ~7) + 2*((w) & 3) + (((w) >> 2) & 1))

// ---------------- device scratch ----------------
__device__ __half g_hbuf0h[TOT];
__device__ __half g_hbuf1h[TOT];
__device__ __half g_hbuf2h[TOT];
__device__ __half g_pre2h[TOT];
__device__ float g_part1[6*64*NBT];
__device__ float g_part2[2*64*NBT];
__device__ float g_scale1[192], g_shift1[192];
__device__ float g_scale2[64],  g_shift2[64];
__device__ float g_Wt[5*4096];          // [g][o][c]
__device__ float g_diag[2][NND*NCH];
__device__ float g_offv[2][MAXNZ*NCH];
__device__ int   g_offcol[2][MAXNZ];
__device__ int   g_rowptr[2][NND+1];

// ---------------- helpers ----------------
__device__ __forceinline__ uint32 h2f(float a, float b){
    __half2 h = __floats2half2_rn(a, b);
    return *reinterpret_cast<uint32*>(&h);
}
__device__ __forceinline__ uint32 h2g(const float* __restrict__ p){
    return h2f(__ldg(p), __ldg(p + 1));
}
__device__ __forceinline__ void mma_f16(float c[4], const uint32 a[4], const uint32 b[2]){
    asm volatile("mma.sync.aligned.m16n8k16.row.col.f32.f16.f16.f32 "
                 "{%0,%1,%2,%3}, {%4,%5,%6,%7}, {%8,%9}, {%0,%1,%2,%3};"
                 : "+f"(c[0]), "+f"(c[1]), "+f"(c[2]), "+f"(c[3])
                 : "r"(a[0]), "r"(a[1]), "r"(a[2]), "r"(a[3]),
                   "r"(b[0]), "r"(b[1]));
}
__device__ __forceinline__ float redg(float v){
    v += __shfl_down_sync(0xffffffffu, v, 16);
    v += __shfl_down_sync(0xffffffffu, v, 8);
    v += __shfl_down_sync(0xffffffffu, v, 4);
    return v;
}

__global__ void k_nop(){ }

// ---------------- prep: parallel softmax adjacency construction (proven) ----------------
__global__ void k_prep(const float* __restrict__ e_sym, const int* __restrict__ rows_sym,
                       const int* __restrict__ cols_sym, int nnz_sym,
                       const float* __restrict__ e_con, const int* __restrict__ rows_con,
                       const int* __restrict__ cols_con, int nnz_con,
                       const float* __restrict__ W_sym, const float* __restrict__ W_con,
                       const float* __restrict__ W_dis)
{
    int blk = blockIdx.x, tid = threadIdx.x;
    if (blk == 2){
        for (int p = tid; p < 5*4096; p += 256){
            int g = p >> 12, rem = p & 4095, c = rem >> 6, o = rem & 63;
            float v;
            if (g < 2)      v = W_sym[g*4096 + c*64 + o];
            else if (g < 4) v = W_con[(g-2)*4096 + c*64 + o];
            else            v = W_dis[c*64 + o];
            g_Wt[g*4096 + o*64 + c] = v;
        }
        return;
    }
    int br = blk;
    const float* e  = br ? e_con   : e_sym;
    const int* rows = br ? rows_con : rows_sym;
    const int* cols = br ? cols_con : cols_sym;
    int nnz         = br ? nnz_con : nnz_sym;

    __shared__ int   srows[512], scols[512], sscan[512];
    __shared__ int   srs[NND+1];
    __shared__ float sden[NND*NCH];

    for (int p = tid; p < 512; p += 256){
        int r = (p < nnz) ? rows[p] : 0x7fffffff;
        int c = (p < nnz) ? cols[p] : 0x7fffffff;
        srows[p] = r; scols[p] = c;
        sscan[p] = (p < nnz && r != c) ? 1 : 0;
    }
    for (int p = tid; p < NND*NCH; p += 256) g_diag[br][p] = 0.f;
    __syncthreads();

    if (tid < 32){
        int carry = 0;
        for (int base = 0; base < 512; base += 32){
            int v = sscan[base + tid];
#pragma unroll
            for (int d = 1; d < 32; d <<= 1){
                int t = __shfl_up_sync(0xffffffffu, v, d);
                if (tid >= d) v += t;
            }
            sscan[base + tid] = v + carry;
            carry += __shfl_sync(0xffffffffu, v, 31);
        }
    }
    __syncthreads();

    for (int p = tid; p < nnz; p += 256)
        if (srows[p] != scols[p]) g_offcol[br][sscan[p] - 1] = scols[p];

    for (int p = tid; p <= NND; p += 256){
        int cntoff = 0, cntall = 0;
        for (int k = 0; k < nnz; k++){
            int ro = srows[k];
            cntall += (ro < p);
            cntoff += (ro < p && ro != scols[k]);
        }
        g_rowptr[br][p] = cntoff;
        srs[p] = cntall;
    }
    __syncthreads();

    for (int p = tid; p < NND*NCH; p += 256){
        int i = p >> 6, o = p & 63;
        float s = 0.f;
        int kb = srs[i], ke = srs[i+1];
        for (int k = kb; k < ke; k++) s += expf(e[o*nnz + k]);
        sden[p] = s;
    }
    __syncthreads();

    for (int p = tid; p < 64*nnz; p += 256){
        int k = p >> 6, o = p & 63;
        int r = srows[k];
        float v = expf(e[o*nnz + k]) / sden[r*64 + o];
        if (r != scols[k]) g_offv[br][(sscan[k] - 1)*64 + o] = v;
        else               g_diag[br][r*64 + o] = v;
    }
}

// ---------------- main fused kernel: fp16 mma (m16n8k16) ----------------
__global__ __launch_bounds__(256, 2) void k_main(const float* __restrict__ x,
                                                 const float* __restrict__ att,
                                                 const float* __restrict__ b_dis)
{
    extern __shared__ __align__(16) float smem_[];
    float*  sx    = smem_;                         // 1496 (fp32 pitch 68)
    uint32* sxh   = (uint32*)(sx + 1496);          // 880 (half2 words, pitch XPH, permuted)
    uint32* sdish = sxh + 880;                     // 880
    float*  sh1s  = (float*)(sdish + 880);         // 1408 (also S1/S2 scratch)
    float*  sh1c  = sh1s + 1408;                   // 1408
    uint32* sdwT  = (uint32*)(sh1c + 1408);        // 1280 (64 rows x pitch 20 words)
    uint32* satth = sdwT + 1280;                   // 440 (22 rows x pitch 20 words)
    float*  sdiag = (float*)(satth + 440);         // 2816
    float*  soffv = sdiag + 2816;                  // 8192
    int*    ssrp  = (int*)(soffv + 8192);          // 48
    int*    ssocol= ssrp + 48;                     // 128
    float*  sS1   = (float*)(ssocol + 128);        // 64
    float*  sS2   = sS1 + 64;                      // 64
    uint32* swdh  = (uint32*)(sS2 + 64);           // 2304 (Wdis half2, 64 x pitch 36)

    int tid = threadIdx.x;
    int lane = tid & 31, w = tid >> 5;
    int g = lane >> 2, tig = lane & 3;
    int n0 = w*8;
    int o0 = n0 + 2*tig;
    int r2ok = (g + 16) < NND;

    // persistent fp16 B fragments: 4 matrices x 4 ksteps x 2 regs = 32 regs
    uint32 bw0s[4][2], bw1s[4][2], bw0c[4][2], bw1c[4][2];
#pragma unroll
    for (int k = 0; k < 4; k++){
        const float* w0 = g_Wt + 0*4096 + (n0 + g)*64 + k*16 + 2*tig;
        const float* w1 = g_Wt + 1*4096 + (n0 + g)*64 + k*16 + 2*tig;
        const float* w2 = g_Wt + 2*4096 + (n0 + g)*64 + k*16 + 2*tig;
        const float* w3 = g_Wt + 3*4096 + (n0 + g)*64 + k*16 + 2*tig;
        bw0s[k][0] = h2g(w0); bw0s[k][1] = h2g(w0 + 8);
        bw1s[k][0] = h2g(w1); bw1s[k][1] = h2g(w1 + 8);
        bw0c[k][0] = h2g(w2); bw0c[k][1] = h2g(w2 + 8);
        bw1c[k][0] = h2g(w3); bw1c[k][1] = h2g(w3 + 8);
    }

    // ---- block-constant staging ----
    // att as half2 words, rows 22, pitch 20 words (cols j>=22 zeroed)
    for (int p = tid; p < NND*16; p += 256){
        int i = p >> 4, wd = p & 15;
        int j0 = 2*wd, j1 = 2*wd + 1;
        float v0 = (j0 < NND) ? __ldg(&att[i*NND + j0]) : 0.f;
        float v1 = (j1 < NND) ? __ldg(&att[i*NND + j1]) : 0.f;
        satth[i*20 + wd] = h2f(v0, v1);
    }
    // zero sdwT pad (words 11..19 of each of 64 rows -> j>=22 zeros, never rewritten)
    for (int p = tid; p < 64*9; p += 256){
        int o = p / 9, wd = 11 + (p % 9);
        sdwT[o*20 + wd] = 0u;
    }
    // Wdis as half2 words: 64 rows x 32 words, pitch 36
    for (int p = tid; p < 64*32; p += 256){
        int o = p >> 5, wd = p & 31;
        swdh[o*36 + wd] = h2f(g_Wt[4*4096 + o*64 + 2*wd], g_Wt[4*4096 + o*64 + 2*wd + 1]);
    }
    for (int p = tid; p < 2*(NND+1); p += 256) ssrp[(p/(NND+1))*23 + (p%(NND+1))] = g_rowptr[p/(NND+1)][p%(NND+1)];
    for (int p = tid; p < 2*NND*64; p += 256) sdiag[p] = g_diag[p/(NND*64)][p%(NND*64)];
    {
        int cnt0 = g_rowptr[0][NND]; if (cnt0 > OFFCAP0) cnt0 = OFFCAP0;
        int cnt1 = g_rowptr[1][NND]; if (cnt1 > OFFCAP1) cnt1 = OFFCAP1;
        for (int p = tid; p < cnt0*64; p += 256) soffv[p] = g_offv[0][p];
        for (int p = tid; p < cnt1*64; p += 256) soffv[OFFCAP0*64 + p] = g_offv[1][p];
        for (int p = tid; p < cnt0; p += 256) ssocol[p] = g_offcol[0][p];
        for (int p = tid; p < cnt1; p += 256) ssocol[OFFCAP0 + p] = g_offcol[1][p];
    }

    float2 bd = *(const float2*)&b_dis[o0];

    float4 xr0, xr1;
    {
        const float4* xg = (const float4*)(x + (size_t)(blockIdx.x*SPB)*SLICE);
        xr0 = __ldg(xg + tid);
        xr1 = (tid + 256 < SLICE/4) ? __ldg(xg + tid + 256) : make_float4(0,0,0,0);
    }

    for (int s = 0; s < SPB; s++){
        int bt = blockIdx.x*SPB + s;
        __syncthreads();

        // stage x: fp32 (pitch 68) + permuted half2 (pitch XPH)
        {
            int i = tid >> 4, c = (tid & 15)*4;
            *(float4*)&sx[i*68 + c] = xr0;
            int w0 = c >> 1;
            sxh[i*XPH + POSW(w0    )] = h2f(xr0.x, xr0.y);
            sxh[i*XPH + POSW(w0 + 1)] = h2f(xr0.z, xr0.w);
            if (tid + 256 < SLICE/4){
                int p = tid + 256; i = p >> 4; c = (p & 15)*4;
                *(float4*)&sx[i*68 + c] = xr1;
                w0 = c >> 1;
                sxh[i*XPH + POSW(w0    )] = h2f(xr1.x, xr1.y);
                sxh[i*XPH + POSW(w0 + 1)] = h2f(xr1.z, xr1.w);
            }
        }
        if (s + 1 < SPB){
            const float4* xg = (const float4*)(x + (size_t)(bt + 1)*SLICE);
            xr0 = __ldg(xg + tid);
            if (tid + 256 < SLICE/4) xr1 = __ldg(xg + tid + 256);
        }
        __syncthreads();

        // parallel S1/S2 (scratch = sh1s)
        {
            int ch = tid & 63, grp = tid >> 6;
            int rb = grp*6, re = rb + 6; if (re > NND) re = NND;
            float s1 = 0.f, s2 = 0.f;
            for (int i = rb; i < re; i++){
                float v = sx[i*68 + ch];
                s1 += v; s2 += v*v;
            }
            sh1s[grp*64 + ch]       = s1;
            sh1s[256 + grp*64 + ch] = s2;
        }
        __syncthreads();
        if (tid < 64){
            sS1[tid] = sh1s[tid] + sh1s[64 + tid] + sh1s[128 + tid] + sh1s[192 + tid];
            sS2[tid] = sh1s[256 + tid] + sh1s[320 + tid] + sh1s[384 + tid] + sh1s[448 + tid];
        }
        __syncthreads();

        // dist -> permuted half2
        for (int p = tid; p < NND*32; p += 256){
            int i = p >> 5, wd = p & 31;
            int c0 = 2*wd;
            float u0 = sx[i*68 + c0], u1 = sx[i*68 + c0 + 1];
            float d0 = sS2[c0    ] - 2.f*u0*sS1[c0    ] + (float)NND*u0*u0;
            float d1 = sS2[c0 + 1] - 2.f*u1*sS1[c0 + 1] + (float)NND*u1*u1;
            float v0 = sqrtf(fmaxf(d0, 0.f)) + 1e-8f;
            float v1 = sqrtf(fmaxf(d1, 0.f)) + 1e-8f;
            sdish[i*XPH + POSW(wd)] = h2f(v0, v1);
        }
        __syncthreads();

        size_t obase = (size_t)bt*SLICE;

        // ===== fused 4-weight x-gemm: 4 k16 steps, 8 mma each =====
        float hs0[4] = {0,0,0,0}, hs1[4] = {0,0,0,0};
        float es0[4] = {0,0,0,0}, es1[4] = {0,0,0,0};
        float hc0[4] = {0,0,0,0}, hc1[4] = {0,0,0,0};
        float ec0[4] = {0,0,0,0}, ec1[4] = {0,0,0,0};
#pragma unroll
        for (int k = 0; k < 4; k++){
            const uint32* p0 = sxh + g*XPH + k*8 + 2*tig;
            uint2 va = *(const uint2*)p0;               // row g:   (a0, a2)
            uint2 vb = *(const uint2*)(p0 + 8*XPH);     // row g+8: (a1, a3)
            uint2 vc = r2ok ? *(const uint2*)(p0 + 16*XPH) : make_uint2(0u, 0u);
            uint32 A0[4] = { va.x, vb.x, va.y, vb.y };
            uint32 A1[4] = { vc.x, 0u,   vc.y, 0u   };
            mma_f16(hs0, A0, bw0s[k]);  mma_f16(hs1, A1, bw0s[k]);
            mma_f16(es0, A0, bw1s[k]);  mma_f16(es1, A1, bw1s[k]);
            mma_f16(hc0, A0, bw0c[k]);  mma_f16(hc1, A1, bw0c[k]);
            mma_f16(ec0, A0, bw1c[k]);  mma_f16(ec1, A1, bw1c[k]);
        }
        __syncthreads();   // sh1s scratch consumed
        sh1s[ g      *64 + o0    ] = es0[0];
        sh1s[ g      *64 + o0 + 1] = es0[1];
        sh1s[(g + 8) *64 + o0    ] = es0[2];
        sh1s[(g + 8) *64 + o0 + 1] = es0[3];
        sh1c[ g      *64 + o0    ] = ec0[0];
        sh1c[ g      *64 + o0 + 1] = ec0[1];
        sh1c[(g + 8) *64 + o0    ] = ec0[2];
        sh1c[(g + 8) *64 + o0 + 1] = ec0[3];
        if (r2ok){
            sh1s[(g + 16)*64 + o0    ] = es1[0];
            sh1s[(g + 16)*64 + o0 + 1] = es1[1];
            sh1c[(g + 16)*64 + o0    ] = ec1[0];
            sh1c[(g + 16)*64 + o0 + 1] = ec1[1];
        }
        __syncwarp();

        // ===== mix epilogues (unchanged fp32 path) =====
#pragma unroll
        for (int br = 0; br < 2; br++){
            const float* sh1 = br ? sh1c : sh1s;
            const int ob = br ? OFFCAP0 : 0;
            const int CAP = br ? ROWCAP1 : ROWCAP0;
            float su0 = 0.f, su1 = 0.f, sq0 = 0.f, sq1 = 0.f;
            int rr[3] = { g, g + 8, g + 16 };
            float va[3], vb[3];
            if (br == 0){ va[0]=hs0[0]; va[1]=hs0[2]; va[2]=hs1[0]; vb[0]=hs0[1]; vb[1]=hs0[3]; vb[2]=hs1[1]; }
            else        { va[0]=hc0[0]; va[1]=hc0[2]; va[2]=hc1[0]; vb[0]=hc0[1]; vb[1]=hc0[3]; vb[2]=hc1[1]; }
#pragma unroll
            for (int q = 0; q < 3; q++){
                if (q == 2 && !r2ok) break;
                int r = rr[q];
                float2 dg = *(const float2*)&sdiag[br*(NND*64) + r*64 + o0];
                float v0 = va[q]*dg.x, v1 = vb[q]*dg.y;
                int mb = ssrp[br*23 + r], me = ssrp[br*23 + r + 1];
#pragma unroll
                for (int m = 0; m < CAP; m++){
                    int idx = mb + m;
                    if (idx < me){
                        int cm = ssocol[ob + idx];
                        float2 ov = *(const float2*)&soffv[(ob + idx)*64 + o0];
                        v0 += ov.x * sh1[cm*64 + o0];
                        v1 += ov.y * sh1[cm*64 + o0 + 1];
                    }
                }
                __half2 sth = __floats2half2_rn(v0, v1);
                if (br == 0) *(__half2*)&g_hbuf0h[obase + r*64 + o0] = sth;
                else         *(__half2*)&g_hbuf1h[obase + r*64 + o0] = sth;
                su0 += v0; su1 += v1; sq0 += v0*v0; sq1 += v1*v1;
            }
            su0 = redg(su0); su1 = redg(su1); sq0 = redg(sq0); sq1 = redg(sq1);
            if (lane < 4){
                g_part1[(size_t)((2*br  )*64 + o0    )*NBT + bt] = su0;
                g_part1[(size_t)((2*br  )*64 + o0 + 1)*NBT + bt] = su1;
                g_part1[(size_t)((2*br+1)*64 + o0    )*NBT + bt] = sq0;
                g_part1[(size_t)((2*br+1)*64 + o0 + 1)*NBT + bt] = sq1;
            }
        }

        // ===== z branch: dis @ Wdis (fp16 mma), then att @ dw (fp16 mma) =====
        {
            float acc0[4] = {0,0,0,0}, acc1[4] = {0,0,0,0};
#pragma unroll
            for (int k = 0; k < 4; k++){
                uint32 b[2];
                b[0] = swdh[(n0 + g)*36 + k*8 + tig];
                b[1] = swdh[(n0 + g)*36 + k*8 + tig + 4];
                const uint32* p0 = sdish + g*XPH + k*8 + 2*tig;
                uint2 va = *(const uint2*)p0;
                uint2 vb = *(const uint2*)(p0 + 8*XPH);
                uint2 vc = r2ok ? *(const uint2*)(p0 + 16*XPH) : make_uint2(0u, 0u);
                uint32 A0[4] = { va.x, vb.x, va.y, vb.y };
                uint32 A1[4] = { vc.x, 0u,   vc.y, 0u   };
                mma_f16(acc0, A0, b);
                mma_f16(acc1, A1, b);
            }
            __syncwarp();
            // store dw transposed as halves: sdwT rows n (pitch 20 words = 40 halves)
            {
                __half* dwh = (__half*)sdwT;
                dwh[ o0     *40 + g     ] = __float2half_rn(acc0[0]);
                dwh[(o0 + 1)*40 + g     ] = __float2half_rn(acc0[1]);
                dwh[ o0     *40 + g + 8 ] = __float2half_rn(acc0[2]);
                dwh[(o0 + 1)*40 + g + 8 ] = __float2half_rn(acc0[3]);
                if (r2ok){
                    dwh[ o0     *40 + g + 16] = __float2half_rn(acc1[0]);
                    dwh[(o0 + 1)*40 + g + 16] = __float2half_rn(acc1[1]);
                }
            }
            __syncwarp();

            float az0[4] = {0,0,0,0}, az1[4] = {0,0,0,0};
#pragma unroll
            for (int k = 0; k < 2; k++){
                uint32 A0[4], A1[4], bz[2];
                A0[0] = satth[ g      *20 + k*8 + tig];
                A0[1] = satth[(g + 8) *20 + k*8 + tig];
                A0[2] = satth[ g      *20 + k*8 + tig + 4];
                A0[3] = satth[(g + 8) *20 + k*8 + tig + 4];
                A1[0] = r2ok ? satth[(g + 16)*20 + k*8 + tig] : 0u;
                A1[1] = 0u;
                A1[2] = r2ok ? satth[(g + 16)*20 + k*8 + tig + 4] : 0u;
                A1[3] = 0u;
                bz[0] = sdwT[(n0 + g)*20 + k*8 + tig];
                bz[1] = sdwT[(n0 + g)*20 + k*8 + tig + 4];
                mma_f16(az0, A0, bz);
                mma_f16(az1, A1, bz);
            }
            float su0 = 0.f, su1 = 0.f, sq0 = 0.f, sq1 = 0.f;
            int rr[3] = { g, g + 8, g + 16 };
            float va[3] = { az0[0], az0[2], az1[0] };
            float vb[3] = { az0[1], az0[3], az1[1] };
#pragma unroll
            for (int q = 0; q < 3; q++){
                if (q == 2 && !r2ok) break;
                int r = rr[q];
                float v0 = va[q] + bd.x, v1 = vb[q] + bd.y;
                *(__half2*)&g_hbuf2h[obase + r*64 + o0] = __floats2half2_rn(v0, v1);
                su0 += v0; su1 += v1; sq0 += v0*v0; sq1 += v1*v1;
            }
            su0 = redg(su0); su1 = redg(su1); sq0 = redg(sq0); sq1 = redg(sq1);
            if (lane < 4){
                g_part1[(size_t)(4*64 + o0    )*NBT + bt] = su0;
                g_part1[(size_t)(4*64 + o0 + 1)*NBT + bt] = su1;
                g_part1[(size_t)(5*64 + o0    )*NBT + bt] = sq0;
                g_part1[(size_t)(5*64 + o0 + 1)*NBT + bt] = sq1;
            }
        }
    }
}

// ---------------- BN stats finalize (unchanged) ----------------
__global__ void k_finalize(int which, const float* __restrict__ gammas,
                           const float* __restrict__ betas)
{
    int ch = blockIdx.x, tid = threadIdx.x;
    int b = ch >> 6, o = ch & 63;
    const float* part = which ? g_part2 : g_part1;
    const float* psum = part + (size_t)((2*b  )*64 + o) * NBT;
    const float* psq  = part + (size_t)((2*b+1)*64 + o) * NBT;
    __shared__ float r1[256], r2[256];
    float s = 0.f, q = 0.f;
    for (int t = tid; t < NBT; t += 256){ s += psum[t]; q += psq[t]; }
    r1[tid] = s; r2[tid] = q;
    __syncthreads();
    for (int off = 128; off; off >>= 1){
        if (tid < off){ r1[tid] += r1[tid+off]; r2[tid] += r2[tid+off]; }
        __syncthreads();
    }
    if (tid == 0){
        const float invM = 1.f / 70400.f;
        float mu  = r1[0]*invM;
        float var = r2[0]*invM - mu*mu;
        int grow = which ? 3 : b;
        float g  = gammas[grow*64 + o], be = betas[grow*64 + o];
        float sc = g * rsqrtf(var + 1e-5f);
        if (which){ g_scale2[o]  = sc; g_shift2[o]  = be - mu*sc; }
        else      { g_scale1[ch] = sc; g_shift1[ch] = be - mu*sc; }
    }
}

// ---------------- k_cat: fp16 mma, 128 threads / 4 warps / 2 n-tiles ----------------
__global__ __launch_bounds__(128) void k_cat(const float* __restrict__ cat_w)
{
    __shared__ __align__(16) uint32 scat[2][NND*CPH];
    __shared__ float ssc[192], ssh[192];

    int tid = threadIdx.x;
    int lane = tid & 31, w = tid >> 5;
    int g = lane >> 2, tig = lane & 3;
    int n0 = w*16;
    int oA = n0 + 2*tig;
    int oB = oA + 8;
    int r2ok = (g + 16) < NND;

    // fp16 B fragments: 12 k16-steps x (2 ntiles x 2)
    uint32 bc[12][4];
#pragma unroll
    for (int k = 0; k < 12; k++){
        const float* wp0 = cat_w + (n0 + g)*192 + k*16 + 2*tig;
        const float* wp1 = cat_w + (n0 + 8 + g)*192 + k*16 + 2*tig;
        bc[k][0] = h2g(wp0); bc[k][1] = h2g(wp0 + 8);
        bc[k][2] = h2g(wp1); bc[k][3] = h2g(wp1 + 8);
    }
    for (int p = tid; p < 192; p += 128){ ssc[p] = g_scale1[p]; ssh[p] = g_shift1[p]; }

    uint4 pf[5];
#pragma unroll
    for (int k = 0; k < 5; k++){
        int f = tid + k*128;
        if (f < 528){
            int buf = f / 176, p = f % 176;
            const __half* hb = (buf == 0) ? g_hbuf0h : ((buf == 1) ? g_hbuf1h : g_hbuf2h);
            pf[k] = __ldg((const uint4*)(hb + (size_t)(blockIdx.x*SPB_CAT)*SLICE) + p);
        }
    }
    __syncthreads();

    for (int s = 0; s < SPB_CAT; s++){
        int bt = blockIdx.x*SPB_CAT + s;
        int cur = s & 1;

        // stage BN(ReLU(fp16)) as permuted half2 into scat[cur]
#pragma unroll
        for (int k = 0; k < 5; k++){
            int f = tid + k*128;
            if (f < 528){
                int buf = f / 176, p = f % 176;
                int i = p >> 3, c = (p & 7)*8;
                int fc = buf*64 + c;
                int w0 = fc >> 1;                 // first of 4 logical words
                uint32 hw[4] = { pf[k].x, pf[k].y, pf[k].z, pf[k].w };
#pragma unroll
                for (int hh = 0; hh < 4; hh++){
                    float2 fv = __half22float2(*reinterpret_cast<__half2*>(&hw[hh]));
                    float r0 = fmaxf(fv.x*ssc[fc + 2*hh    ] + ssh[fc + 2*hh    ], 0.f);
                    float r1 = fmaxf(fv.y*ssc[fc + 2*hh + 1] + ssh[fc + 2*hh + 1], 0.f);
                    scat[cur][i*CPH + POSW(w0 + hh)] = h2f(r0, r1);
                }
            }
        }
        if (s + 1 < SPB_CAT){
#pragma unroll
            for (int k = 0; k < 5; k++){
                int f = tid + k*128;
                if (f < 528){
                    int buf = f / 176, p = f % 176;
                    const __half* hb = (buf == 0) ? g_hbuf0h : ((buf == 1) ? g_hbuf1h : g_hbuf2h);
                    pf[k] = __ldg((const uint4*)(hb + (size_t)(bt + 1)*SLICE) + p);
                }
            }
        }
        __syncthreads();

        const uint32* sc = scat[cur];
        float a0A[4] = {0,0,0,0}, a1A[4] = {0,0,0,0};
        float a0B[4] = {0,0,0,0}, a1B[4] = {0,0,0,0};
#pragma unroll
        for (int k = 0; k < 12; k++){
            const uint32* p0 = sc + g*CPH + k*8 + 2*tig;
            uint2 va = *(const uint2*)p0;
            uint2 vb = *(const uint2*)(p0 + 8*CPH);
            uint2 vc = r2ok ? *(const uint2*)(p0 + 16*CPH) : make_uint2(0u, 0u);
            uint32 A0[4] = { va.x, vb.x, va.y, vb.y };
            uint32 A1[4] = { vc.x, 0u,   vc.y, 0u   };
            uint32 b0[2] = { bc[k][0], bc[k][1] };
            uint32 b1[2] = { bc[k][2], bc[k][3] };
            mma_f16(a0A, A0, b0);  mma_f16(a1A, A1, b0);
            mma_f16(a0B, A0, b1);  mma_f16(a1B, A1, b1);
        }

        float suA0=0.f, suA1=0.f, sqA0=0.f, sqA1=0.f;
        float suB0=0.f, suB1=0.f, sqB0=0.f, sqB1=0.f;
        int rr[3] = { g, g + 8, g + 16 };
        float vaA[3] = { a0A[0], a0A[2], a1A[0] };
        float vbA[3] = { a0A[1], a0A[3], a1A[1] };
        float vaB[3] = { a0B[0], a0B[2], a1B[0] };
        float vbB[3] = { a0B[1], a0B[3], a1B[1] };
        size_t obase = (size_t)bt*SLICE;
#pragma unroll
        for (int q = 0; q < 3; q++){
            if (q == 2 && !r2ok) break;
            int r = rr[q];
            float v0 = vaA[q], v1 = vbA[q], v2 = vaB[q], v3 = vbB[q];
            *(__half2*)&g_pre2h[obase + r*64 + oA] = __floats2half2_rn(v0, v1);
            *(__half2*)&g_pre2h[obase + r*64 + oB] = __floats2half2_rn(v2, v3);
            suA0 += v0; suA1 += v1; sqA0 += v0*v0; sqA1 += v1*v1;
            suB0 += v2; suB1 += v3; sqB0 += v2*v2; sqB1 += v3*v3;
        }
        suA0 = redg(suA0); suA1 = redg(suA1); sqA0 = redg(sqA0); sqA1 = redg(sqA1);
        suB0 = redg(suB0); suB1 = redg(suB1); sqB0 = redg(sqB0); sqB1 = redg(sqB1);
        if (lane < 4){
            g_part2[(size_t)(oA    )*NBT + bt] = suA0;
            g_part2[(size_t)(oA + 1)*NBT + bt] = suA1;
            g_part2[(size_t)(oB    )*NBT + bt] = suB0;
            g_part2[(size_t)(oB + 1)*NBT + bt] = suB1;
            g_part2[(size_t)(64 + oA    )*NBT + bt] = sqA0;
            g_part2[(size_t)(64 + oA + 1)*NBT + bt] = sqA1;
            g_part2[(size_t)(64 + oB    )*NBT + bt] = sqB0;
            g_part2[(size_t)(64 + oB + 1)*NBT + bt] = sqB1;
        }
    }
}

// ---------------- final BN+ReLU elementwise (fp16 in, fp32 out) ----------------
__global__ void k_out(float* __restrict__ out)
{
    size_t idx8 = (size_t)blockIdx.x*256 + threadIdx.x;
    if (idx8 < TOT/8){
        uint4 v = reinterpret_cast<const uint4*>(g_pre2h)[idx8];
        int ob = (int)((idx8*8) & 63);
        uint32 hw[4] = { v.x, v.y, v.z, v.w };
        float4 o0, o1;
        float2 f0 = __half22float2(*reinterpret_cast<__half2*>(&hw[0]));
        float2 f1 = __half22float2(*reinterpret_cast<__half2*>(&hw[1]));
        float2 f2 = __half22float2(*reinterpret_cast<__half2*>(&hw[2]));
        float2 f3 = __half22float2(*reinterpret_cast<__half2*>(&hw[3]));
        o0.x = fmaxf(f0.x*g_scale2[ob  ] + g_shift2[ob  ], 0.f);
        o0.y = fmaxf(f0.y*g_scale2[ob+1] + g_shift2[ob+1], 0.f);
        o0.z = fmaxf(f1.x*g_scale2[ob+2] + g_shift2[ob+2], 0.f);
        o0.w = fmaxf(f1.y*g_scale2[ob+3] + g_shift2[ob+3], 0.f);
        o1.x = fmaxf(f2.x*g_scale2[ob+4] + g_shift2[ob+4], 0.f);
        o1.y = fmaxf(f2.y*g_scale2[ob+5] + g_shift2[ob+5], 0.f);
        o1.z = fmaxf(f3.x*g_scale2[ob+6] + g_shift2[ob+6], 0.f);
        o1.w = fmaxf(f3.y*g_scale2[ob+7] + g_shift2[ob+7], 0.f);
        reinterpret_cast<float4*>(out)[idx8*2    ] = o0;
        reinterpret_cast<float4*>(out)[idx8*2 + 1] = o1;
    }
}

// ---------------- launch ----------------
#define KMAIN_SMEM_BYTES (21408*4)

extern "C" void kernel_launch(void* const* d_in, const int* in_sizes, int n_in,
                              void* d_out, int out_size)
{
    const float* x        = (const float*)d_in[0];
    const float* W_sym    = (const float*)d_in[1];
    const float* e_sym    = (const float*)d_in[2];
    const float* W_con    = (const float*)d_in[3];
    const float* e_con    = (const float*)d_in[4];
    const float* W_dis    = (const float*)d_in[5];
    const float* att      = (const float*)d_in[6];
    const float* b_dis    = (const float*)d_in[7];
    const float* cat_w    = (const float*)d_in[8];
    const float* gammas   = (const float*)d_in[9];
    const float* betas    = (const float*)d_in[10];
    const int*   rows_sym = (const int*)d_in[11];
    const int*   cols_sym = (const int*)d_in[12];
    const int*   rows_con = (const int*)d_in[13];
    const int*   cols_con = (const int*)d_in[14];
    int nnz_sym = in_sizes[11];
    int nnz_con = in_sizes[13];

    static int configured = 0;
    if (!configured){
        cudaFuncSetAttribute(k_main, cudaFuncAttributeMaxDynamicSharedMemorySize, KMAIN_SMEM_BYTES);
        configured = 1;
    }

    k_prep<<<3, 256>>>(e_sym, rows_sym, cols_sym, nnz_sym,
                       e_con, rows_con, cols_con, nnz_con,
                       W_sym, W_con, W_dis);
    k_nop<<<1, 32>>>();
    k_nop<<<1, 32>>>();
    k_main<<<GRID1, 256, KMAIN_SMEM_BYTES>>>(x, att, b_dis);
    k_finalize<<<192, 256>>>(0, gammas, betas);
    k_cat<<<GRID_CAT, 128>>>(cat_w);
    k_finalize<<<64, 256>>>(1, gammas, betas);
    k_out<<<(TOT/8 + 255)/256, 256>>>((float*)d_out);
    (void)n_in; (void)out_size;
}

// round 15
// speedup vs baseline: 1.7140x; 1.1347x over previous
#include <cuda_runtime.h>
#include <cuda_fp16.h>
#include <cstdint>

typedef unsigned int uint32;

#define NBT   3200
#define NND   22
#define NCH   64
#define SLICE (NND*NCH)
#define TOT   (NBT*SLICE)
#define MAXNZ 484
#define PERSIST 296         // 148 SMs x 2 blocks: exact single-wave residency
#define SPB_CAT 8
#define GRID_CAT (NBT/SPB_CAT)
#define OFFCAP0 32
#define OFFCAP1 96
#define ROWCAP0 3
#define ROWCAP1 6
#define XPH   40            // b32-word pitch of half2 x/dist buffers (40 mod 32 = 8)
#define CPH   104           // b32-word pitch of half2 scat buffer (104 mod 32 = 8)
// permuted position of logical word w within its 8-word group: order [0,4,1,5,2,6,3,7]
#define POSW(w) (((w) & ~7) + 2*((w) & 3) + (((w) >> 2) & 1))

// ---------------- device scratch ----------------
__device__ __half g_hbuf0h[TOT];
__device__ __half g_hbuf1h[TOT];
__device__ __half g_hbuf2h[TOT];
__device__ __half g_pre2h[TOT];
__device__ float g_part1[6*64*NBT];
__device__ float g_part2[2*64*NBT];
__device__ float g_scale1[192], g_shift1[192];
__device__ float g_scale2[64],  g_shift2[64];
__device__ float g_Wt[5*4096];          // [g][o][c]
__device__ float g_diag[2][NND*NCH];
__device__ float g_offv[2][MAXNZ*NCH];
__device__ int   g_offcol[2][MAXNZ];
__device__ int   g_rowptr[2][NND+1];

// ---------------- helpers ----------------
__device__ __forceinline__ uint32 h2f(float a, float b){
    __half2 h = __floats2half2_rn(a, b);
    return *reinterpret_cast<uint32*>(&h);
}
__device__ __forceinline__ uint32 h2g(const float* __restrict__ p){
    return h2f(__ldg(p), __ldg(p + 1));
}
__device__ __forceinline__ void mma_f16(float c[4], const uint32 a[4], const uint32 b[2]){
    asm volatile("mma.sync.aligned.m16n8k16.row.col.f32.f16.f16.f32 "
                 "{%0,%1,%2,%3}, {%4,%5,%6,%7}, {%8,%9}, {%0,%1,%2,%3};"
                 : "+f"(c[0]), "+f"(c[1]), "+f"(c[2]), "+f"(c[3])
                 : "r"(a[0]), "r"(a[1]), "r"(a[2]), "r"(a[3]),
                   "r"(b[0]), "r"(b[1]));
}
__device__ __forceinline__ float redg(float v){
    v += __shfl_down_sync(0xffffffffu, v, 16);
    v += __shfl_down_sync(0xffffffffu, v, 8);
    v += __shfl_down_sync(0xffffffffu, v, 4);
    return v;
}

__global__ void k_nop(){ }

// ---------------- prep: parallel softmax adjacency construction (proven) ----------------
__global__ void k_prep(const float* __restrict__ e_sym, const int* __restrict__ rows_sym,
                       const int* __restrict__ cols_sym, int nnz_sym,
                       const float* __restrict__ e_con, const int* __restrict__ rows_con,
                       const int* __restrict__ cols_con, int nnz_con,
                       const float* __restrict__ W_sym, const float* __restrict__ W_con,
                       const float* __restrict__ W_dis)
{
    int blk = blockIdx.x, tid = threadIdx.x;
    if (blk == 2){
        for (int p = tid; p < 5*4096; p += 256){
            int g = p >> 12, rem = p & 4095, c = rem >> 6, o = rem & 63;
            float v;
            if (g < 2)      v = W_sym[g*4096 + c*64 + o];
            else if (g < 4) v = W_con[(g-2)*4096 + c*64 + o];
            else            v = W_dis[c*64 + o];
            g_Wt[g*4096 + o*64 + c] = v;
        }
        return;
    }
    int br = blk;
    const float* e  = br ? e_con   : e_sym;
    const int* rows = br ? rows_con : rows_sym;
    const int* cols = br ? cols_con : cols_sym;
    int nnz         = br ? nnz_con : nnz_sym;

    __shared__ int   srows[512], scols[512], sscan[512];
    __shared__ int   srs[NND+1];
    __shared__ float sden[NND*NCH];

    for (int p = tid; p < 512; p += 256){
        int r = (p < nnz) ? rows[p] : 0x7fffffff;
        int c = (p < nnz) ? cols[p] : 0x7fffffff;
        srows[p] = r; scols[p] = c;
        sscan[p] = (p < nnz && r != c) ? 1 : 0;
    }
    for (int p = tid; p < NND*NCH; p += 256) g_diag[br][p] = 0.f;
    __syncthreads();

    if (tid < 32){
        int carry = 0;
        for (int base = 0; base < 512; base += 32){
            int v = sscan[base + tid];
#pragma unroll
            for (int d = 1; d < 32; d <<= 1){
                int t = __shfl_up_sync(0xffffffffu, v, d);
                if (tid >= d) v += t;
            }
            sscan[base + tid] = v + carry;
            carry += __shfl_sync(0xffffffffu, v, 31);
        }
    }
    __syncthreads();

    for (int p = tid; p < nnz; p += 256)
        if (srows[p] != scols[p]) g_offcol[br][sscan[p] - 1] = scols[p];

    for (int p = tid; p <= NND; p += 256){
        int cntoff = 0, cntall = 0;
        for (int k = 0; k < nnz; k++){
            int ro = srows[k];
            cntall += (ro < p);
            cntoff += (ro < p && ro != scols[k]);
        }
        g_rowptr[br][p] = cntoff;
        srs[p] = cntall;
    }
    __syncthreads();

    for (int p = tid; p < NND*NCH; p += 256){
        int i = p >> 6, o = p & 63;
        float s = 0.f;
        int kb = srs[i], ke = srs[i+1];
        for (int k = kb; k < ke; k++) s += expf(e[o*nnz + k]);
        sden[p] = s;
    }
    __syncthreads();

    for (int p = tid; p < 64*nnz; p += 256){
        int k = p >> 6, o = p & 63;
        int r = srows[k];
        float v = expf(e[o*nnz + k]) / sden[r*64 + o];
        if (r != scols[k]) g_offv[br][(sscan[k] - 1)*64 + o] = v;
        else               g_diag[br][r*64 + o] = v;
    }
}

// ---------------- main fused kernel: persistent, 4 barriers/slice ----------------
__global__ __launch_bounds__(256, 2) void k_main(const float* __restrict__ x,
                                                 const float* __restrict__ att,
                                                 const float* __restrict__ b_dis)
{
    extern __shared__ __align__(16) float smem_[];
    float*  sx    = smem_;                         // 1496 (fp32 pitch 68)
    uint32* sxh   = (uint32*)(sx + 1496);          // 880 (half2 words, pitch XPH, permuted)
    uint32* sdish = sxh + 880;                     // 880
    float*  sh1s  = (float*)(sdish + 880);         // 1408 (also S1/S2 scratch)
    float*  sh1c  = sh1s + 1408;                   // 1408
    uint32* sdwT  = (uint32*)(sh1c + 1408);        // 1280 (64 rows x pitch 20 words)
    uint32* satth = sdwT + 1280;                   // 440 (22 rows x pitch 20 words)
    float*  sdiag = (float*)(satth + 440);         // 2816
    float*  soffv = sdiag + 2816;                  // 8192
    int*    ssrp  = (int*)(soffv + 8192);          // 48
    int*    ssocol= ssrp + 48;                     // 128
    float*  sS1   = (float*)(ssocol + 128);        // 64
    float*  sS2   = sS1 + 64;                      // 64
    uint32* swdh  = (uint32*)(sS2 + 64);           // 2304 (Wdis half2, 64 x pitch 36)

    int tid = threadIdx.x;
    int lane = tid & 31, w = tid >> 5;
    int g = lane >> 2, tig = lane & 3;
    int n0 = w*8;
    int o0 = n0 + 2*tig;
    int r2ok = (g + 16) < NND;

    // persistent fp16 B fragments: 4 matrices x 4 ksteps x 2 regs = 32 regs
    uint32 bw0s[4][2], bw1s[4][2], bw0c[4][2], bw1c[4][2];
#pragma unroll
    for (int k = 0; k < 4; k++){
        const float* w0 = g_Wt + 0*4096 + (n0 + g)*64 + k*16 + 2*tig;
        const float* w1 = g_Wt + 1*4096 + (n0 + g)*64 + k*16 + 2*tig;
        const float* w2 = g_Wt + 2*4096 + (n0 + g)*64 + k*16 + 2*tig;
        const float* w3 = g_Wt + 3*4096 + (n0 + g)*64 + k*16 + 2*tig;
        bw0s[k][0] = h2g(w0); bw0s[k][1] = h2g(w0 + 8);
        bw1s[k][0] = h2g(w1); bw1s[k][1] = h2g(w1 + 8);
        bw0c[k][0] = h2g(w2); bw0c[k][1] = h2g(w2 + 8);
        bw1c[k][0] = h2g(w3); bw1c[k][1] = h2g(w3 + 8);
    }

    // ---- block-constant staging (once per persistent block) ----
    for (int p = tid; p < NND*16; p += 256){
        int i = p >> 4, wd = p & 15;
        int j0 = 2*wd, j1 = 2*wd + 1;
        float v0 = (j0 < NND) ? __ldg(&att[i*NND + j0]) : 0.f;
        float v1 = (j1 < NND) ? __ldg(&att[i*NND + j1]) : 0.f;
        satth[i*20 + wd] = h2f(v0, v1);
    }
    for (int p = tid; p < 64*9; p += 256){
        int o = p / 9, wd = 11 + (p % 9);
        sdwT[o*20 + wd] = 0u;
    }
    for (int p = tid; p < 64*32; p += 256){
        int o = p >> 5, wd = p & 31;
        swdh[o*36 + wd] = h2f(g_Wt[4*4096 + o*64 + 2*wd], g_Wt[4*4096 + o*64 + 2*wd + 1]);
    }
    for (int p = tid; p < 2*(NND+1); p += 256) ssrp[(p/(NND+1))*23 + (p%(NND+1))] = g_rowptr[p/(NND+1)][p%(NND+1)];
    for (int p = tid; p < 2*NND*64; p += 256) sdiag[p] = g_diag[p/(NND*64)][p%(NND*64)];
    {
        int cnt0 = g_rowptr[0][NND]; if (cnt0 > OFFCAP0) cnt0 = OFFCAP0;
        int cnt1 = g_rowptr[1][NND]; if (cnt1 > OFFCAP1) cnt1 = OFFCAP1;
        for (int p = tid; p < cnt0*64; p += 256) soffv[p] = g_offv[0][p];
        for (int p = tid; p < cnt1*64; p += 256) soffv[OFFCAP0*64 + p] = g_offv[1][p];
        for (int p = tid; p < cnt0; p += 256) ssocol[p] = g_offcol[0][p];
        for (int p = tid; p < cnt1; p += 256) ssocol[OFFCAP0 + p] = g_offcol[1][p];
    }

    float2 bd = *(const float2*)&b_dis[o0];

    // prefetch first slice
    float4 xr0, xr1;
    {
        const float4* xg = (const float4*)(x + (size_t)blockIdx.x*SLICE);
        xr0 = __ldg(xg + tid);
        xr1 = (tid + 256 < SLICE/4) ? __ldg(xg + tid + 256) : make_float4(0,0,0,0);
    }

    for (int bt = blockIdx.x; bt < NBT; bt += PERSIST){
        // NOTE: no top barrier needed — prior slice's post-mma phases never
        // touch sx/sxh, and BAR1 below fences everything else.

        // stage x: fp32 (pitch 68) + permuted half2 (pitch XPH)
        {
            int i = tid >> 4, c = (tid & 15)*4;
            *(float4*)&sx[i*68 + c] = xr0;
            int w0 = c >> 1;
            sxh[i*XPH + POSW(w0    )] = h2f(xr0.x, xr0.y);
            sxh[i*XPH + POSW(w0 + 1)] = h2f(xr0.z, xr0.w);
            if (tid + 256 < SLICE/4){
                int p = tid + 256; i = p >> 4; c = (p & 15)*4;
                *(float4*)&sx[i*68 + c] = xr1;
                w0 = c >> 1;
                sxh[i*XPH + POSW(w0    )] = h2f(xr1.x, xr1.y);
                sxh[i*XPH + POSW(w0 + 1)] = h2f(xr1.z, xr1.w);
            }
        }
        if (bt + PERSIST < NBT){
            const float4* xg = (const float4*)(x + (size_t)(bt + PERSIST)*SLICE);
            xr0 = __ldg(xg + tid);
            if (tid + 256 < SLICE/4) xr1 = __ldg(xg + tid + 256);
        }
        __syncthreads();   // BAR1: stage done (also fences prior-slice readers)

        // parallel S1/S2 partials (scratch = sh1s)
        {
            int ch = tid & 63, grp = tid >> 6;
            int rb = grp*6, re = rb + 6; if (re > NND) re = NND;
            float s1 = 0.f, s2 = 0.f;
            for (int i = rb; i < re; i++){
                float v = sx[i*68 + ch];
                s1 += v; s2 += v*v;
            }
            sh1s[grp*64 + ch]       = s1;
            sh1s[256 + grp*64 + ch] = s2;
        }
        __syncthreads();   // BAR2: partials done
        if (tid < 64){
            sS1[tid] = sh1s[tid] + sh1s[64 + tid] + sh1s[128 + tid] + sh1s[192 + tid];
            sS2[tid] = sh1s[256 + tid] + sh1s[320 + tid] + sh1s[384 + tid] + sh1s[448 + tid];
        }
        __syncthreads();   // BAR3: S1/S2 combined

        // dist -> permuted half2 (no barrier after: mma reads only sxh;
        // sdish's first reader is after BAR4)
        for (int p = tid; p < NND*32; p += 256){
            int i = p >> 5, wd = p & 31;
            int c0 = 2*wd;
            float u0 = sx[i*68 + c0], u1 = sx[i*68 + c0 + 1];
            float d0 = sS2[c0    ] - 2.f*u0*sS1[c0    ] + (float)NND*u0*u0;
            float d1 = sS2[c0 + 1] - 2.f*u1*sS1[c0 + 1] + (float)NND*u1*u1;
            float v0 = sqrtf(fmaxf(d0, 0.f)) + 1e-8f;
            float v1 = sqrtf(fmaxf(d1, 0.f)) + 1e-8f;
            sdish[i*XPH + POSW(wd)] = h2f(v0, v1);
        }

        size_t obase = (size_t)bt*SLICE;

        // ===== fused 4-weight x-gemm: 4 k16 steps, 8 mma each =====
        float hs0[4] = {0,0,0,0}, hs1[4] = {0,0,0,0};
        float es0[4] = {0,0,0,0}, es1[4] = {0,0,0,0};
        float hc0[4] = {0,0,0,0}, hc1[4] = {0,0,0,0};
        float ec0[4] = {0,0,0,0}, ec1[4] = {0,0,0,0};
#pragma unroll
        for (int k = 0; k < 4; k++){
            const uint32* p0 = sxh + g*XPH + k*8 + 2*tig;
            uint2 va = *(const uint2*)p0;
            uint2 vb = *(const uint2*)(p0 + 8*XPH);
            uint2 vc = r2ok ? *(const uint2*)(p0 + 16*XPH) : make_uint2(0u, 0u);
            uint32 A0[4] = { va.x, vb.x, va.y, vb.y };
            uint32 A1[4] = { vc.x, 0u,   vc.y, 0u   };
            mma_f16(hs0, A0, bw0s[k]);  mma_f16(hs1, A1, bw0s[k]);
            mma_f16(es0, A0, bw1s[k]);  mma_f16(es1, A1, bw1s[k]);
            mma_f16(hc0, A0, bw0c[k]);  mma_f16(hc1, A1, bw0c[k]);
            mma_f16(ec0, A0, bw1c[k]);  mma_f16(ec1, A1, bw1c[k]);
        }
        __syncthreads();   // BAR4: sh1s scratch consumed, sdish/sxh retired

        sh1s[ g      *64 + o0    ] = es0[0];
        sh1s[ g      *64 + o0 + 1] = es0[1];
        sh1s[(g + 8) *64 + o0    ] = es0[2];
        sh1s[(g + 8) *64 + o0 + 1] = es0[3];
        sh1c[ g      *64 + o0    ] = ec0[0];
        sh1c[ g      *64 + o0 + 1] = ec0[1];
        sh1c[(g + 8) *64 + o0    ] = ec0[2];
        sh1c[(g + 8) *64 + o0 + 1] = ec0[3];
        if (r2ok){
            sh1s[(g + 16)*64 + o0    ] = es1[0];
            sh1s[(g + 16)*64 + o0 + 1] = es1[1];
            sh1c[(g + 16)*64 + o0    ] = ec1[0];
            sh1c[(g + 16)*64 + o0 + 1] = ec1[1];
        }
        __syncwarp();

        // ===== mix epilogues (unchanged fp32 path) =====
#pragma unroll
        for (int br = 0; br < 2; br++){
            const float* sh1 = br ? sh1c : sh1s;
            const int ob = br ? OFFCAP0 : 0;
            const int CAP = br ? ROWCAP1 : ROWCAP0;
            float su0 = 0.f, su1 = 0.f, sq0 = 0.f, sq1 = 0.f;
            int rr[3] = { g, g + 8, g + 16 };
            float va[3], vb[3];
            if (br == 0){ va[0]=hs0[0]; va[1]=hs0[2]; va[2]=hs1[0]; vb[0]=hs0[1]; vb[1]=hs0[3]; vb[2]=hs1[1]; }
            else        { va[0]=hc0[0]; va[1]=hc0[2]; va[2]=hc1[0]; vb[0]=hc0[1]; vb[1]=hc0[3]; vb[2]=hc1[1]; }
#pragma unroll
            for (int q = 0; q < 3; q++){
                if (q == 2 && !r2ok) break;
                int r = rr[q];
                float2 dg = *(const float2*)&sdiag[br*(NND*64) + r*64 + o0];
                float v0 = va[q]*dg.x, v1 = vb[q]*dg.y;
                int mb = ssrp[br*23 + r], me = ssrp[br*23 + r + 1];
#pragma unroll
                for (int m = 0; m < CAP; m++){
                    int idx = mb + m;
                    if (idx < me){
                        int cm = ssocol[ob + idx];
                        float2 ov = *(const float2*)&soffv[(ob + idx)*64 + o0];
                        v0 += ov.x * sh1[cm*64 + o0];
                        v1 += ov.y * sh1[cm*64 + o0 + 1];
                    }
                }
                __half2 sth = __floats2half2_rn(v0, v1);
                if (br == 0) *(__half2*)&g_hbuf0h[obase + r*64 + o0] = sth;
                else         *(__half2*)&g_hbuf1h[obase + r*64 + o0] = sth;
                su0 += v0; su1 += v1; sq0 += v0*v0; sq1 += v1*v1;
            }
            su0 = redg(su0); su1 = redg(su1); sq0 = redg(sq0); sq1 = redg(sq1);
            if (lane < 4){
                g_part1[(size_t)((2*br  )*64 + o0    )*NBT + bt] = su0;
                g_part1[(size_t)((2*br  )*64 + o0 + 1)*NBT + bt] = su1;
                g_part1[(size_t)((2*br+1)*64 + o0    )*NBT + bt] = sq0;
                g_part1[(size_t)((2*br+1)*64 + o0 + 1)*NBT + bt] = sq1;
            }
        }

        // ===== z branch: dis @ Wdis, then att @ dw (all warp-local smem) =====
        {
            float acc0[4] = {0,0,0,0}, acc1[4] = {0,0,0,0};
#pragma unroll
            for (int k = 0; k < 4; k++){
                uint32 b[2];
                b[0] = swdh[(n0 + g)*36 + k*8 + tig];
                b[1] = swdh[(n0 + g)*36 + k*8 + tig + 4];
                const uint32* p0 = sdish + g*XPH + k*8 + 2*tig;
                uint2 va = *(const uint2*)p0;
                uint2 vb = *(const uint2*)(p0 + 8*XPH);
                uint2 vc = r2ok ? *(const uint2*)(p0 + 16*XPH) : make_uint2(0u, 0u);
                uint32 A0[4] = { va.x, vb.x, va.y, vb.y };
                uint32 A1[4] = { vc.x, 0u,   vc.y, 0u   };
                mma_f16(acc0, A0, b);
                mma_f16(acc1, A1, b);
            }
            __syncwarp();
            {
                __half* dwh = (__half*)sdwT;
                dwh[ o0     *40 + g     ] = __float2half_rn(acc0[0]);
                dwh[(o0 + 1)*40 + g     ] = __float2half_rn(acc0[1]);
                dwh[ o0     *40 + g + 8 ] = __float2half_rn(acc0[2]);
                dwh[(o0 + 1)*40 + g + 8 ] = __float2half_rn(acc0[3]);
                if (r2ok){
                    dwh[ o0     *40 + g + 16] = __float2half_rn(acc1[0]);
                    dwh[(o0 + 1)*40 + g + 16] = __float2half_rn(acc1[1]);
                }
            }
            __syncwarp();

            float az0[4] = {0,0,0,0}, az1[4] = {0,0,0,0};
#pragma unroll
            for (int k = 0; k < 2; k++){
                uint32 A0[4], A1[4], bz[2];
                A0[0] = satth[ g      *20 + k*8 + tig];
                A0[1] = satth[(g + 8) *20 + k*8 + tig];
                A0[2] = satth[ g      *20 + k*8 + tig + 4];
                A0[3] = satth[(g + 8) *20 + k*8 + tig + 4];
                A1[0] = r2ok ? satth[(g + 16)*20 + k*8 + tig] : 0u;
                A1[1] = 0u;
                A1[2] = r2ok ? satth[(g + 16)*20 + k*8 + tig + 4] : 0u;
                A1[3] = 0u;
                bz[0] = sdwT[(n0 + g)*20 + k*8 + tig];
                bz[1] = sdwT[(n0 + g)*20 + k*8 + tig + 4];
                mma_f16(az0, A0, bz);
                mma_f16(az1, A1, bz);
            }
            float su0 = 0.f, su1 = 0.f, sq0 = 0.f, sq1 = 0.f;
            int rr[3] = { g, g + 8, g + 16 };
            float va[3] = { az0[0], az0[2], az1[0] };
            float vb[3] = { az0[1], az0[3], az1[1] };
#pragma unroll
            for (int q = 0; q < 3; q++){
                if (q == 2 && !r2ok) break;
                int r = rr[q];
                float v0 = va[q] + bd.x, v1 = vb[q] + bd.y;
                *(__half2*)&g_hbuf2h[obase + r*64 + o0] = __floats2half2_rn(v0, v1);
                su0 += v0; su1 += v1; sq0 += v0*v0; sq1 += v1*v1;
            }
            su0 = redg(su0); su1 = redg(su1); sq0 = redg(sq0); sq1 = redg(sq1);
            if (lane < 4){
                g_part1[(size_t)(4*64 + o0    )*NBT + bt] = su0;
                g_part1[(size_t)(4*64 + o0 + 1)*NBT + bt] = su1;
                g_part1[(size_t)(5*64 + o0    )*NBT + bt] = sq0;
                g_part1[(size_t)(5*64 + o0 + 1)*NBT + bt] = sq1;
            }
        }
    }
}

// ---------------- BN stats finalize (unchanged) ----------------
__global__ void k_finalize(int which, const float* __restrict__ gammas,
                           const float* __restrict__ betas)
{
    int ch = blockIdx.x, tid = threadIdx.x;
    int b = ch >> 6, o = ch & 63;
    const float* part = which ? g_part2 : g_part1;
    const float* psum = part + (size_t)((2*b  )*64 + o) * NBT;
    const float* psq  = part + (size_t)((2*b+1)*64 + o) * NBT;
    __shared__ float r1[256], r2[256];
    float s = 0.f, q = 0.f;
    for (int t = tid; t < NBT; t += 256){ s += psum[t]; q += psq[t]; }
    r1[tid] = s; r2[tid] = q;
    __syncthreads();
    for (int off = 128; off; off >>= 1){
        if (tid < off){ r1[tid] += r1[tid+off]; r2[tid] += r2[tid+off]; }
        __syncthreads();
    }
    if (tid == 0){
        const float invM = 1.f / 70400.f;
        float mu  = r1[0]*invM;
        float var = r2[0]*invM - mu*mu;
        int grow = which ? 3 : b;
        float g  = gammas[grow*64 + o], be = betas[grow*64 + o];
        float sc = g * rsqrtf(var + 1e-5f);
        if (which){ g_scale2[o]  = sc; g_shift2[o]  = be - mu*sc; }
        else      { g_scale1[ch] = sc; g_shift1[ch] = be - mu*sc; }
    }
}

// ---------------- k_cat: fp16 mma, 128 threads / 4 warps / 2 n-tiles ----------------
__global__ __launch_bounds__(128) void k_cat(const float* __restrict__ cat_w)
{
    __shared__ __align__(16) uint32 scat[2][NND*CPH];
    __shared__ float ssc[192], ssh[192];

    int tid = threadIdx.x;
    int lane = tid & 31, w = tid >> 5;
    int g = lane >> 2, tig = lane & 3;
    int n0 = w*16;
    int oA = n0 + 2*tig;
    int oB = oA + 8;
    int r2ok = (g + 16) < NND;

    uint32 bc[12][4];
#pragma unroll
    for (int k = 0; k < 12; k++){
        const float* wp0 = cat_w + (n0 + g)*192 + k*16 + 2*tig;
        const float* wp1 = cat_w + (n0 + 8 + g)*192 + k*16 + 2*tig;
        bc[k][0] = h2g(wp0); bc[k][1] = h2g(wp0 + 8);
        bc[k][2] = h2g(wp1); bc[k][3] = h2g(wp1 + 8);
    }
    for (int p = tid; p < 192; p += 128){ ssc[p] = g_scale1[p]; ssh[p] = g_shift1[p]; }

    uint4 pf[5];
#pragma unroll
    for (int k = 0; k < 5; k++){
        int f = tid + k*128;
        if (f < 528){
            int buf = f / 176, p = f % 176;
            const __half* hb = (buf == 0) ? g_hbuf0h : ((buf == 1) ? g_hbuf1h : g_hbuf2h);
            pf[k] = __ldg((const uint4*)(hb + (size_t)(blockIdx.x*SPB_CAT)*SLICE) + p);
        }
    }
    __syncthreads();

    for (int s = 0; s < SPB_CAT; s++){
        int bt = blockIdx.x*SPB_CAT + s;
        int cur = s & 1;

#pragma unroll
        for (int k = 0; k < 5; k++){
            int f = tid + k*128;
            if (f < 528){
                int buf = f / 176, p = f % 176;
                int i = p >> 3, c = (p & 7)*8;
                int fc = buf*64 + c;
                int w0 = fc >> 1;
                uint32 hw[4] = { pf[k].x, pf[k].y, pf[k].z, pf[k].w };
#pragma unroll
                for (int hh = 0; hh < 4; hh++){
                    float2 fv = __half22float2(*reinterpret_cast<__half2*>(&hw[hh]));
                    float r0 = fmaxf(fv.x*ssc[fc + 2*hh    ] + ssh[fc + 2*hh    ], 0.f);
                    float r1 = fmaxf(fv.y*ssc[fc + 2*hh + 1] + ssh[fc + 2*hh + 1], 0.f);
                    scat[cur][i*CPH + POSW(w0 + hh)] = h2f(r0, r1);
                }
            }
        }
        if (s + 1 < SPB_CAT){
#pragma unroll
            for (int k = 0; k < 5; k++){
                int f = tid + k*128;
                if (f < 528){
                    int buf = f / 176, p = f % 176;
                    const __half* hb = (buf == 0) ? g_hbuf0h : ((buf == 1) ? g_hbuf1h : g_hbuf2h);
                    pf[k] = __ldg((const uint4*)(hb + (size_t)(bt + 1)*SLICE) + p);
                }
            }
        }
        __syncthreads();

        const uint32* sc = scat[cur];
        float a0A[4] = {0,0,0,0}, a1A[4] = {0,0,0,0};
        float a0B[4] = {0,0,0,0}, a1B[4] = {0,0,0,0};
#pragma unroll
        for (int k = 0; k < 12; k++){
            const uint32* p0 = sc + g*CPH + k*8 + 2*tig;
            uint2 va = *(const uint2*)p0;
            uint2 vb = *(const uint2*)(p0 + 8*CPH);
            uint2 vc = r2ok ? *(const uint2*)(p0 + 16*CPH) : make_uint2(0u, 0u);
            uint32 A0[4] = { va.x, vb.x, va.y, vb.y };
            uint32 A1[4] = { vc.x, 0u,   vc.y, 0u   };
            uint32 b0[2] = { bc[k][0], bc[k][1] };
            uint32 b1[2] = { bc[k][2], bc[k][3] };
            mma_f16(a0A, A0, b0);  mma_f16(a1A, A1, b0);
            mma_f16(a0B, A0, b1);  mma_f16(a1B, A1, b1);
        }

        float suA0=0.f, suA1=0.f, sqA0=0.f, sqA1=0.f;
        float suB0=0.f, suB1=0.f, sqB0=0.f, sqB1=0.f;
        int rr[3] = { g, g + 8, g + 16 };
        float vaA[3] = { a0A[0], a0A[2], a1A[0] };
        float vbA[3] = { a0A[1], a0A[3], a1A[1] };
        float vaB[3] = { a0B[0], a0B[2], a1B[0] };
        float vbB[3] = { a0B[1], a0B[3], a1B[1] };
        size_t obase = (size_t)bt*SLICE;
#pragma unroll
        for (int q = 0; q < 3; q++){
            if (q == 2 && !r2ok) break;
            int r = rr[q];
            float v0 = vaA[q], v1 = vbA[q], v2 = vaB[q], v3 = vbB[q];
            *(__half2*)&g_pre2h[obase + r*64 + oA] = __floats2half2_rn(v0, v1);
            *(__half2*)&g_pre2h[obase + r*64 + oB] = __floats2half2_rn(v2, v3);
            suA0 += v0; suA1 += v1; sqA0 += v0*v0; sqA1 += v1*v1;
            suB0 += v2; suB1 += v3; sqB0 += v2*v2; sqB1 += v3*v3;
        }
        suA0 = redg(suA0); suA1 = redg(suA1); sqA0 = redg(sqA0); sqA1 = redg(sqA1);
        suB0 = redg(suB0); suB1 = redg(suB1); sqB0 = redg(sqB0); sqB1 = redg(sqB1);
        if (lane < 4){
            g_part2[(size_t)(oA    )*NBT + bt] = suA0;
            g_part2[(size_t)(oA + 1)*NBT + bt] = suA1;
            g_part2[(size_t)(oB    )*NBT + bt] = suB0;
            g_part2[(size_t)(oB + 1)*NBT + bt] = suB1;
            g_part2[(size_t)(64 + oA    )*NBT + bt] = sqA0;
            g_part2[(size_t)(64 + oA + 1)*NBT + bt] = sqA1;
            g_part2[(size_t)(64 + oB    )*NBT + bt] = sqB0;
            g_part2[(size_t)(64 + oB + 1)*NBT + bt] = sqB1;
        }
    }
}

// ---------------- final BN+ReLU elementwise (fp16 in, fp32 out) ----------------
__global__ void k_out(float* __restrict__ out)
{
    size_t idx8 = (size_t)blockIdx.x*256 + threadIdx.x;
    if (idx8 < TOT/8){
        uint4 v = reinterpret_cast<const uint4*>(g_pre2h)[idx8];
        int ob = (int)((idx8*8) & 63);
        uint32 hw[4] = { v.x, v.y, v.z, v.w };
        float4 o0, o1;
        float2 f0 = __half22float2(*reinterpret_cast<__half2*>(&hw[0]));
        float2 f1 = __half22float2(*reinterpret_cast<__half2*>(&hw[1]));
        float2 f2 = __half22float2(*reinterpret_cast<__half2*>(&hw[2]));
        float2 f3 = __half22float2(*reinterpret_cast<__half2*>(&hw[3]));
        o0.x = fmaxf(f0.x*g_scale2[ob  ] + g_shift2[ob  ], 0.f);
        o0.y = fmaxf(f0.y*g_scale2[ob+1] + g_shift2[ob+1], 0.f);
        o0.z = fmaxf(f1.x*g_scale2[ob+2] + g_shift2[ob+2], 0.f);
        o0.w = fmaxf(f1.y*g_scale2[ob+3] + g_shift2[ob+3], 0.f);
        o1.x = fmaxf(f2.x*g_scale2[ob+4] + g_shift2[ob+4], 0.f);
        o1.y = fmaxf(f2.y*g_scale2[ob+5] + g_shift2[ob+5], 0.f);
        o1.z = fmaxf(f3.x*g_scale2[ob+6] + g_shift2[ob+6], 0.f);
        o1.w = fmaxf(f3.y*g_scale2[ob+7] + g_shift2[ob+7], 0.f);
        reinterpret_cast<float4*>(out)[idx8*2    ] = o0;
        reinterpret_cast<float4*>(out)[idx8*2 + 1] = o1;
    }
}

// ---------------- launch ----------------
#define KMAIN_SMEM_BYTES (21408*4)

extern "C" void kernel_launch(void* const* d_in, const int* in_sizes, int n_in,
                              void* d_out, int out_size)
{
    const float* x        = (const float*)d_in[0];
    const float* W_sym    = (const float*)d_in[1];
    const float* e_sym    = (const float*)d_in[2];
    const float* W_con    = (const float*)d_in[3];
    const float* e_con    = (const float*)d_in[4];
    const float* W_dis    = (const float*)d_in[5];
    const float* att      = (const float*)d_in[6];
    const float* b_dis    = (const float*)d_in[7];
    const float* cat_w    = (const float*)d_in[8];
    const float* gammas   = (const float*)d_in[9];
    const float* betas    = (const float*)d_in[10];
    const int*   rows_sym = (const int*)d_in[11];
    const int*   cols_sym = (const int*)d_in[12];
    const int*   rows_con = (const int*)d_in[13];
    const int*   cols_con = (const int*)d_in[14];
    int nnz_sym = in_sizes[11];
    int nnz_con = in_sizes[13];

    static int configured = 0;
    if (!configured){
        cudaFuncSetAttribute(k_main, cudaFuncAttributeMaxDynamicSharedMemorySize, KMAIN_SMEM_BYTES);
        configured = 1;
    }

    k_prep<<<3, 256>>>(e_sym, rows_sym, cols_sym, nnz_sym,
                       e_con, rows_con, cols_con, nnz_con,
                       W_sym, W_con, W_dis);
    k_nop<<<1, 32>>>();
    k_nop<<<1, 32>>>();
    k_main<<<PERSIST, 256, KMAIN_SMEM_BYTES>>>(x, att, b_dis);
    k_finalize<<<192, 256>>>(0, gammas, betas);
    k_cat<<<GRID_CAT, 128>>>(cat_w);
    k_finalize<<<64, 256>>>(1, gammas, betas);
    k_out<<<(TOT/8 + 255)/256, 256>>>((float*)d_out);
    (void)n_in; (void)out_size;
}

// round 16
// speedup vs baseline: 1.7814x; 1.0394x over previous
#include <cuda_runtime.h>
#include <cuda_fp16.h>
#include <cstdint>

typedef unsigned int uint32;

#define NBT   3200
#define NND   22
#define NCH   64
#define SLICE (NND*NCH)
#define TOT   (NBT*SLICE)
#define MAXNZ 484
#define PERSIST 296         // 148 SMs x 2 blocks
#define NPAIRS 1480         // 296 x 5: uniform pair phase, slices 0..2959
#define TAILBASE 2960
#define SPB_CAT 8
#define GRID_CAT (NBT/SPB_CAT)
#define OFFCAP0 32
#define OFFCAP1 96
#define ROWCAP0 1           // adj_sym: jl/jr disjoint -> <=1 off-diag per row
#define ROWCAP1 6
#define XPH   40            // b32-word pitch of half2 x/dist buffers (40 mod 32 = 8)
#define CPH   104
#define POSW(w) (((w) & ~7) + 2*((w) & 3) + (((w) >> 2) & 1))

// ---------------- device scratch ----------------
__device__ __half g_hbuf0h[TOT];
__device__ __half g_hbuf1h[TOT];
__device__ __half g_hbuf2h[TOT];
__device__ __half g_pre2h[TOT];
__device__ float g_part1[6*64*NBT];
__device__ float g_part2[2*64*NBT];
__device__ float g_scale1[192], g_shift1[192];
__device__ float g_scale2[64],  g_shift2[64];
__device__ float g_Wt[5*4096];          // [g][o][c]
__device__ float g_diag[2][NND*NCH];
__device__ float g_offv[2][MAXNZ*NCH];
__device__ int   g_offcol[2][MAXNZ];
__device__ int   g_rowptr[2][NND+1];

// ---------------- helpers ----------------
__device__ __forceinline__ uint32 h2f(float a, float b){
    __half2 h = __floats2half2_rn(a, b);
    return *reinterpret_cast<uint32*>(&h);
}
__device__ __forceinline__ uint32 h2g(const float* __restrict__ p){
    return h2f(__ldg(p), __ldg(p + 1));
}
__device__ __forceinline__ void mma_f16(float c[4], const uint32 a[4], const uint32 b[2]){
    asm volatile("mma.sync.aligned.m16n8k16.row.col.f32.f16.f16.f32 "
                 "{%0,%1,%2,%3}, {%4,%5,%6,%7}, {%8,%9}, {%0,%1,%2,%3};"
                 : "+f"(c[0]), "+f"(c[1]), "+f"(c[2]), "+f"(c[3])
                 : "r"(a[0]), "r"(a[1]), "r"(a[2]), "r"(a[3]),
                   "r"(b[0]), "r"(b[1]));
}
__device__ __forceinline__ float redg(float v){
    v += __shfl_down_sync(0xffffffffu, v, 16);
    v += __shfl_down_sync(0xffffffffu, v, 8);
    v += __shfl_down_sync(0xffffffffu, v, 4);
    return v;
}

// ---------------- prep: parallel softmax adjacency construction (proven) ----------------
__global__ void k_prep(const float* __restrict__ e_sym, const int* __restrict__ rows_sym,
                       const int* __restrict__ cols_sym, int nnz_sym,
                       const float* __restrict__ e_con, const int* __restrict__ rows_con,
                       const int* __restrict__ cols_con, int nnz_con,
                       const float* __restrict__ W_sym, const float* __restrict__ W_con,
                       const float* __restrict__ W_dis)
{
    int blk = blockIdx.x, tid = threadIdx.x;
    if (blk == 2){
        for (int p = tid; p < 5*4096; p += 256){
            int g = p >> 12, rem = p & 4095, c = rem >> 6, o = rem & 63;
            float v;
            if (g < 2)      v = W_sym[g*4096 + c*64 + o];
            else if (g < 4) v = W_con[(g-2)*4096 + c*64 + o];
            else            v = W_dis[c*64 + o];
            g_Wt[g*4096 + o*64 + c] = v;
        }
        return;
    }
    int br = blk;
    const float* e  = br ? e_con   : e_sym;
    const int* rows = br ? rows_con : rows_sym;
    const int* cols = br ? cols_con : cols_sym;
    int nnz         = br ? nnz_con : nnz_sym;

    __shared__ int   srows[512], scols[512], sscan[512];
    __shared__ int   srs[NND+1];
    __shared__ float sden[NND*NCH];

    for (int p = tid; p < 512; p += 256){
        int r = (p < nnz) ? rows[p] : 0x7fffffff;
        int c = (p < nnz) ? cols[p] : 0x7fffffff;
        srows[p] = r; scols[p] = c;
        sscan[p] = (p < nnz && r != c) ? 1 : 0;
    }
    for (int p = tid; p < NND*NCH; p += 256) g_diag[br][p] = 0.f;
    __syncthreads();

    if (tid < 32){
        int carry = 0;
        for (int base = 0; base < 512; base += 32){
            int v = sscan[base + tid];
#pragma unroll
            for (int d = 1; d < 32; d <<= 1){
                int t = __shfl_up_sync(0xffffffffu, v, d);
                if (tid >= d) v += t;
            }
            sscan[base + tid] = v + carry;
            carry += __shfl_sync(0xffffffffu, v, 31);
        }
    }
    __syncthreads();

    for (int p = tid; p < nnz; p += 256)
        if (srows[p] != scols[p]) g_offcol[br][sscan[p] - 1] = scols[p];

    for (int p = tid; p <= NND; p += 256){
        int cntoff = 0, cntall = 0;
        for (int k = 0; k < nnz; k++){
            int ro = srows[k];
            cntall += (ro < p);
            cntoff += (ro < p && ro != scols[k]);
        }
        g_rowptr[br][p] = cntoff;
        srs[p] = cntall;
    }
    __syncthreads();

    for (int p = tid; p < NND*NCH; p += 256){
        int i = p >> 6, o = p & 63;
        float s = 0.f;
        int kb = srs[i], ke = srs[i+1];
        for (int k = kb; k < ke; k++) s += expf(e[o*nnz + k]);
        sden[p] = s;
    }
    __syncthreads();

    for (int p = tid; p < 64*nnz; p += 256){
        int k = p >> 6, o = p & 63;
        int r = srows[k];
        float v = expf(e[o*nnz + k]) / sden[r*64 + o];
        if (r != scols[k]) g_offv[br][(sscan[k] - 1)*64 + o] = v;
        else               g_diag[br][r*64 + o] = v;
    }
}

// ---------------- main fused kernel: persistent, pair-packed phases ----------------
__global__ __launch_bounds__(256, 2) void k_main(const float* __restrict__ x,
                                                 const float* __restrict__ att,
                                                 const float* __restrict__ b_dis)
{
    extern __shared__ __align__(16) float smem_[];
    float*  sx    = smem_;                         // 2992 (2 x 22x68)
    uint32* sxh   = (uint32*)(sx + 2992);          // 1760 (2 x 880)
    uint32* sdish = sxh + 1760;                    // 1760
    float*  sh1s  = (float*)(sdish + 1760);        // 1408 (also S1/S2 scratch, 1024 used)
    float*  sh1c  = sh1s + 1408;                   // 1408
    uint32* sdwT  = (uint32*)(sh1c + 1408);        // 1280
    uint32* satth = sdwT + 1280;                   // 440
    float*  sdiag = (float*)(satth + 440);         // 2816
    float*  soffv = sdiag + 2816;                  // 8192
    int*    ssrp  = (int*)(soffv + 8192);          // 48
    int*    ssocol= ssrp + 48;                     // 128
    float*  sS1   = (float*)(ssocol + 128);        // 128 (2x64)
    float*  sS2   = sS1 + 128;                     // 128
    uint32* swdh  = (uint32*)(sS2 + 128);          // 2304

    int tid = threadIdx.x;
    int lane = tid & 31, w = tid >> 5;
    int g = lane >> 2, tig = lane & 3;
    int n0 = w*8;
    int o0 = n0 + 2*tig;
    int r2ok = (g + 16) < NND;

    uint32 bw0s[4][2], bw1s[4][2], bw0c[4][2], bw1c[4][2];
#pragma unroll
    for (int k = 0; k < 4; k++){
        const float* w0 = g_Wt + 0*4096 + (n0 + g)*64 + k*16 + 2*tig;
        const float* w1 = g_Wt + 1*4096 + (n0 + g)*64 + k*16 + 2*tig;
        const float* w2 = g_Wt + 2*4096 + (n0 + g)*64 + k*16 + 2*tig;
        const float* w3 = g_Wt + 3*4096 + (n0 + g)*64 + k*16 + 2*tig;
        bw0s[k][0] = h2g(w0); bw0s[k][1] = h2g(w0 + 8);
        bw1s[k][0] = h2g(w1); bw1s[k][1] = h2g(w1 + 8);
        bw0c[k][0] = h2g(w2); bw0c[k][1] = h2g(w2 + 8);
        bw1c[k][0] = h2g(w3); bw1c[k][1] = h2g(w3 + 8);
    }

    // ---- block-constant staging ----
    for (int p = tid; p < NND*16; p += 256){
        int i = p >> 4, wd = p & 15;
        int j0 = 2*wd, j1 = 2*wd + 1;
        float v0 = (j0 < NND) ? __ldg(&att[i*NND + j0]) : 0.f;
        float v1 = (j1 < NND) ? __ldg(&att[i*NND + j1]) : 0.f;
        satth[i*20 + wd] = h2f(v0, v1);
    }
    for (int p = tid; p < 64*9; p += 256){
        int o = p / 9, wd = 11 + (p % 9);
        sdwT[o*20 + wd] = 0u;
    }
    for (int p = tid; p < 64*32; p += 256){
        int o = p >> 5, wd = p & 31;
        swdh[o*36 + wd] = h2f(g_Wt[4*4096 + o*64 + 2*wd], g_Wt[4*4096 + o*64 + 2*wd + 1]);
    }
    for (int p = tid; p < 2*(NND+1); p += 256) ssrp[(p/(NND+1))*23 + (p%(NND+1))] = g_rowptr[p/(NND+1)][p%(NND+1)];
    for (int p = tid; p < 2*NND*64; p += 256) sdiag[p] = g_diag[p/(NND*64)][p%(NND*64)];
    {
        int cnt0 = g_rowptr[0][NND]; if (cnt0 > OFFCAP0) cnt0 = OFFCAP0;
        int cnt1 = g_rowptr[1][NND]; if (cnt1 > OFFCAP1) cnt1 = OFFCAP1;
        for (int p = tid; p < cnt0*64; p += 256) soffv[p] = g_offv[0][p];
        for (int p = tid; p < cnt1*64; p += 256) soffv[OFFCAP0*64 + p] = g_offv[1][p];
        for (int p = tid; p < cnt0; p += 256) ssocol[p] = g_offcol[0][p];
        for (int p = tid; p < cnt1; p += 256) ssocol[OFFCAP0 + p] = g_offcol[1][p];
    }

    float2 bd = *(const float2*)&b_dis[o0];

    // prefetch first pair (704 float4)
    float4 xr0, xr1, xr2;
    {
        const float4* xg = (const float4*)(x + (size_t)(2*blockIdx.x)*SLICE);
        xr0 = __ldg(xg + tid);
        xr1 = __ldg(xg + tid + 256);
        xr2 = (tid < 192) ? __ldg(xg + tid + 512) : make_float4(0,0,0,0);
    }

    for (int iter = 0; iter < 6; iter++){
        int bt0, nsl;
        if (iter < 5){ bt0 = 2*(blockIdx.x + iter*PERSIST); nsl = 2; }
        else { bt0 = TAILBASE + blockIdx.x; if (bt0 >= NBT) break; nsl = 1; }

        __syncthreads();   // TOP: prior-iter readers of sx/sxh/sh1s retired

        // stage from prefetched regs (q0 always slice 0)
        {
            int i = tid >> 4, c = (tid & 15)*4;
            *(float4*)&sx[i*68 + c] = xr0;
            int w0 = c >> 1;
            sxh[i*XPH + POSW(w0    )] = h2f(xr0.x, xr0.y);
            sxh[i*XPH + POSW(w0 + 1)] = h2f(xr0.z, xr0.w);
        }
        {
            int q = tid + 256;
            if (q < nsl*352){
                int sl = (q >= 352); int qq = q - sl*352;
                int i = qq >> 4, c = (qq & 15)*4;
                *(float4*)&sx[sl*1496 + i*68 + c] = xr1;
                int w0 = c >> 1;
                sxh[sl*880 + i*XPH + POSW(w0    )] = h2f(xr1.x, xr1.y);
                sxh[sl*880 + i*XPH + POSW(w0 + 1)] = h2f(xr1.z, xr1.w);
            }
        }
        {
            int q = tid + 512;
            if (q < nsl*352){   // only possible when nsl==2 -> slice 1
                int qq = q - 352;
                int i = qq >> 4, c = (qq & 15)*4;
                *(float4*)&sx[1496 + i*68 + c] = xr2;
                int w0 = c >> 1;
                sxh[880 + i*XPH + POSW(w0    )] = h2f(xr2.x, xr2.y);
                sxh[880 + i*XPH + POSW(w0 + 1)] = h2f(xr2.z, xr2.w);
            }
        }
        // prefetch next iteration
        {
            int btn = 0, nsln = 0;
            if (iter < 4){ btn = 2*(blockIdx.x + (iter + 1)*PERSIST); nsln = 2; }
            else if (iter == 4){ btn = TAILBASE + blockIdx.x; nsln = (btn < NBT) ? 1 : 0; }
            if (nsln){
                const float4* xg = (const float4*)(x + (size_t)btn*SLICE);
                xr0 = __ldg(xg + tid);
                if (tid + 256 < nsln*352) xr1 = __ldg(xg + tid + 256);
                if (nsln == 2 && tid < 192) xr2 = __ldg(xg + tid + 512);
            }
        }
        __syncthreads();   // BAR1: stage done

        // S1/S2 partials (scratch = sh1s; per-slice layout identical to single-slice)
        {
            int r8 = (tid >> 6) & 3, ch = tid & 63;
            int rb = r8*6, re = rb + 6; if (re > NND) re = NND;
            float s1 = 0.f, s2 = 0.f;
            for (int i = rb; i < re; i++){
                float v = sx[i*68 + ch];
                s1 += v; s2 += v*v;
            }
            sh1s[r8*64 + ch]       = s1;
            sh1s[256 + r8*64 + ch] = s2;
            if (nsl == 2){
                float t1 = 0.f, t2 = 0.f;
                for (int i = rb; i < re; i++){
                    float v = sx[1496 + i*68 + ch];
                    t1 += v; t2 += v*v;
                }
                sh1s[512 + r8*64 + ch]       = t1;
                sh1s[512 + 256 + r8*64 + ch] = t2;
            }
        }
        __syncthreads();   // BAR2
        if (tid < 64*nsl){
            int sl = tid >> 6, ch = tid & 63;
            int b = sl*512;
            sS1[sl*64 + ch] = sh1s[b + ch] + sh1s[b + 64 + ch] + sh1s[b + 128 + ch] + sh1s[b + 192 + ch];
            sS2[sl*64 + ch] = sh1s[b + 256 + ch] + sh1s[b + 320 + ch] + sh1s[b + 384 + ch] + sh1s[b + 448 + ch];
        }
        __syncthreads();   // BAR3

        // dist (both slices)
        for (int t = tid; t < nsl*704; t += 256){
            int sl = (t >= 704); int tt = t - sl*704;
            int i = tt >> 5, wd = tt & 31;
            int c0 = 2*wd;
            float u0 = sx[sl*1496 + i*68 + c0], u1 = sx[sl*1496 + i*68 + c0 + 1];
            float d0 = sS2[sl*64 + c0    ] - 2.f*u0*sS1[sl*64 + c0    ] + (float)NND*u0*u0;
            float d1 = sS2[sl*64 + c0 + 1] - 2.f*u1*sS1[sl*64 + c0 + 1] + (float)NND*u1*u1;
            float v0 = sqrtf(fmaxf(d0, 0.f)) + 1e-8f;
            float v1 = sqrtf(fmaxf(d1, 0.f)) + 1e-8f;
            sdish[sl*880 + i*XPH + POSW(wd)] = h2f(v0, v1);
        }

        // per-slice compute: barrier-free, warp-local after BAR4
        for (int sl = 0; sl < nsl; sl++){
            const uint32* sxhp  = sxh + sl*880;
            const uint32* sdshp = sdish + sl*880;
            int bt = bt0 + sl;
            size_t obase = (size_t)bt*SLICE;

            // fused 4-weight x-gemm
            float hs0[4] = {0,0,0,0}, hs1[4] = {0,0,0,0};
            float es0[4] = {0,0,0,0}, es1[4] = {0,0,0,0};
            float hc0[4] = {0,0,0,0}, hc1[4] = {0,0,0,0};
            float ec0[4] = {0,0,0,0}, ec1[4] = {0,0,0,0};
#pragma unroll
            for (int k = 0; k < 4; k++){
                const uint32* p0 = sxhp + g*XPH + k*8 + 2*tig;
                uint2 va = *(const uint2*)p0;
                uint2 vb = *(const uint2*)(p0 + 8*XPH);
                uint2 vc = r2ok ? *(const uint2*)(p0 + 16*XPH) : make_uint2(0u, 0u);
                uint32 A0[4] = { va.x, vb.x, va.y, vb.y };
                uint32 A1[4] = { vc.x, 0u,   vc.y, 0u   };
                mma_f16(hs0, A0, bw0s[k]);  mma_f16(hs1, A1, bw0s[k]);
                mma_f16(es0, A0, bw1s[k]);  mma_f16(es1, A1, bw1s[k]);
                mma_f16(hc0, A0, bw0c[k]);  mma_f16(hc1, A1, bw0c[k]);
                mma_f16(ec0, A0, bw1c[k]);  mma_f16(ec1, A1, bw1c[k]);
            }
            if (sl == 0) __syncthreads();   // BAR4: dist writes visible block-wide
            __syncwarp();                   // sl=1: prior epilogue's sh1 reads retired (warp-local)

            sh1s[ g      *64 + o0    ] = es0[0];
            sh1s[ g      *64 + o0 + 1] = es0[1];
            sh1s[(g + 8) *64 + o0    ] = es0[2];
            sh1s[(g + 8) *64 + o0 + 1] = es0[3];
            sh1c[ g      *64 + o0    ] = ec0[0];
            sh1c[ g      *64 + o0 + 1] = ec0[1];
            sh1c[(g + 8) *64 + o0    ] = ec0[2];
            sh1c[(g + 8) *64 + o0 + 1] = ec0[3];
            if (r2ok){
                sh1s[(g + 16)*64 + o0    ] = es1[0];
                sh1s[(g + 16)*64 + o0 + 1] = es1[1];
                sh1c[(g + 16)*64 + o0    ] = ec1[0];
                sh1c[(g + 16)*64 + o0 + 1] = ec1[1];
            }
            __syncwarp();

            // mix epilogues
#pragma unroll
            for (int br = 0; br < 2; br++){
                const float* sh1 = br ? sh1c : sh1s;
                const int ob = br ? OFFCAP0 : 0;
                const int CAP = br ? ROWCAP1 : ROWCAP0;
                float su0 = 0.f, su1 = 0.f, sq0 = 0.f, sq1 = 0.f;
                int rr[3] = { g, g + 8, g + 16 };
                float va[3], vb[3];
                if (br == 0){ va[0]=hs0[0]; va[1]=hs0[2]; va[2]=hs1[0]; vb[0]=hs0[1]; vb[1]=hs0[3]; vb[2]=hs1[1]; }
                else        { va[0]=hc0[0]; va[1]=hc0[2]; va[2]=hc1[0]; vb[0]=hc0[1]; vb[1]=hc0[3]; vb[2]=hc1[1]; }
#pragma unroll
                for (int q = 0; q < 3; q++){
                    if (q == 2 && !r2ok) break;
                    int r = rr[q];
                    float2 dg = *(const float2*)&sdiag[br*(NND*64) + r*64 + o0];
                    float v0 = va[q]*dg.x, v1 = vb[q]*dg.y;
                    int mb = ssrp[br*23 + r], me = ssrp[br*23 + r + 1];
#pragma unroll
                    for (int m = 0; m < CAP; m++){
                        int idx = mb + m;
                        if (idx < me){
                            int cm = ssocol[ob + idx];
                            float2 ov = *(const float2*)&soffv[(ob + idx)*64 + o0];
                            v0 += ov.x * sh1[cm*64 + o0];
                            v1 += ov.y * sh1[cm*64 + o0 + 1];
                        }
                    }
                    __half2 sth = __floats2half2_rn(v0, v1);
                    if (br == 0) *(__half2*)&g_hbuf0h[obase + r*64 + o0] = sth;
                    else         *(__half2*)&g_hbuf1h[obase + r*64 + o0] = sth;
                    su0 += v0; su1 += v1; sq0 += v0*v0; sq1 += v1*v1;
                }
                su0 = redg(su0); su1 = redg(su1); sq0 = redg(sq0); sq1 = redg(sq1);
                if (lane < 4){
                    g_part1[(size_t)((2*br  )*64 + o0    )*NBT + bt] = su0;
                    g_part1[(size_t)((2*br  )*64 + o0 + 1)*NBT + bt] = su1;
                    g_part1[(size_t)((2*br+1)*64 + o0    )*NBT + bt] = sq0;
                    g_part1[(size_t)((2*br+1)*64 + o0 + 1)*NBT + bt] = sq1;
                }
            }

            // z branch (warp-local smem throughout)
            {
                float acc0[4] = {0,0,0,0}, acc1[4] = {0,0,0,0};
#pragma unroll
                for (int k = 0; k < 4; k++){
                    uint32 b[2];
                    b[0] = swdh[(n0 + g)*36 + k*8 + tig];
                    b[1] = swdh[(n0 + g)*36 + k*8 + tig + 4];
                    const uint32* p0 = sdshp + g*XPH + k*8 + 2*tig;
                    uint2 va = *(const uint2*)p0;
                    uint2 vb = *(const uint2*)(p0 + 8*XPH);
                    uint2 vc = r2ok ? *(const uint2*)(p0 + 16*XPH) : make_uint2(0u, 0u);
                    uint32 A0[4] = { va.x, vb.x, va.y, vb.y };
                    uint32 A1[4] = { vc.x, 0u,   vc.y, 0u   };
                    mma_f16(acc0, A0, b);
                    mma_f16(acc1, A1, b);
                }
                __syncwarp();
                {
                    __half* dwh = (__half*)sdwT;
                    dwh[ o0     *40 + g     ] = __float2half_rn(acc0[0]);
                    dwh[(o0 + 1)*40 + g     ] = __float2half_rn(acc0[1]);
                    dwh[ o0     *40 + g + 8 ] = __float2half_rn(acc0[2]);
                    dwh[(o0 + 1)*40 + g + 8 ] = __float2half_rn(acc0[3]);
                    if (r2ok){
                        dwh[ o0     *40 + g + 16] = __float2half_rn(acc1[0]);
                        dwh[(o0 + 1)*40 + g + 16] = __float2half_rn(acc1[1]);
                    }
                }
                __syncwarp();

                float az0[4] = {0,0,0,0}, az1[4] = {0,0,0,0};
#pragma unroll
                for (int k = 0; k < 2; k++){
                    uint32 A0[4], A1[4], bz[2];
                    A0[0] = satth[ g      *20 + k*8 + tig];
                    A0[1] = satth[(g + 8) *20 + k*8 + tig];
                    A0[2] = satth[ g      *20 + k*8 + tig + 4];
                    A0[3] = satth[(g + 8) *20 + k*8 + tig + 4];
                    A1[0] = r2ok ? satth[(g + 16)*20 + k*8 + tig] : 0u;
                    A1[1] = 0u;
                    A1[2] = r2ok ? satth[(g + 16)*20 + k*8 + tig + 4] : 0u;
                    A1[3] = 0u;
                    bz[0] = sdwT[(n0 + g)*20 + k*8 + tig];
                    bz[1] = sdwT[(n0 + g)*20 + k*8 + tig + 4];
                    mma_f16(az0, A0, bz);
                    mma_f16(az1, A1, bz);
                }
                float su0 = 0.f, su1 = 0.f, sq0 = 0.f, sq1 = 0.f;
                int rr[3] = { g, g + 8, g + 16 };
                float va[3] = { az0[0], az0[2], az1[0] };
                float vb[3] = { az0[1], az0[3], az1[1] };
#pragma unroll
                for (int q = 0; q < 3; q++){
                    if (q == 2 && !r2ok) break;
                    int r = rr[q];
                    float v0 = va[q] + bd.x, v1 = vb[q] + bd.y;
                    *(__half2*)&g_hbuf2h[obase + r*64 + o0] = __floats2half2_rn(v0, v1);
                    su0 += v0; su1 += v1; sq0 += v0*v0; sq1 += v1*v1;
                }
                su0 = redg(su0); su1 = redg(su1); sq0 = redg(sq0); sq1 = redg(sq1);
                if (lane < 4){
                    g_part1[(size_t)(4*64 + o0    )*NBT + bt] = su0;
                    g_part1[(size_t)(4*64 + o0 + 1)*NBT + bt] = su1;
                    g_part1[(size_t)(5*64 + o0    )*NBT + bt] = sq0;
                    g_part1[(size_t)(5*64 + o0 + 1)*NBT + bt] = sq1;
                }
            }
        }
    }
}

// ---------------- BN stats finalize (unchanged) ----------------
__global__ void k_finalize(int which, const float* __restrict__ gammas,
                           const float* __restrict__ betas)
{
    int ch = blockIdx.x, tid = threadIdx.x;
    int b = ch >> 6, o = ch & 63;
    const float* part = which ? g_part2 : g_part1;
    const float* psum = part + (size_t)((2*b  )*64 + o) * NBT;
    const float* psq  = part + (size_t)((2*b+1)*64 + o) * NBT;
    __shared__ float r1[256], r2[256];
    float s = 0.f, q = 0.f;
    for (int t = tid; t < NBT; t += 256){ s += psum[t]; q += psq[t]; }
    r1[tid] = s; r2[tid] = q;
    __syncthreads();
    for (int off = 128; off; off >>= 1){
        if (tid < off){ r1[tid] += r1[tid+off]; r2[tid] += r2[tid+off]; }
        __syncthreads();
    }
    if (tid == 0){
        const float invM = 1.f / 70400.f;
        float mu  = r1[0]*invM;
        float var = r2[0]*invM - mu*mu;
        int grow = which ? 3 : b;
        float g  = gammas[grow*64 + o], be = betas[grow*64 + o];
        float sc = g * rsqrtf(var + 1e-5f);
        if (which){ g_scale2[o]  = sc; g_shift2[o]  = be - mu*sc; }
        else      { g_scale1[ch] = sc; g_shift1[ch] = be - mu*sc; }
    }
}

// ---------------- k_cat: fp16 mma, 128 threads / 4 warps / 2 n-tiles ----------------
__global__ __launch_bounds__(128) void k_cat(const float* __restrict__ cat_w)
{
    __shared__ __align__(16) uint32 scat[2][NND*CPH];
    __shared__ float ssc[192], ssh[192];

    int tid = threadIdx.x;
    int lane = tid & 31, w = tid >> 5;
    int g = lane >> 2, tig = lane & 3;
    int n0 = w*16;
    int oA = n0 + 2*tig;
    int oB = oA + 8;
    int r2ok = (g + 16) < NND;

    uint32 bc[12][4];
#pragma unroll
    for (int k = 0; k < 12; k++){
        const float* wp0 = cat_w + (n0 + g)*192 + k*16 + 2*tig;
        const float* wp1 = cat_w + (n0 + 8 + g)*192 + k*16 + 2*tig;
        bc[k][0] = h2g(wp0); bc[k][1] = h2g(wp0 + 8);
        bc[k][2] = h2g(wp1); bc[k][3] = h2g(wp1 + 8);
    }
    for (int p = tid; p < 192; p += 128){ ssc[p] = g_scale1[p]; ssh[p] = g_shift1[p]; }

    uint4 pf[5];
#pragma unroll
    for (int k = 0; k < 5; k++){
        int f = tid + k*128;
        if (f < 528){
            int buf = f / 176, p = f % 176;
            const __half* hb = (buf == 0) ? g_hbuf0h : ((buf == 1) ? g_hbuf1h : g_hbuf2h);
            pf[k] = __ldg((const uint4*)(hb + (size_t)(blockIdx.x*SPB_CAT)*SLICE) + p);
        }
    }
    __syncthreads();

    for (int s = 0; s < SPB_CAT; s++){
        int bt = blockIdx.x*SPB_CAT + s;
        int cur = s & 1;

#pragma unroll
        for (int k = 0; k < 5; k++){
            int f = tid + k*128;
            if (f < 528){
                int buf = f / 176, p = f % 176;
                int i = p >> 3, c = (p & 7)*8;
                int fc = buf*64 + c;
                int w0 = fc >> 1;
                uint32 hw[4] = { pf[k].x, pf[k].y, pf[k].z, pf[k].w };
#pragma unroll
                for (int hh = 0; hh < 4; hh++){
                    float2 fv = __half22float2(*reinterpret_cast<__half2*>(&hw[hh]));
                    float r0 = fmaxf(fv.x*ssc[fc + 2*hh    ] + ssh[fc + 2*hh    ], 0.f);
                    float r1 = fmaxf(fv.y*ssc[fc + 2*hh + 1] + ssh[fc + 2*hh + 1], 0.f);
                    scat[cur][i*CPH + POSW(w0 + hh)] = h2f(r0, r1);
                }
            }
        }
        if (s + 1 < SPB_CAT){
#pragma unroll
            for (int k = 0; k < 5; k++){
                int f = tid + k*128;
                if (f < 528){
                    int buf = f / 176, p = f % 176;
                    const __half* hb = (buf == 0) ? g_hbuf0h : ((buf == 1) ? g_hbuf1h : g_hbuf2h);
                    pf[k] = __ldg((const uint4*)(hb + (size_t)(bt + 1)*SLICE) + p);
                }
            }
        }
        __syncthreads();

        const uint32* sc = scat[cur];
        float a0A[4] = {0,0,0,0}, a1A[4] = {0,0,0,0};
        float a0B[4] = {0,0,0,0}, a1B[4] = {0,0,0,0};
#pragma unroll
        for (int k = 0; k < 12; k++){
            const uint32* p0 = sc + g*CPH + k*8 + 2*tig;
            uint2 va = *(const uint2*)p0;
            uint2 vb = *(const uint2*)(p0 + 8*CPH);
            uint2 vc = r2ok ? *(const uint2*)(p0 + 16*CPH) : make_uint2(0u, 0u);
            uint32 A0[4] = { va.x, vb.x, va.y, vb.y };
            uint32 A1[4] = { vc.x, 0u,   vc.y, 0u   };
            uint32 b0[2] = { bc[k][0], bc[k][1] };
            uint32 b1[2] = { bc[k][2], bc[k][3] };
            mma_f16(a0A, A0, b0);  mma_f16(a1A, A1, b0);
            mma_f16(a0B, A0, b1);  mma_f16(a1B, A1, b1);
        }

        float suA0=0.f, suA1=0.f, sqA0=0.f, sqA1=0.f;
        float suB0=0.f, suB1=0.f, sqB0=0.f, sqB1=0.f;
        int rr[3] = { g, g + 8, g + 16 };
        float vaA[3] = { a0A[0], a0A[2], a1A[0] };
        float vbA[3] = { a0A[1], a0A[3], a1A[1] };
        float vaB[3] = { a0B[0], a0B[2], a1B[0] };
        float vbB[3] = { a0B[1], a0B[3], a1B[1] };
        size_t obase = (size_t)bt*SLICE;
#pragma unroll
        for (int q = 0; q < 3; q++){
            if (q == 2 && !r2ok) break;
            int r = rr[q];
            float v0 = vaA[q], v1 = vbA[q], v2 = vaB[q], v3 = vbB[q];
            *(__half2*)&g_pre2h[obase + r*64 + oA] = __floats2half2_rn(v0, v1);
            *(__half2*)&g_pre2h[obase + r*64 + oB] = __floats2half2_rn(v2, v3);
            suA0 += v0; suA1 += v1; sqA0 += v0*v0; sqA1 += v1*v1;
            suB0 += v2; suB1 += v3; sqB0 += v2*v2; sqB1 += v3*v3;
        }
        suA0 = redg(suA0); suA1 = redg(suA1); sqA0 = redg(sqA0); sqA1 = redg(sqA1);
        suB0 = redg(suB0); suB1 = redg(suB1); sqB0 = redg(sqB0); sqB1 = redg(sqB1);
        if (lane < 4){
            g_part2[(size_t)(oA    )*NBT + bt] = suA0;
            g_part2[(size_t)(oA + 1)*NBT + bt] = suA1;
            g_part2[(size_t)(oB    )*NBT + bt] = suB0;
            g_part2[(size_t)(oB + 1)*NBT + bt] = suB1;
            g_part2[(size_t)(64 + oA    )*NBT + bt] = sqA0;
            g_part2[(size_t)(64 + oA + 1)*NBT + bt] = sqA1;
            g_part2[(size_t)(64 + oB    )*NBT + bt] = sqB0;
            g_part2[(size_t)(64 + oB + 1)*NBT + bt] = sqB1;
        }
    }
}

// ---------------- final BN+ReLU elementwise (fp16 in, fp32 out) ----------------
__global__ void k_out(float* __restrict__ out)
{
    size_t idx8 = (size_t)blockIdx.x*256 + threadIdx.x;
    if (idx8 < TOT/8){
        uint4 v = reinterpret_cast<const uint4*>(g_pre2h)[idx8];
        int ob = (int)((idx8*8) & 63);
        uint32 hw[4] = { v.x, v.y, v.z, v.w };
        float4 o0, o1;
        float2 f0 = __half22float2(*reinterpret_cast<__half2*>(&hw[0]));
        float2 f1 = __half22float2(*reinterpret_cast<__half2*>(&hw[1]));
        float2 f2 = __half22float2(*reinterpret_cast<__half2*>(&hw[2]));
        float2 f3 = __half22float2(*reinterpret_cast<__half2*>(&hw[3]));
        o0.x = fmaxf(f0.x*g_scale2[ob  ] + g_shift2[ob  ], 0.f);
        o0.y = fmaxf(f0.y*g_scale2[ob+1] + g_shift2[ob+1], 0.f);
        o0.z = fmaxf(f1.x*g_scale2[ob+2] + g_shift2[ob+2], 0.f);
        o0.w = fmaxf(f1.y*g_scale2[ob+3] + g_shift2[ob+3], 0.f);
        o1.x = fmaxf(f2.x*g_scale2[ob+4] + g_shift2[ob+4], 0.f);
        o1.y = fmaxf(f2.y*g_scale2[ob+5] + g_shift2[ob+5], 0.f);
        o1.z = fmaxf(f3.x*g_scale2[ob+6] + g_shift2[ob+6], 0.f);
        o1.w = fmaxf(f3.y*g_scale2[ob+7] + g_shift2[ob+7], 0.f);
        reinterpret_cast<float4*>(out)[idx8*2    ] = o0;
        reinterpret_cast<float4*>(out)[idx8*2 + 1] = o1;
    }
}

// ---------------- launch ----------------
#define KMAIN_SMEM_BYTES (24792*4)

extern "C" void kernel_launch(void* const* d_in, const int* in_sizes, int n_in,
                              void* d_out, int out_size)
{
    const float* x        = (const float*)d_in[0];
    const float* W_sym    = (const float*)d_in[1];
    const float* e_sym    = (const float*)d_in[2];
    const float* W_con    = (const float*)d_in[3];
    const float* e_con    = (const float*)d_in[4];
    const float* W_dis    = (const float*)d_in[5];
    const float* att      = (const float*)d_in[6];
    const float* b_dis    = (const float*)d_in[7];
    const float* cat_w    = (const float*)d_in[8];
    const float* gammas   = (const float*)d_in[9];
    const float* betas    = (const float*)d_in[10];
    const int*   rows_sym = (const int*)d_in[11];
    const int*   cols_sym = (const int*)d_in[12];
    const int*   rows_con = (const int*)d_in[13];
    const int*   cols_con = (const int*)d_in[14];
    int nnz_sym = in_sizes[11];
    int nnz_con = in_sizes[13];

    static int configured = 0;
    if (!configured){
        cudaFuncSetAttribute(k_main, cudaFuncAttributeMaxDynamicSharedMemorySize, KMAIN_SMEM_BYTES);
        configured = 1;
    }

    k_prep<<<3, 256>>>(e_sym, rows_sym, cols_sym, nnz_sym,
                       e_con, rows_con, cols_con, nnz_con,
                       W_sym, W_con, W_dis);
    k_main<<<PERSIST, 256, KMAIN_SMEM_BYTES>>>(x, att, b_dis);
    k_finalize<<<192, 256>>>(0, gammas, betas);
    k_cat<<<GRID_CAT, 128>>>(cat_w);
    k_finalize<<<64, 256>>>(1, gammas, betas);
    k_out<<<(TOT/8 + 255)/256, 256>>>((float*)d_out);
    (void)n_in; (void)out_size;
}

// round 17
// speedup vs baseline: 1.7865x; 1.0029x over previous
#include <cuda_runtime.h>
#include <cuda_fp16.h>
#include <cstdint>

typedef unsigned int uint32;

#define NBT   3200
#define NND   22
#define NCH   64
#define SLICE (NND*NCH)
#define TOT   (NBT*SLICE)
#define MAXNZ 484
#define PERSIST 296         // 148 SMs x 2 blocks
#define TAILBASE 2960
#define SPB_CAT 8
#define GRID_CAT (NBT/SPB_CAT)
#define OFFCAP0 32
#define OFFCAP1 96
#define ROWCAP0 1           // adj_sym: jl/jr disjoint -> <=1 off-diag per row
#define ROWCAP1 6
#define XPH   40            // b32-word pitch of half2 x/dist buffers (40 mod 32 = 8)
#define CPH   104
#define POSW(w) (((w) & ~7) + 2*((w) & 3) + (((w) >> 2) & 1))

// ---------------- device scratch ----------------
__device__ __half g_hbuf0h[TOT];
__device__ __half g_hbuf1h[TOT];
__device__ __half g_hbuf2h[TOT];
__device__ __half g_pre2h[TOT];
__device__ float g_part1[6*64*NBT];
__device__ float g_part2[2*64*NBT];
__device__ float g_scale1[192], g_shift1[192];
__device__ float g_scale2[64],  g_shift2[64];
__device__ float g_Wt[5*4096];          // [g][o][c]
__device__ float g_diag[2][NND*NCH];
__device__ float g_offv[2][MAXNZ*NCH];
__device__ int   g_offcol[2][MAXNZ];
__device__ int   g_rowptr[2][NND+1];

// ---------------- helpers ----------------
__device__ __forceinline__ uint32 h2f(float a, float b){
    __half2 h = __floats2half2_rn(a, b);
    return *reinterpret_cast<uint32*>(&h);
}
__device__ __forceinline__ uint32 h2g(const float* __restrict__ p){
    return h2f(__ldg(p), __ldg(p + 1));
}
__device__ __forceinline__ void mma_f16(float c[4], const uint32 a[4], const uint32 b[2]){
    asm volatile("mma.sync.aligned.m16n8k16.row.col.f32.f16.f16.f32 "
                 "{%0,%1,%2,%3}, {%4,%5,%6,%7}, {%8,%9}, {%0,%1,%2,%3};"
                 : "+f"(c[0]), "+f"(c[1]), "+f"(c[2]), "+f"(c[3])
                 : "r"(a[0]), "r"(a[1]), "r"(a[2]), "r"(a[3]),
                   "r"(b[0]), "r"(b[1]));
}
__device__ __forceinline__ float redg(float v){
    v += __shfl_down_sync(0xffffffffu, v, 16);
    v += __shfl_down_sync(0xffffffffu, v, 8);
    v += __shfl_down_sync(0xffffffffu, v, 4);
    return v;
}

// ---------------- prep: parallel softmax adjacency construction (proven) ----------------
__global__ void k_prep(const float* __restrict__ e_sym, const int* __restrict__ rows_sym,
                       const int* __restrict__ cols_sym, int nnz_sym,
                       const float* __restrict__ e_con, const int* __restrict__ rows_con,
                       const int* __restrict__ cols_con, int nnz_con,
                       const float* __restrict__ W_sym, const float* __restrict__ W_con,
                       const float* __restrict__ W_dis)
{
    int blk = blockIdx.x, tid = threadIdx.x;
    if (blk == 2){
        for (int p = tid; p < 5*4096; p += 256){
            int g = p >> 12, rem = p & 4095, c = rem >> 6, o = rem & 63;
            float v;
            if (g < 2)      v = W_sym[g*4096 + c*64 + o];
            else if (g < 4) v = W_con[(g-2)*4096 + c*64 + o];
            else            v = W_dis[c*64 + o];
            g_Wt[g*4096 + o*64 + c] = v;
        }
        return;
    }
    int br = blk;
    const float* e  = br ? e_con   : e_sym;
    const int* rows = br ? rows_con : rows_sym;
    const int* cols = br ? cols_con : cols_sym;
    int nnz         = br ? nnz_con : nnz_sym;

    __shared__ int   srows[512], scols[512], sscan[512];
    __shared__ int   srs[NND+1];
    __shared__ float sden[NND*NCH];

    for (int p = tid; p < 512; p += 256){
        int r = (p < nnz) ? rows[p] : 0x7fffffff;
        int c = (p < nnz) ? cols[p] : 0x7fffffff;
        srows[p] = r; scols[p] = c;
        sscan[p] = (p < nnz && r != c) ? 1 : 0;
    }
    for (int p = tid; p < NND*NCH; p += 256) g_diag[br][p] = 0.f;
    __syncthreads();

    if (tid < 32){
        int carry = 0;
        for (int base = 0; base < 512; base += 32){
            int v = sscan[base + tid];
#pragma unroll
            for (int d = 1; d < 32; d <<= 1){
                int t = __shfl_up_sync(0xffffffffu, v, d);
                if (tid >= d) v += t;
            }
            sscan[base + tid] = v + carry;
            carry += __shfl_sync(0xffffffffu, v, 31);
        }
    }
    __syncthreads();

    for (int p = tid; p < nnz; p += 256)
        if (srows[p] != scols[p]) g_offcol[br][sscan[p] - 1] = scols[p];

    for (int p = tid; p <= NND; p += 256){
        int cntoff = 0, cntall = 0;
        for (int k = 0; k < nnz; k++){
            int ro = srows[k];
            cntall += (ro < p);
            cntoff += (ro < p && ro != scols[k]);
        }
        g_rowptr[br][p] = cntoff;
        srs[p] = cntall;
    }
    __syncthreads();

    for (int p = tid; p < NND*NCH; p += 256){
        int i = p >> 6, o = p & 63;
        float s = 0.f;
        int kb = srs[i], ke = srs[i+1];
        for (int k = kb; k < ke; k++) s += expf(e[o*nnz + k]);
        sden[p] = s;
    }
    __syncthreads();

    for (int p = tid; p < 64*nnz; p += 256){
        int k = p >> 6, o = p & 63;
        int r = srows[k];
        float v = expf(e[o*nnz + k]) / sden[r*64 + o];
        if (r != scols[k]) g_offv[br][(sscan[k] - 1)*64 + o] = v;
        else               g_diag[br][r*64 + o] = v;
    }
}

// ---------------- main fused kernel: persistent, pair-packed, 4 barriers/pair ----------------
__global__ __launch_bounds__(256, 2) void k_main(const float* __restrict__ x,
                                                 const float* __restrict__ att,
                                                 const float* __restrict__ b_dis)
{
    extern __shared__ __align__(16) float smem_[];
    float*  sx    = smem_;                         // 2992 (2 x 22x68)
    uint32* sxh   = (uint32*)(sx + 2992);          // 1760 (2 x 880)
    uint32* sdish = sxh + 1760;                    // 1760
    float*  sh1s  = (float*)(sdish + 1760);        // 1408
    float*  sh1c  = sh1s + 1408;                   // 1408
    uint32* sdwT  = (uint32*)(sh1c + 1408);        // 1280
    uint32* satth = sdwT + 1280;                   // 440
    float*  sdiag = (float*)(satth + 440);         // 2816
    float*  soffv = sdiag + 2816;                  // 8192
    int*    ssrp  = (int*)(soffv + 8192);          // 48
    int*    ssocol= ssrp + 48;                     // 128
    float*  sS1   = (float*)(ssocol + 128);        // 128 (2x64)
    float*  sS2   = sS1 + 128;                     // 128
    uint32* swdh  = (uint32*)(sS2 + 128);          // 2304

    int tid = threadIdx.x;
    int lane = tid & 31, w = tid >> 5;
    int g = lane >> 2, tig = lane & 3;
    int n0 = w*8;
    int o0 = n0 + 2*tig;
    int r2ok = (g + 16) < NND;

    uint32 bw0s[4][2], bw1s[4][2], bw0c[4][2], bw1c[4][2];
#pragma unroll
    for (int k = 0; k < 4; k++){
        const float* w0 = g_Wt + 0*4096 + (n0 + g)*64 + k*16 + 2*tig;
        const float* w1 = g_Wt + 1*4096 + (n0 + g)*64 + k*16 + 2*tig;
        const float* w2 = g_Wt + 2*4096 + (n0 + g)*64 + k*16 + 2*tig;
        const float* w3 = g_Wt + 3*4096 + (n0 + g)*64 + k*16 + 2*tig;
        bw0s[k][0] = h2g(w0); bw0s[k][1] = h2g(w0 + 8);
        bw1s[k][0] = h2g(w1); bw1s[k][1] = h2g(w1 + 8);
        bw0c[k][0] = h2g(w2); bw0c[k][1] = h2g(w2 + 8);
        bw1c[k][0] = h2g(w3); bw1c[k][1] = h2g(w3 + 8);
    }

    // ---- block-constant staging ----
    for (int p = tid; p < NND*16; p += 256){
        int i = p >> 4, wd = p & 15;
        int j0 = 2*wd, j1 = 2*wd + 1;
        float v0 = (j0 < NND) ? __ldg(&att[i*NND + j0]) : 0.f;
        float v1 = (j1 < NND) ? __ldg(&att[i*NND + j1]) : 0.f;
        satth[i*20 + wd] = h2f(v0, v1);
    }
    for (int p = tid; p < 64*9; p += 256){
        int o = p / 9, wd = 11 + (p % 9);
        sdwT[o*20 + wd] = 0u;
    }
    for (int p = tid; p < 64*32; p += 256){
        int o = p >> 5, wd = p & 31;
        swdh[o*36 + wd] = h2f(g_Wt[4*4096 + o*64 + 2*wd], g_Wt[4*4096 + o*64 + 2*wd + 1]);
    }
    for (int p = tid; p < 2*(NND+1); p += 256) ssrp[(p/(NND+1))*23 + (p%(NND+1))] = g_rowptr[p/(NND+1)][p%(NND+1)];
    for (int p = tid; p < 2*NND*64; p += 256) sdiag[p] = g_diag[p/(NND*64)][p%(NND*64)];
    {
        int cnt0 = g_rowptr[0][NND]; if (cnt0 > OFFCAP0) cnt0 = OFFCAP0;
        int cnt1 = g_rowptr[1][NND]; if (cnt1 > OFFCAP1) cnt1 = OFFCAP1;
        for (int p = tid; p < cnt0*64; p += 256) soffv[p] = g_offv[0][p];
        for (int p = tid; p < cnt1*64; p += 256) soffv[OFFCAP0*64 + p] = g_offv[1][p];
        for (int p = tid; p < cnt0; p += 256) ssocol[p] = g_offcol[0][p];
        for (int p = tid; p < cnt1; p += 256) ssocol[OFFCAP0 + p] = g_offcol[1][p];
    }

    float2 bd = *(const float2*)&b_dis[o0];

    // prefetch first pair (704 float4)
    float4 xr0, xr1, xr2;
    {
        const float4* xg = (const float4*)(x + (size_t)(2*blockIdx.x)*SLICE);
        xr0 = __ldg(xg + tid);
        xr1 = __ldg(xg + tid + 256);
        xr2 = (tid < 192) ? __ldg(xg + tid + 512) : make_float4(0,0,0,0);
    }

    for (int iter = 0; iter < 6; iter++){
        int bt0, nsl;
        if (iter < 5){ bt0 = 2*(blockIdx.x + iter*PERSIST); nsl = 2; }
        else { bt0 = TAILBASE + blockIdx.x; if (bt0 >= NBT) break; nsl = 1; }

        __syncthreads();   // TOP: prior-iter readers of sxh/sdish retired

        // stage from prefetched regs
        {
            int i = tid >> 4, c = (tid & 15)*4;
            *(float4*)&sx[i*68 + c] = xr0;
            int w0 = c >> 1;
            sxh[i*XPH + POSW(w0    )] = h2f(xr0.x, xr0.y);
            sxh[i*XPH + POSW(w0 + 1)] = h2f(xr0.z, xr0.w);
        }
        {
            int q = tid + 256;
            if (q < nsl*352){
                int sl = (q >= 352); int qq = q - sl*352;
                int i = qq >> 4, c = (qq & 15)*4;
                *(float4*)&sx[sl*1496 + i*68 + c] = xr1;
                int w0 = c >> 1;
                sxh[sl*880 + i*XPH + POSW(w0    )] = h2f(xr1.x, xr1.y);
                sxh[sl*880 + i*XPH + POSW(w0 + 1)] = h2f(xr1.z, xr1.w);
            }
        }
        {
            int q = tid + 512;
            if (q < nsl*352){
                int qq = q - 352;
                int i = qq >> 4, c = (qq & 15)*4;
                *(float4*)&sx[1496 + i*68 + c] = xr2;
                int w0 = c >> 1;
                sxh[880 + i*XPH + POSW(w0    )] = h2f(xr2.x, xr2.y);
                sxh[880 + i*XPH + POSW(w0 + 1)] = h2f(xr2.z, xr2.w);
            }
        }
        // prefetch next iteration
        {
            int btn = 0, nsln = 0;
            if (iter < 4){ btn = 2*(blockIdx.x + (iter + 1)*PERSIST); nsln = 2; }
            else if (iter == 4){ btn = TAILBASE + blockIdx.x; nsln = (btn < NBT) ? 1 : 0; }
            if (nsln){
                const float4* xg = (const float4*)(x + (size_t)btn*SLICE);
                xr0 = __ldg(xg + tid);
                if (tid + 256 < nsln*352) xr1 = __ldg(xg + tid + 256);
                if (nsln == 2 && tid < 192) xr2 = __ldg(xg + tid + 512);
            }
        }
        __syncthreads();   // BAR1: stage done

        // S1/S2: single phase, one thread per (slice, channel), serial 22-row sum
        if (tid < 64*nsl){
            int sl = tid >> 6, ch = tid & 63;
            const float* sxp = sx + sl*1496;
            float s1 = 0.f, s2 = 0.f;
#pragma unroll
            for (int i = 0; i < NND; i++){
                float v = sxp[i*68 + ch];
                s1 += v; s2 += v*v;
            }
            sS1[sl*64 + ch] = s1;
            sS2[sl*64 + ch] = s2;
        }
        __syncthreads();   // BAR2: S1/S2 done

        // dist (both slices)
        for (int t = tid; t < nsl*704; t += 256){
            int sl = (t >= 704); int tt = t - sl*704;
            int i = tt >> 5, wd = tt & 31;
            int c0 = 2*wd;
            float u0 = sx[sl*1496 + i*68 + c0], u1 = sx[sl*1496 + i*68 + c0 + 1];
            float d0 = sS2[sl*64 + c0    ] - 2.f*u0*sS1[sl*64 + c0    ] + (float)NND*u0*u0;
            float d1 = sS2[sl*64 + c0 + 1] - 2.f*u1*sS1[sl*64 + c0 + 1] + (float)NND*u1*u1;
            float v0 = sqrtf(fmaxf(d0, 0.f)) + 1e-8f;
            float v1 = sqrtf(fmaxf(d1, 0.f)) + 1e-8f;
            sdish[sl*880 + i*XPH + POSW(wd)] = h2f(v0, v1);
        }

        // per-slice compute: barrier-free, warp-local after BAR4
        for (int sl = 0; sl < nsl; sl++){
            const uint32* sxhp  = sxh + sl*880;
            const uint32* sdshp = sdish + sl*880;
            int bt = bt0 + sl;
            size_t obase = (size_t)bt*SLICE;

            // fused 4-weight x-gemm
            float hs0[4] = {0,0,0,0}, hs1[4] = {0,0,0,0};
            float es0[4] = {0,0,0,0}, es1[4] = {0,0,0,0};
            float hc0[4] = {0,0,0,0}, hc1[4] = {0,0,0,0};
            float ec0[4] = {0,0,0,0}, ec1[4] = {0,0,0,0};
#pragma unroll
            for (int k = 0; k < 4; k++){
                const uint32* p0 = sxhp + g*XPH + k*8 + 2*tig;
                uint2 va = *(const uint2*)p0;
                uint2 vb = *(const uint2*)(p0 + 8*XPH);
                uint2 vc = r2ok ? *(const uint2*)(p0 + 16*XPH) : make_uint2(0u, 0u);
                uint32 A0[4] = { va.x, vb.x, va.y, vb.y };
                uint32 A1[4] = { vc.x, 0u,   vc.y, 0u   };
                mma_f16(hs0, A0, bw0s[k]);  mma_f16(hs1, A1, bw0s[k]);
                mma_f16(es0, A0, bw1s[k]);  mma_f16(es1, A1, bw1s[k]);
                mma_f16(hc0, A0, bw0c[k]);  mma_f16(hc1, A1, bw0c[k]);
                mma_f16(ec0, A0, bw1c[k]);  mma_f16(ec1, A1, bw1c[k]);
            }
            if (sl == 0) __syncthreads();   // BAR4: dist writes visible block-wide
            __syncwarp();                   // sl=1: prior epilogue's sh1 reads retired (warp-local)

            sh1s[ g      *64 + o0    ] = es0[0];
            sh1s[ g      *64 + o0 + 1] = es0[1];
            sh1s[(g + 8) *64 + o0    ] = es0[2];
            sh1s[(g + 8) *64 + o0 + 1] = es0[3];
            sh1c[ g      *64 + o0    ] = ec0[0];
            sh1c[ g      *64 + o0 + 1] = ec0[1];
            sh1c[(g + 8) *64 + o0    ] = ec0[2];
            sh1c[(g + 8) *64 + o0 + 1] = ec0[3];
            if (r2ok){
                sh1s[(g + 16)*64 + o0    ] = es1[0];
                sh1s[(g + 16)*64 + o0 + 1] = es1[1];
                sh1c[(g + 16)*64 + o0    ] = ec1[0];
                sh1c[(g + 16)*64 + o0 + 1] = ec1[1];
            }
            __syncwarp();

            // mix epilogues
#pragma unroll
            for (int br = 0; br < 2; br++){
                const float* sh1 = br ? sh1c : sh1s;
                const int ob = br ? OFFCAP0 : 0;
                const int CAP = br ? ROWCAP1 : ROWCAP0;
                float su0 = 0.f, su1 = 0.f, sq0 = 0.f, sq1 = 0.f;
                int rr[3] = { g, g + 8, g + 16 };
                float va[3], vb[3];
                if (br == 0){ va[0]=hs0[0]; va[1]=hs0[2]; va[2]=hs1[0]; vb[0]=hs0[1]; vb[1]=hs0[3]; vb[2]=hs1[1]; }
                else        { va[0]=hc0[0]; va[1]=hc0[2]; va[2]=hc1[0]; vb[0]=hc0[1]; vb[1]=hc0[3]; vb[2]=hc1[1]; }
#pragma unroll
                for (int q = 0; q < 3; q++){
                    if (q == 2 && !r2ok) break;
                    int r = rr[q];
                    float2 dg = *(const float2*)&sdiag[br*(NND*64) + r*64 + o0];
                    float v0 = va[q]*dg.x, v1 = vb[q]*dg.y;
                    int mb = ssrp[br*23 + r], me = ssrp[br*23 + r + 1];
#pragma unroll
                    for (int m = 0; m < CAP; m++){
                        int idx = mb + m;
                        if (idx < me){
                            int cm = ssocol[ob + idx];
                            float2 ov = *(const float2*)&soffv[(ob + idx)*64 + o0];
                            v0 += ov.x * sh1[cm*64 + o0];
                            v1 += ov.y * sh1[cm*64 + o0 + 1];
                        }
                    }
                    __half2 sth = __floats2half2_rn(v0, v1);
                    if (br == 0) *(__half2*)&g_hbuf0h[obase + r*64 + o0] = sth;
                    else         *(__half2*)&g_hbuf1h[obase + r*64 + o0] = sth;
                    su0 += v0; su1 += v1; sq0 += v0*v0; sq1 += v1*v1;
                }
                su0 = redg(su0); su1 = redg(su1); sq0 = redg(sq0); sq1 = redg(sq1);
                if (lane < 4){
                    g_part1[(size_t)((2*br  )*64 + o0    )*NBT + bt] = su0;
                    g_part1[(size_t)((2*br  )*64 + o0 + 1)*NBT + bt] = su1;
                    g_part1[(size_t)((2*br+1)*64 + o0    )*NBT + bt] = sq0;
                    g_part1[(size_t)((2*br+1)*64 + o0 + 1)*NBT + bt] = sq1;
                }
            }

            // z branch (warp-local smem throughout)
            {
                float acc0[4] = {0,0,0,0}, acc1[4] = {0,0,0,0};
#pragma unroll
                for (int k = 0; k < 4; k++){
                    uint32 b[2];
                    b[0] = swdh[(n0 + g)*36 + k*8 + tig];
                    b[1] = swdh[(n0 + g)*36 + k*8 + tig + 4];
                    const uint32* p0 = sdshp + g*XPH + k*8 + 2*tig;
                    uint2 va = *(const uint2*)p0;
                    uint2 vb = *(const uint2*)(p0 + 8*XPH);
                    uint2 vc = r2ok ? *(const uint2*)(p0 + 16*XPH) : make_uint2(0u, 0u);
                    uint32 A0[4] = { va.x, vb.x, va.y, vb.y };
                    uint32 A1[4] = { vc.x, 0u,   vc.y, 0u   };
                    mma_f16(acc0, A0, b);
                    mma_f16(acc1, A1, b);
                }
                __syncwarp();
                {
                    __half* dwh = (__half*)sdwT;
                    dwh[ o0     *40 + g     ] = __float2half_rn(acc0[0]);
                    dwh[(o0 + 1)*40 + g     ] = __float2half_rn(acc0[1]);
                    dwh[ o0     *40 + g + 8 ] = __float2half_rn(acc0[2]);
                    dwh[(o0 + 1)*40 + g + 8 ] = __float2half_rn(acc0[3]);
                    if (r2ok){
                        dwh[ o0     *40 + g + 16] = __float2half_rn(acc1[0]);
                        dwh[(o0 + 1)*40 + g + 16] = __float2half_rn(acc1[1]);
                    }
                }
                __syncwarp();

                float az0[4] = {0,0,0,0}, az1[4] = {0,0,0,0};
#pragma unroll
                for (int k = 0; k < 2; k++){
                    uint32 A0[4], A1[4], bz[2];
                    A0[0] = satth[ g      *20 + k*8 + tig];
                    A0[1] = satth[(g + 8) *20 + k*8 + tig];
                    A0[2] = satth[ g      *20 + k*8 + tig + 4];
                    A0[3] = satth[(g + 8) *20 + k*8 + tig + 4];
                    A1[0] = r2ok ? satth[(g + 16)*20 + k*8 + tig] : 0u;
                    A1[1] = 0u;
                    A1[2] = r2ok ? satth[(g + 16)*20 + k*8 + tig + 4] : 0u;
                    A1[3] = 0u;
                    bz[0] = sdwT[(n0 + g)*20 + k*8 + tig];
                    bz[1] = sdwT[(n0 + g)*20 + k*8 + tig + 4];
                    mma_f16(az0, A0, bz);
                    mma_f16(az1, A1, bz);
                }
                float su0 = 0.f, su1 = 0.f, sq0 = 0.f, sq1 = 0.f;
                int rr[3] = { g, g + 8, g + 16 };
                float va[3] = { az0[0], az0[2], az1[0] };
                float vb[3] = { az0[1], az0[3], az1[1] };
#pragma unroll
                for (int q = 0; q < 3; q++){
                    if (q == 2 && !r2ok) break;
                    int r = rr[q];
                    float v0 = va[q] + bd.x, v1 = vb[q] + bd.y;
                    *(__half2*)&g_hbuf2h[obase + r*64 + o0] = __floats2half2_rn(v0, v1);
                    su0 += v0; su1 += v1; sq0 += v0*v0; sq1 += v1*v1;
                }
                su0 = redg(su0); su1 = redg(su1); sq0 = redg(sq0); sq1 = redg(sq1);
                if (lane < 4){
                    g_part1[(size_t)(4*64 + o0    )*NBT + bt] = su0;
                    g_part1[(size_t)(4*64 + o0 + 1)*NBT + bt] = su1;
                    g_part1[(size_t)(5*64 + o0    )*NBT + bt] = sq0;
                    g_part1[(size_t)(5*64 + o0 + 1)*NBT + bt] = sq1;
                }
            }
        }
    }
}

// ---------------- BN stats finalize (unchanged) ----------------
__global__ void k_finalize(int which, const float* __restrict__ gammas,
                           const float* __restrict__ betas)
{
    int ch = blockIdx.x, tid = threadIdx.x;
    int b = ch >> 6, o = ch & 63;
    const float* part = which ? g_part2 : g_part1;
    const float* psum = part + (size_t)((2*b  )*64 + o) * NBT;
    const float* psq  = part + (size_t)((2*b+1)*64 + o) * NBT;
    __shared__ float r1[256], r2[256];
    float s = 0.f, q = 0.f;
    for (int t = tid; t < NBT; t += 256){ s += psum[t]; q += psq[t]; }
    r1[tid] = s; r2[tid] = q;
    __syncthreads();
    for (int off = 128; off; off >>= 1){
        if (tid < off){ r1[tid] += r1[tid+off]; r2[tid] += r2[tid+off]; }
        __syncthreads();
    }
    if (tid == 0){
        const float invM = 1.f / 70400.f;
        float mu  = r1[0]*invM;
        float var = r2[0]*invM - mu*mu;
        int grow = which ? 3 : b;
        float g  = gammas[grow*64 + o], be = betas[grow*64 + o];
        float sc = g * rsqrtf(var + 1e-5f);
        if (which){ g_scale2[o]  = sc; g_shift2[o]  = be - mu*sc; }
        else      { g_scale1[ch] = sc; g_shift1[ch] = be - mu*sc; }
    }
}

// ---------------- k_cat: fp16 mma, 128 threads / 4 warps / 2 n-tiles (proven 29us) ----------------
__global__ __launch_bounds__(128) void k_cat(const float* __restrict__ cat_w)
{
    __shared__ __align__(16) uint32 scat[2][NND*CPH];
    __shared__ float ssc[192], ssh[192];

    int tid = threadIdx.x;
    int lane = tid & 31, w = tid >> 5;
    int g = lane >> 2, tig = lane & 3;
    int n0 = w*16;
    int oA = n0 + 2*tig;
    int oB = oA + 8;
    int r2ok = (g + 16) < NND;

    uint32 bc[12][4];
#pragma unroll
    for (int k = 0; k < 12; k++){
        const float* wp0 = cat_w + (n0 + g)*192 + k*16 + 2*tig;
        const float* wp1 = cat_w + (n0 + 8 + g)*192 + k*16 + 2*tig;
        bc[k][0] = h2g(wp0); bc[k][1] = h2g(wp0 + 8);
        bc[k][2] = h2g(wp1); bc[k][3] = h2g(wp1 + 8);
    }
    for (int p = tid; p < 192; p += 128){ ssc[p] = g_scale1[p]; ssh[p] = g_shift1[p]; }

    uint4 pf[5];
#pragma unroll
    for (int k = 0; k < 5; k++){
        int f = tid + k*128;
        if (f < 528){
            int buf = f / 176, p = f % 176;
            const __half* hb = (buf == 0) ? g_hbuf0h : ((buf == 1) ? g_hbuf1h : g_hbuf2h);
            pf[k] = __ldg((const uint4*)(hb + (size_t)(blockIdx.x*SPB_CAT)*SLICE) + p);
        }
    }
    __syncthreads();

    for (int s = 0; s < SPB_CAT; s++){
        int bt = blockIdx.x*SPB_CAT + s;
        int cur = s & 1;

#pragma unroll
        for (int k = 0; k < 5; k++){
            int f = tid + k*128;
            if (f < 528){
                int buf = f / 176, p = f % 176;
                int i = p >> 3, c = (p & 7)*8;
                int fc = buf*64 + c;
                int w0 = fc >> 1;
                uint32 hw[4] = { pf[k].x, pf[k].y, pf[k].z, pf[k].w };
#pragma unroll
                for (int hh = 0; hh < 4; hh++){
                    float2 fv = __half22float2(*reinterpret_cast<__half2*>(&hw[hh]));
                    float r0 = fmaxf(fv.x*ssc[fc + 2*hh    ] + ssh[fc + 2*hh    ], 0.f);
                    float r1 = fmaxf(fv.y*ssc[fc + 2*hh + 1] + ssh[fc + 2*hh + 1], 0.f);
                    scat[cur][i*CPH + POSW(w0 + hh)] = h2f(r0, r1);
                }
            }
        }
        if (s + 1 < SPB_CAT){
#pragma unroll
            for (int k = 0; k < 5; k++){
                int f = tid + k*128;
                if (f < 528){
                    int buf = f / 176, p = f % 176;
                    const __half* hb = (buf == 0) ? g_hbuf0h : ((buf == 1) ? g_hbuf1h : g_hbuf2h);
                    pf[k] = __ldg((const uint4*)(hb + (size_t)(bt + 1)*SLICE) + p);
                }
            }
        }
        __syncthreads();

        const uint32* sc = scat[cur];
        float a0A[4] = {0,0,0,0}, a1A[4] = {0,0,0,0};
        float a0B[4] = {0,0,0,0}, a1B[4] = {0,0,0,0};
#pragma unroll
        for (int k = 0; k < 12; k++){
            const uint32* p0 = sc + g*CPH + k*8 + 2*tig;
            uint2 va = *(const uint2*)p0;
            uint2 vb = *(const uint2*)(p0 + 8*CPH);
            uint2 vc = r2ok ? *(const uint2*)(p0 + 16*CPH) : make_uint2(0u, 0u);
            uint32 A0[4] = { va.x, vb.x, va.y, vb.y };
            uint32 A1[4] = { vc.x, 0u,   vc.y, 0u   };
            uint32 b0[2] = { bc[k][0], bc[k][1] };
            uint32 b1[2] = { bc[k][2], bc[k][3] };
            mma_f16(a0A, A0, b0);  mma_f16(a1A, A1, b0);
            mma_f16(a0B, A0, b1);  mma_f16(a1B, A1, b1);
        }

        float suA0=0.f, suA1=0.f, sqA0=0.f, sqA1=0.f;
        float suB0=0.f, suB1=0.f, sqB0=0.f, sqB1=0.f;
        int rr[3] = { g, g + 8, g + 16 };
        float vaA[3] = { a0A[0], a0A[2], a1A[0] };
        float vbA[3] = { a0A[1], a0A[3], a1A[1] };
        float vaB[3] = { a0B[0], a0B[2], a1B[0] };
        float vbB[3] = { a0B[1], a0B[3], a1B[1] };
        size_t obase = (size_t)bt*SLICE;
#pragma unroll
        for (int q = 0; q < 3; q++){
            if (q == 2 && !r2ok) break;
            int r = rr[q];
            float v0 = vaA[q], v1 = vbA[q], v2 = vaB[q], v3 = vbB[q];
            *(__half2*)&g_pre2h[obase + r*64 + oA] = __floats2half2_rn(v0, v1);
            *(__half2*)&g_pre2h[obase + r*64 + oB] = __floats2half2_rn(v2, v3);
            suA0 += v0; suA1 += v1; sqA0 += v0*v0; sqA1 += v1*v1;
            suB0 += v2; suB1 += v3; sqB0 += v2*v2; sqB1 += v3*v3;
        }
        suA0 = redg(suA0); suA1 = redg(suA1); sqA0 = redg(sqA0); sqA1 = redg(sqA1);
        suB0 = redg(suB0); suB1 = redg(suB1); sqB0 = redg(sqB0); sqB1 = redg(sqB1);
        if (lane < 4){
            g_part2[(size_t)(oA    )*NBT + bt] = suA0;
            g_part2[(size_t)(oA + 1)*NBT + bt] = suA1;
            g_part2[(size_t)(oB    )*NBT + bt] = suB0;
            g_part2[(size_t)(oB + 1)*NBT + bt] = suB1;
            g_part2[(size_t)(64 + oA    )*NBT + bt] = sqA0;
            g_part2[(size_t)(64 + oA + 1)*NBT + bt] = sqA1;
            g_part2[(size_t)(64 + oB    )*NBT + bt] = sqB0;
            g_part2[(size_t)(64 + oB + 1)*NBT + bt] = sqB1;
        }
    }
}

// ---------------- final BN+ReLU elementwise (fp16 in, fp32 out) ----------------
__global__ void k_out(float* __restrict__ out)
{
    size_t idx8 = (size_t)blockIdx.x*256 + threadIdx.x;
    if (idx8 < TOT/8){
        uint4 v = reinterpret_cast<const uint4*>(g_pre2h)[idx8];
        int ob = (int)((idx8*8) & 63);
        uint32 hw[4] = { v.x, v.y, v.z, v.w };
        float4 o0, o1;
        float2 f0 = __half22float2(*reinterpret_cast<__half2*>(&hw[0]));
        float2 f1 = __half22float2(*reinterpret_cast<__half2*>(&hw[1]));
        float2 f2 = __half22float2(*reinterpret_cast<__half2*>(&hw[2]));
        float2 f3 = __half22float2(*reinterpret_cast<__half2*>(&hw[3]));
        o0.x = fmaxf(f0.x*g_scale2[ob  ] + g_shift2[ob  ], 0.f);
        o0.y = fmaxf(f0.y*g_scale2[ob+1] + g_shift2[ob+1], 0.f);
        o0.z = fmaxf(f1.x*g_scale2[ob+2] + g_shift2[ob+2], 0.f);
        o0.w = fmaxf(f1.y*g_scale2[ob+3] + g_shift2[ob+3], 0.f);
        o1.x = fmaxf(f2.x*g_scale2[ob+4] + g_shift2[ob+4], 0.f);
        o1.y = fmaxf(f2.y*g_scale2[ob+5] + g_shift2[ob+5], 0.f);
        o1.z = fmaxf(f3.x*g_scale2[ob+6] + g_shift2[ob+6], 0.f);
        o1.w = fmaxf(f3.y*g_scale2[ob+7] + g_shift2[ob+7], 0.f);
        reinterpret_cast<float4*>(out)[idx8*2    ] = o0;
        reinterpret_cast<float4*>(out)[idx8*2 + 1] = o1;
    }
}

// ---------------- launch ----------------
#define KMAIN_SMEM_BYTES (24792*4)

extern "C" void kernel_launch(void* const* d_in, const int* in_sizes, int n_in,
                              void* d_out, int out_size)
{
    const float* x        = (const float*)d_in[0];
    const float* W_sym    = (const float*)d_in[1];
    const float* e_sym    = (const float*)d_in[2];
    const float* W_con    = (const float*)d_in[3];
    const float* e_con    = (const float*)d_in[4];
    const float* W_dis    = (const float*)d_in[5];
    const float* att      = (const float*)d_in[6];
    const float* b_dis    = (const float*)d_in[7];
    const float* cat_w    = (const float*)d_in[8];
    const float* gammas   = (const float*)d_in[9];
    const float* betas    = (const float*)d_in[10];
    const int*   rows_sym = (const int*)d_in[11];
    const int*   cols_sym = (const int*)d_in[12];
    const int*   rows_con = (const int*)d_in[13];
    const int*   cols_con = (const int*)d_in[14];
    int nnz_sym = in_sizes[11];
    int nnz_con = in_sizes[13];

    static int configured = 0;
    if (!configured){
        cudaFuncSetAttribute(k_main, cudaFuncAttributeMaxDynamicSharedMemorySize, KMAIN_SMEM_BYTES);
        configured = 1;
    }

    k_prep<<<3, 256>>>(e_sym, rows_sym, cols_sym, nnz_sym,
                       e_con, rows_con, cols_con, nnz_con,
                       W_sym, W_con, W_dis);
    k_main<<<PERSIST, 256, KMAIN_SMEM_BYTES>>>(x, att, b_dis);
    k_finalize<<<192, 256>>>(0, gammas, betas);
    k_cat<<<GRID_CAT, 128>>>(cat_w);
    k_finalize<<<64, 256>>>(1, gammas, betas);
    k_out<<<(TOT/8 + 255)/256, 256>>>((float*)d_out);
    (void)n_in; (void)out_size;
}